// round 1
// baseline (speedup 1.0000x reference)
#include <cuda_runtime.h>

#define BATCH 4
#define DM 192
#define DI 192
#define LL 4096
#define KK 4
#define NS 16
#define RR 12
#define CPROJ 44   // RR + 2*NS

// ---------------- scratch (static device allocations; no cudaMalloc) ----------
__device__ float g_xin[BATCH*LL*DI];          // 12.6 MB  x_inner [b][p][d]
__device__ float g_yin[BATCH*LL*DI];          // 12.6 MB  y_inner [b][p][d]
__device__ float g_delta[(size_t)BATCH*KK*LL*DI]; // 50.3 MB  delta [bk][l][d]
__device__ float g_Bs[BATCH*KK*LL*NS];        // 4.2 MB   B [bk][l][n]
__device__ float g_Cs[BATCH*KK*LL*NS];        // 4.2 MB   C [bk][l][n]
__device__ float g_sy[(size_t)BATCH*KK*LL*DI];    // 50.3 MB  scan out [bk][l][d]
__device__ float g_anl2[KK*DI*NS];            // A * log2(e)  (A = -exp(A_logs))
__device__ float g_dsum[DI];                  // sum_k Ds[k,d]

// ---------------- kernel 0: tiny precompute --------------------------------
__global__ void k0_init(const float* __restrict__ A_logs, const float* __restrict__ Ds) {
    int t = threadIdx.x;
    for (int i = t; i < KK*DI*NS; i += blockDim.x)
        g_anl2[i] = -expf(A_logs[i]) * 1.4426950408889634f;
    if (t < DI) g_dsum[t] = Ds[t] + Ds[DI + t] + Ds[2*DI + t] + Ds[3*DI + t];
}

// ---------------- kernel 1: in_proj (x and y) -------------------------------
// x_inner[b][p][d] = sum_c x[b][c][p] * w[c][d]
// block: 256 threads, 64-pixel tile; grid: (256 tiles, 2 matrices)
__global__ void k1_inproj(const float* __restrict__ x, const float* __restrict__ y,
                          const float* __restrict__ wx, const float* __restrict__ wy) {
    __shared__ float xs_s[16][64];
    __shared__ float ws_s[16][192];
    const float* src = blockIdx.y ? y : x;
    const float* w   = blockIdx.y ? wy : wx;
    float* dst       = blockIdx.y ? g_yin : g_xin;
    int tile = blockIdx.x;
    int b  = tile >> 6;               // LL/64 = 64 tiles per batch
    int p0 = (tile & 63) * 64;
    int t  = threadIdx.x;
    int dg = t & 15;                  // 16 d-groups
    int pg = t >> 4;                  // 16 pixel-groups
    int d0 = dg * 12;
    int px = pg * 4;
    float acc[4][12];
#pragma unroll
    for (int i = 0; i < 4; i++)
#pragma unroll
        for (int j = 0; j < 12; j++) acc[i][j] = 0.f;

    for (int c0 = 0; c0 < DM; c0 += 16) {
        __syncthreads();
        for (int idx = t; idx < 16*64; idx += 256) {
            int cc = idx >> 6, j = idx & 63;
            xs_s[cc][j] = src[((size_t)(b*DM + c0 + cc))*LL + p0 + j];
        }
        for (int idx = t; idx < 16*192; idx += 256) {
            int cc = idx / 192, d = idx % 192;
            ws_s[cc][d] = w[(c0 + cc)*DI + d];
        }
        __syncthreads();
#pragma unroll
        for (int cc = 0; cc < 16; cc++) {
            float4 xv = *(const float4*)&xs_s[cc][px];
            float wv[12];
#pragma unroll
            for (int j = 0; j < 12; j += 4) {
                float4 wq = *(const float4*)&ws_s[cc][d0 + j];
                wv[j] = wq.x; wv[j+1] = wq.y; wv[j+2] = wq.z; wv[j+3] = wq.w;
            }
#pragma unroll
            for (int j = 0; j < 12; j++) {
                acc[0][j] = fmaf(xv.x, wv[j], acc[0][j]);
                acc[1][j] = fmaf(xv.y, wv[j], acc[1][j]);
                acc[2][j] = fmaf(xv.z, wv[j], acc[2][j]);
                acc[3][j] = fmaf(xv.w, wv[j], acc[3][j]);
            }
        }
    }
#pragma unroll
    for (int i = 0; i < 4; i++) {
        float* o = dst + ((size_t)b*LL + p0 + px + i)*DI + d0;
#pragma unroll
        for (int j = 0; j < 12; j += 4)
            *(float4*)(o + j) = make_float4(acc[i][j], acc[i][j+1], acc[i][j+2], acc[i][j+3]);
    }
}

// ---------------- kernel 2: x_proj + dt_proj + softplus + B/C ---------------
__device__ __forceinline__ int perm_pixel(int k, int l) {
    if (k == 0) return l;
    if (k == 1) return (l & 63)*64 + (l >> 6);
    if (k == 2) return LL - 1 - l;
    int l2 = LL - 1 - l;
    return (l2 & 63)*64 + (l2 >> 6);
}

// grid: (L/32, K, B), block 256
__global__ void k2_xproj(const float* __restrict__ xpw, const float* __restrict__ dtw,
                         const float* __restrict__ dtb) {
    __shared__ float xin_s[32*193];
    __shared__ float proj_s[CPROJ*33];
    __shared__ float dtw_s[DI*RR];
    int ltile = blockIdx.x * 32;
    int k = blockIdx.y, b = blockIdx.z;
    int t = threadIdx.x;

    for (int i = t; i < DI*RR; i += 256) dtw_s[i] = dtw[k*DI*RR + i];
    for (int idx = t; idx < 32*DI; idx += 256) {
        int l = idx / DI, d = idx % DI;
        int p = perm_pixel(k, ltile + l);
        xin_s[l*193 + d] = g_xin[((size_t)b*LL + p)*DI + d];
    }
    __syncthreads();

    // phase 2: proj[c][l] = dot(xpw[k][c][:], xin[l][:])
    if (t < 176) {
        int c  = t >> 2;   // 0..43
        int lg = t & 3;    // 4 groups of 8 l's
        const float* wrow = xpw + ((size_t)k*CPROJ + c)*DI;
        float acc[8];
#pragma unroll
        for (int j = 0; j < 8; j++) acc[j] = 0.f;
        for (int d = 0; d < DI; d++) {
            float wv = __ldg(wrow + d);
#pragma unroll
            for (int j = 0; j < 8; j++)
                acc[j] = fmaf(wv, xin_s[(lg*8 + j)*193 + d], acc[j]);
        }
#pragma unroll
        for (int j = 0; j < 8; j++) proj_s[c*33 + lg*8 + j] = acc[j];
    }
    __syncthreads();

    if (t < DI) {
        // phase 3: delta[l][d] = softplus(dtw[d]·proj[0:12][l] + bias[d])
        int d = t;
        float w[RR];
#pragma unroll
        for (int r = 0; r < RR; r++) w[r] = dtw_s[d*RR + r];
        float bias = dtb[k*DI + d];
        float* dptr = g_delta + ((size_t)(b*KK + k)*LL + ltile)*DI + d;
        for (int l = 0; l < 32; l++) {
            float acc = bias;
#pragma unroll
            for (int r = 0; r < RR; r++) acc = fmaf(w[r], proj_s[r*33 + l], acc);
            float sp = fmaxf(acc, 0.f) + log1pf(__expf(-fabsf(acc)));
            dptr[(size_t)l*DI] = sp;
        }
    } else {
        // phase 4: scatter B/C (threads 192..255)
        int tt = t - DI;
        size_t base = ((size_t)(b*KK + k)*LL + ltile)*NS;
        for (int idx = tt; idx < 32*NS*2; idx += 64) {
            int l = idx >> 5, m = idx & 31;
            if (m < NS) g_Bs[base + l*NS + m]        = proj_s[(RR + m)*33 + l];
            else        g_Cs[base + l*NS + (m - NS)] = proj_s[(RR + NS + m - NS)*33 + l];
        }
    }
}

// ---------------- kernel 3: selective scan ----------------------------------
// lane = (chain_half, state): warp = 2 chains x 16 states.
// grid: (24 d-tiles, K, B), block 128 (4 warps -> 8 d per block)
__global__ void k3_scan() {
    int b = blockIdx.z, k = blockIdx.y;
    int warp = threadIdx.x >> 5;
    int lane = threadIdx.x & 31;
    int n = lane & 15;
    int d = blockIdx.x*8 + warp*2 + (lane >> 4);

    float an = g_anl2[(k*DI + d)*NS + n];   // A * log2e  (negative)
    size_t bk = (size_t)(b*KK + k);
    const float* dp = g_delta + bk*LL*DI + d;
    const float* Bp = g_Bs + bk*LL*NS + n;
    const float* Cp = g_Cs + bk*LL*NS + n;
    float*       op = g_sy + bk*LL*DI + d;
    const float* yb = g_yin + (size_t)b*LL*DI + d;

    int pstep, pb0, pbs;
    if      (k == 0) { pb0 = 0;     pbs = 64;  pstep = 1;   }
    else if (k == 1) { pb0 = 0;     pbs = 1;   pstep = 64;  }
    else if (k == 2) { pb0 = LL-1;  pbs = -64; pstep = -1;  }
    else             { pb0 = LL-1;  pbs = -1;  pstep = -64; }

    float h = 0.f;
    int ustride = pstep * DI;
    for (int o = 0; o < 64; o++) {
        const float* up = yb + (size_t)(pb0 + o*pbs)*DI;
#pragma unroll 4
        for (int i = 0; i < 64; i++) {
            float dlt = *dp;
            float uv  = *up;
            float Bv  = *Bp;
            float Cv  = *Cp;
            float dA;
            asm("ex2.approx.ftz.f32 %0, %1;" : "=f"(dA) : "f"(dlt * an));
            h = fmaf(dA, h, dlt * uv * Bv);
            float part = h * Cv;
            part += __shfl_xor_sync(0xffffffffu, part, 8);
            part += __shfl_xor_sync(0xffffffffu, part, 4);
            part += __shfl_xor_sync(0xffffffffu, part, 2);
            part += __shfl_xor_sync(0xffffffffu, part, 1);
            if (n == 0) *op = part;
            dp += DI; Bp += NS; Cp += NS; op += DI; up += ustride;
        }
    }
}

// ---------------- kernel 5: merge + LayerNorm + out_proj --------------------
// grid: (L/32, B), block 256
__global__ void k5_merge(const float* __restrict__ gamma, const float* __restrict__ beta,
                         const float* __restrict__ opw, float* __restrict__ out) {
    __shared__ float ym_s[32*DI];
    __shared__ float W_s[16*DI];
    __shared__ float mu_s[32], rs_s[32];
    int b = blockIdx.y;
    int p0 = blockIdx.x * 32;
    int t = threadIdx.x;
    size_t bb = (size_t)b * KK;

    // phase A: merge 4 directions + Ds*u term
    for (int idx = t; idx < 32*DI; idx += 256) {
        int pl = idx / DI, d = idx % DI;
        int p  = p0 + pl;
        int l1 = (p & 63)*64 + (p >> 6);
        float v = g_sy[((bb + 0)*LL + p)*DI + d]
                + g_sy[((bb + 2)*LL + (LL-1-p))*DI + d]
                + g_sy[((bb + 1)*LL + l1)*DI + d]
                + g_sy[((bb + 3)*LL + (LL-1-l1))*DI + d]
                + g_dsum[d] * g_yin[((size_t)b*LL + p)*DI + d];
        ym_s[pl*DI + d] = v;
    }
    __syncthreads();

    // phase B: LN stats (warp handles 4 px; 8 lanes per px)
    {
        int warp = t >> 5, lane = t & 31;
        int pl  = warp*4 + (lane >> 3);
        int sub = lane & 7;
        float s = 0.f, s2 = 0.f;
        for (int j = sub; j < DI; j += 8) { float v = ym_s[pl*DI + j]; s += v; s2 += v*v; }
        s  += __shfl_xor_sync(0xffffffffu, s, 4);  s2 += __shfl_xor_sync(0xffffffffu, s2, 4);
        s  += __shfl_xor_sync(0xffffffffu, s, 2);  s2 += __shfl_xor_sync(0xffffffffu, s2, 2);
        s  += __shfl_xor_sync(0xffffffffu, s, 1);  s2 += __shfl_xor_sync(0xffffffffu, s2, 1);
        if (sub == 0) {
            float mu  = s * (1.f/DI);
            float var = s2 * (1.f/DI) - mu*mu;
            mu_s[pl] = mu;
            rs_s[pl] = rsqrtf(var + 1e-5f);
        }
    }
    __syncthreads();

    // phase C: normalize in place
    for (int idx = t; idx < 32*DI; idx += 256) {
        int pl = idx / DI, d = idx % DI;
        ym_s[idx] = (ym_s[idx] - mu_s[pl]) * rs_s[pl] * gamma[d] + beta[d];
    }

    // phase D: out_proj, 2 px x 12 c per thread
    int c0 = (t & 15) * 12;
    int px = (t >> 4) * 2;
    float acc[2][12];
#pragma unroll
    for (int i = 0; i < 2; i++)
#pragma unroll
        for (int j = 0; j < 12; j++) acc[i][j] = 0.f;

    for (int dc = 0; dc < DI; dc += 16) {
        __syncthreads();
        for (int idx = t; idx < 16*DI; idx += 256)
            W_s[idx] = opw[(dc + idx/DI)*DM + (idx % DI)];
        __syncthreads();
#pragma unroll
        for (int dd = 0; dd < 16; dd++) {
            float y0 = ym_s[(px + 0)*DI + dc + dd];
            float y1 = ym_s[(px + 1)*DI + dc + dd];
#pragma unroll
            for (int j = 0; j < 12; j += 4) {
                float4 wq = *(const float4*)&W_s[dd*DI + c0 + j];
                acc[0][j]   = fmaf(y0, wq.x, acc[0][j]);
                acc[0][j+1] = fmaf(y0, wq.y, acc[0][j+1]);
                acc[0][j+2] = fmaf(y0, wq.z, acc[0][j+2]);
                acc[0][j+3] = fmaf(y0, wq.w, acc[0][j+3]);
                acc[1][j]   = fmaf(y1, wq.x, acc[1][j]);
                acc[1][j+1] = fmaf(y1, wq.y, acc[1][j+1]);
                acc[1][j+2] = fmaf(y1, wq.z, acc[1][j+2]);
                acc[1][j+3] = fmaf(y1, wq.w, acc[1][j+3]);
            }
        }
    }
#pragma unroll
    for (int i = 0; i < 2; i++) {
        int p = p0 + px + i;
#pragma unroll
        for (int j = 0; j < 12; j++) {
            int c = c0 + j;
            out[((size_t)(b*DM + c))*LL + p] = acc[i][j];
        }
    }
}

// ---------------- launch ----------------------------------------------------
extern "C" void kernel_launch(void* const* d_in, const int* in_sizes, int n_in,
                              void* d_out, int out_size) {
    const float* x    = (const float*)d_in[0];
    const float* y    = (const float*)d_in[1];
    const float* wx   = (const float*)d_in[2];
    const float* wy   = (const float*)d_in[3];
    const float* xpw  = (const float*)d_in[4];
    const float* dtw  = (const float*)d_in[5];
    const float* dtb  = (const float*)d_in[6];
    const float* Alog = (const float*)d_in[7];
    const float* Ds   = (const float*)d_in[8];
    const float* gam  = (const float*)d_in[9];
    const float* bet  = (const float*)d_in[10];
    const float* opw  = (const float*)d_in[11];
    float* out = (float*)d_out;

    k0_init<<<1, 256>>>(Alog, Ds);
    k1_inproj<<<dim3(256, 2), 256>>>(x, y, wx, wy);
    k2_xproj<<<dim3(LL/32, KK, BATCH), 256>>>(xpw, dtw, dtb);
    k3_scan<<<dim3(DI/8, KK, BATCH), 128>>>();
    k5_merge<<<dim3(LL/32, BATCH), 256>>>(gam, bet, opw, out);
}

// round 2
// speedup vs baseline: 2.9594x; 2.9594x over previous
#include <cuda_runtime.h>

#define BATCH 4
#define DM 192
#define DI 192
#define LL 4096
#define KK 4
#define NS 16
#define RR 12
#define CPROJ 44   // RR + 2*NS
#define CT 64      // chunk length
#define NC 64      // number of chunks

// ---------------- scratch (static device allocations; no cudaMalloc) ----------
__device__ float g_xin[BATCH*LL*DI];              // 12.6 MB  x_inner [b][p][d]
__device__ float g_yin[BATCH*LL*DI];              // 12.6 MB  y_inner [b][p][d]
__device__ float g_delta[(size_t)BATCH*KK*LL*DI]; // 50.3 MB  delta [bk][l][d]
__device__ float g_Bs[BATCH*KK*LL*NS];            // 4.2 MB   B [bk][l][n]
__device__ float g_Cs[BATCH*KK*LL*NS];            // 4.2 MB   C [bk][l][n]
__device__ float g_sy[(size_t)BATCH*KK*LL*DI];    // 50.3 MB  scan out [bk][l][d]
__device__ float g_anl2[KK*DI*NS];                // A * log2(e)  (A = -exp(A_logs))
__device__ float g_dsum[DI];                      // sum_k Ds[k,d]
__device__ float g_H  [(size_t)BATCH*KK*DI*NC*NS]; // 12.6MB chunk-local final h
__device__ float g_P  [(size_t)BATCH*KK*DI*NC*NS]; // 12.6MB chunk decay products
__device__ float g_Hin[(size_t)BATCH*KK*DI*NC*NS]; // 12.6MB chunk carry-in states
__device__ int   g_fast;                           // A[n] == (n+1)*A[0] structure flag

__device__ __forceinline__ float ex2f(float x){
    float r; asm("ex2.approx.ftz.f32 %0, %1;" : "=f"(r) : "f"(x)); return r;
}

// w^(n+1) for n=0..15 via log-depth squaring (depth 4, 15 muls)
__device__ __forceinline__ void pows16(float w, float* pw){
    pw[0]=w;          pw[1]=w*w;        pw[2]=pw[1]*w;    pw[3]=pw[1]*pw[1];
    pw[4]=pw[3]*pw[0];pw[5]=pw[3]*pw[1];pw[6]=pw[3]*pw[2];pw[7]=pw[3]*pw[3];
    pw[8]=pw[7]*pw[0];pw[9]=pw[7]*pw[1];pw[10]=pw[7]*pw[2];pw[11]=pw[7]*pw[3];
    pw[12]=pw[7]*pw[4];pw[13]=pw[7]*pw[5];pw[14]=pw[7]*pw[6];pw[15]=pw[7]*pw[7];
}

// ---------------- kernel 0: tiny precompute --------------------------------
__global__ void k0_init(const float* __restrict__ A_logs, const float* __restrict__ Ds) {
    int t = threadIdx.x;
    if (t == 0) g_fast = 1;
    for (int i = t; i < KK*DI*NS; i += blockDim.x)
        g_anl2[i] = -expf(A_logs[i]) * 1.4426950408889634f;
    if (t < DI) g_dsum[t] = Ds[t] + Ds[DI + t] + Ds[2*DI + t] + Ds[3*DI + t];
    __syncthreads();
    // structure check: anl2[n] == (n+1) * anl2[0] (per d,k) within tolerance
    int ok = 1;
    for (int i = t; i < KK*DI*NS; i += blockDim.x) {
        int n = i % NS;
        float base = g_anl2[i - n];
        float want = (float)(n + 1) * base;
        if (fabsf(g_anl2[i] - want) > 1e-3f * fabsf(want) + 1e-12f) ok = 0;
    }
    if (!ok) atomicExch(&g_fast, 0);
}

// ---------------- kernel 1: in_proj (x and y) -------------------------------
__global__ void k1_inproj(const float* __restrict__ x, const float* __restrict__ y,
                          const float* __restrict__ wx, const float* __restrict__ wy) {
    __shared__ float xs_s[16][64];
    __shared__ float ws_s[16][192];
    const float* src = blockIdx.y ? y : x;
    const float* w   = blockIdx.y ? wy : wx;
    float* dst       = blockIdx.y ? g_yin : g_xin;
    int tile = blockIdx.x;
    int b  = tile >> 6;
    int p0 = (tile & 63) * 64;
    int t  = threadIdx.x;
    int dg = t & 15;
    int pg = t >> 4;
    int d0 = dg * 12;
    int px = pg * 4;
    float acc[4][12];
#pragma unroll
    for (int i = 0; i < 4; i++)
#pragma unroll
        for (int j = 0; j < 12; j++) acc[i][j] = 0.f;

    for (int c0 = 0; c0 < DM; c0 += 16) {
        __syncthreads();
        for (int idx = t; idx < 16*64; idx += 256) {
            int cc = idx >> 6, j = idx & 63;
            xs_s[cc][j] = src[((size_t)(b*DM + c0 + cc))*LL + p0 + j];
        }
        for (int idx = t; idx < 16*192; idx += 256) {
            int cc = idx / 192, d = idx % 192;
            ws_s[cc][d] = w[(c0 + cc)*DI + d];
        }
        __syncthreads();
#pragma unroll
        for (int cc = 0; cc < 16; cc++) {
            float4 xv = *(const float4*)&xs_s[cc][px];
            float wv[12];
#pragma unroll
            for (int j = 0; j < 12; j += 4) {
                float4 wq = *(const float4*)&ws_s[cc][d0 + j];
                wv[j] = wq.x; wv[j+1] = wq.y; wv[j+2] = wq.z; wv[j+3] = wq.w;
            }
#pragma unroll
            for (int j = 0; j < 12; j++) {
                acc[0][j] = fmaf(xv.x, wv[j], acc[0][j]);
                acc[1][j] = fmaf(xv.y, wv[j], acc[1][j]);
                acc[2][j] = fmaf(xv.z, wv[j], acc[2][j]);
                acc[3][j] = fmaf(xv.w, wv[j], acc[3][j]);
            }
        }
    }
#pragma unroll
    for (int i = 0; i < 4; i++) {
        float* o = dst + ((size_t)b*LL + p0 + px + i)*DI + d0;
#pragma unroll
        for (int j = 0; j < 12; j += 4)
            *(float4*)(o + j) = make_float4(acc[i][j], acc[i][j+1], acc[i][j+2], acc[i][j+3]);
    }
}

// ---------------- kernel 2: x_proj + dt_proj + softplus + B/C ---------------
__device__ __forceinline__ int perm_pixel(int k, int l) {
    if (k == 0) return l;
    if (k == 1) return (l & 63)*64 + (l >> 6);
    if (k == 2) return LL - 1 - l;
    int l2 = LL - 1 - l;
    return (l2 & 63)*64 + (l2 >> 6);
}

__global__ void k2_xproj(const float* __restrict__ xpw, const float* __restrict__ dtw,
                         const float* __restrict__ dtb) {
    __shared__ float xin_s[32*193];
    __shared__ float proj_s[CPROJ*33];
    __shared__ float dtw_s[DI*RR];
    int ltile = blockIdx.x * 32;
    int k = blockIdx.y, b = blockIdx.z;
    int t = threadIdx.x;

    for (int i = t; i < DI*RR; i += 256) dtw_s[i] = dtw[k*DI*RR + i];
    for (int idx = t; idx < 32*DI; idx += 256) {
        int l = idx / DI, d = idx % DI;
        int p = perm_pixel(k, ltile + l);
        xin_s[l*193 + d] = g_xin[((size_t)b*LL + p)*DI + d];
    }
    __syncthreads();

    if (t < 176) {
        int c  = t >> 2;
        int lg = t & 3;
        const float* wrow = xpw + ((size_t)k*CPROJ + c)*DI;
        float acc[8];
#pragma unroll
        for (int j = 0; j < 8; j++) acc[j] = 0.f;
        for (int d = 0; d < DI; d++) {
            float wv = __ldg(wrow + d);
#pragma unroll
            for (int j = 0; j < 8; j++)
                acc[j] = fmaf(wv, xin_s[(lg*8 + j)*193 + d], acc[j]);
        }
#pragma unroll
        for (int j = 0; j < 8; j++) proj_s[c*33 + lg*8 + j] = acc[j];
    }
    __syncthreads();

    if (t < DI) {
        int d = t;
        float w[RR];
#pragma unroll
        for (int r = 0; r < RR; r++) w[r] = dtw_s[d*RR + r];
        float bias = dtb[k*DI + d];
        float* dptr = g_delta + ((size_t)(b*KK + k)*LL + ltile)*DI + d;
        for (int l = 0; l < 32; l++) {
            float acc = bias;
#pragma unroll
            for (int r = 0; r < RR; r++) acc = fmaf(w[r], proj_s[r*33 + l], acc);
            float sp = fmaxf(acc, 0.f) + log1pf(__expf(-fabsf(acc)));
            dptr[(size_t)l*DI] = sp;
        }
    } else {
        int tt = t - DI;
        size_t base = ((size_t)(b*KK + k)*LL + ltile)*NS;
        for (int idx = tt; idx < 32*NS*2; idx += 64) {
            int l = idx >> 5, m = idx & 31;
            if (m < NS) g_Bs[base + l*NS + m]        = proj_s[(RR + m)*33 + l];
            else        g_Cs[base + l*NS + (m - NS)] = proj_s[(RR + NS + m - NS)*33 + l];
        }
    }
}

// ---------------- chunked selective scan ------------------------------------
// pass1: per (chain, chunk), local recursion from h=0 -> store H and P.
template<bool FAST>
__device__ __forceinline__ void pass1_loop(const float* dp, const float* up, int ustep,
                                           const float* Bp, const float* an,
                                           float* h, float& S) {
#pragma unroll 2
    for (int t = 0; t < CT; t++) {
        float dlt = *dp;
        float uv  = *up;
        float4 b0 = *(const float4*)Bp;
        float4 b1 = *(const float4*)(Bp + 4);
        float4 b2 = *(const float4*)(Bp + 8);
        float4 b3 = *(const float4*)(Bp + 12);
        float pw[NS];
        if (FAST) { pows16(ex2f(dlt * an[0]), pw); }
        else {
#pragma unroll
            for (int n = 0; n < NS; n++) pw[n] = ex2f(dlt * an[n]);
        }
        float du = dlt * uv;
        float Bv[NS] = {b0.x,b0.y,b0.z,b0.w, b1.x,b1.y,b1.z,b1.w,
                        b2.x,b2.y,b2.z,b2.w, b3.x,b3.y,b3.z,b3.w};
#pragma unroll
        for (int n = 0; n < NS; n++) h[n] = fmaf(pw[n], h[n], du * Bv[n]);
        S += dlt;
        dp += DI; up += ustep; Bp += NS;
    }
}

__device__ __forceinline__ void dir_params(int k, int c, int l0, int& p0, int& pst) {
    if      (k == 0) { p0 = l0;            pst = 1;   }
    else if (k == 1) { p0 = c;             pst = 64;  }
    else if (k == 2) { p0 = LL - 1 - l0;   pst = -1;  }
    else             { p0 = 4032 + 63 - c; pst = -64; }
}

__global__ __launch_bounds__(192) void k3_pass1() {
    int c = blockIdx.x, k = blockIdx.y, b = blockIdx.z;
    int d = threadIdx.x;
    size_t bk = (size_t)(b*KK + k);
    int l0 = c * CT;
    const float* dp = g_delta + (bk*LL + (size_t)l0)*DI + d;
    const float* Bp = g_Bs + (bk*LL + (size_t)l0)*NS;
    int p0, pst; dir_params(k, c, l0, p0, pst);
    const float* up = g_yin + ((size_t)b*LL + p0)*DI + d;
    float an[NS];
    const float* ap = g_anl2 + ((size_t)k*DI + d)*NS;
#pragma unroll
    for (int n = 0; n < NS; n++) an[n] = ap[n];
    float h[NS];
#pragma unroll
    for (int n = 0; n < NS; n++) h[n] = 0.f;
    float S = 0.f;
    if (g_fast) pass1_loop<true >(dp, up, pst*DI, Bp, an, h, S);
    else        pass1_loop<false>(dp, up, pst*DI, Bp, an, h, S);
    size_t ch = bk*DI + d;
    float* Hp = g_H + (ch*NC + c)*NS;
    float* Pp = g_P + (ch*NC + c)*NS;
#pragma unroll
    for (int n = 0; n < NS; n += 4) {
        *(float4*)(Hp + n) = make_float4(h[n], h[n+1], h[n+2], h[n+3]);
        *(float4*)(Pp + n) = make_float4(ex2f(an[n]*S), ex2f(an[n+1]*S),
                                         ex2f(an[n+2]*S), ex2f(an[n+3]*S));
    }
}

// combine: serial over chunks, per (chain, state) lane
__global__ void k3_comb() {
    int t = blockIdx.x * blockDim.x + threadIdx.x;   // 49152 lanes
    int n = t & 15;
    size_t ch = (size_t)(t >> 4);
    const float* Hp = g_H   + ch*NC*NS + n;
    const float* Pp = g_P   + ch*NC*NS + n;
    float*       Ip = g_Hin + ch*NC*NS + n;
    float h = 0.f;
#pragma unroll 4
    for (int c = 0; c < NC; c++) {
        Ip[c*NS] = h;
        h = fmaf(Pp[c*NS], h, Hp[c*NS]);
    }
}

// pass3: re-run recursion seeded with carry-in, emit y.
template<bool FAST>
__device__ __forceinline__ void pass3_loop(const float* dp, const float* up, int ustep,
                                           const float* Bp, const float* Cp, float* op,
                                           const float* an, float* h) {
#pragma unroll 2
    for (int t = 0; t < CT; t++) {
        float dlt = *dp;
        float uv  = *up;
        float4 b0 = *(const float4*)Bp;
        float4 b1 = *(const float4*)(Bp + 4);
        float4 b2 = *(const float4*)(Bp + 8);
        float4 b3 = *(const float4*)(Bp + 12);
        float4 c0 = *(const float4*)Cp;
        float4 c1 = *(const float4*)(Cp + 4);
        float4 c2 = *(const float4*)(Cp + 8);
        float4 c3 = *(const float4*)(Cp + 12);
        float pw[NS];
        if (FAST) { pows16(ex2f(dlt * an[0]), pw); }
        else {
#pragma unroll
            for (int n = 0; n < NS; n++) pw[n] = ex2f(dlt * an[n]);
        }
        float du = dlt * uv;
        float Bv[NS] = {b0.x,b0.y,b0.z,b0.w, b1.x,b1.y,b1.z,b1.w,
                        b2.x,b2.y,b2.z,b2.w, b3.x,b3.y,b3.z,b3.w};
        float Cv[NS] = {c0.x,c0.y,c0.z,c0.w, c1.x,c1.y,c1.z,c1.w,
                        c2.x,c2.y,c2.z,c2.w, c3.x,c3.y,c3.z,c3.w};
        float y0 = 0.f, y1 = 0.f, y2 = 0.f, y3 = 0.f;
#pragma unroll
        for (int n = 0; n < 4; n++) {
            h[n]    = fmaf(pw[n],    h[n],    du * Bv[n]);    y0 = fmaf(h[n],    Cv[n],    y0);
            h[n+4]  = fmaf(pw[n+4],  h[n+4],  du * Bv[n+4]);  y1 = fmaf(h[n+4],  Cv[n+4],  y1);
            h[n+8]  = fmaf(pw[n+8],  h[n+8],  du * Bv[n+8]);  y2 = fmaf(h[n+8],  Cv[n+8],  y2);
            h[n+12] = fmaf(pw[n+12], h[n+12], du * Bv[n+12]); y3 = fmaf(h[n+12], Cv[n+12], y3);
        }
        *op = (y0 + y1) + (y2 + y3);
        dp += DI; up += ustep; Bp += NS; Cp += NS; op += DI;
    }
}

__global__ __launch_bounds__(192) void k3_pass3() {
    int c = blockIdx.x, k = blockIdx.y, b = blockIdx.z;
    int d = threadIdx.x;
    size_t bk = (size_t)(b*KK + k);
    int l0 = c * CT;
    const float* dp = g_delta + (bk*LL + (size_t)l0)*DI + d;
    const float* Bp = g_Bs + (bk*LL + (size_t)l0)*NS;
    const float* Cp = g_Cs + (bk*LL + (size_t)l0)*NS;
    float*       op = g_sy + (bk*LL + (size_t)l0)*DI + d;
    int p0, pst; dir_params(k, c, l0, p0, pst);
    const float* up = g_yin + ((size_t)b*LL + p0)*DI + d;
    float an[NS];
    const float* ap = g_anl2 + ((size_t)k*DI + d)*NS;
#pragma unroll
    for (int n = 0; n < NS; n++) an[n] = ap[n];
    size_t ch = bk*DI + d;
    const float* Ip = g_Hin + (ch*NC + c)*NS;
    float h[NS];
#pragma unroll
    for (int n = 0; n < NS; n += 4) {
        float4 iv = *(const float4*)(Ip + n);
        h[n] = iv.x; h[n+1] = iv.y; h[n+2] = iv.z; h[n+3] = iv.w;
    }
    if (g_fast) pass3_loop<true >(dp, up, pst*DI, Bp, Cp, op, an, h);
    else        pass3_loop<false>(dp, up, pst*DI, Bp, Cp, op, an, h);
}

// ---------------- kernel 5: merge + LayerNorm + out_proj --------------------
__global__ void k5_merge(const float* __restrict__ gamma, const float* __restrict__ beta,
                         const float* __restrict__ opw, float* __restrict__ out) {
    __shared__ float ym_s[32*DI];
    __shared__ float W_s[16*DI];
    __shared__ float mu_s[32], rs_s[32];
    int b = blockIdx.y;
    int p0 = blockIdx.x * 32;
    int t = threadIdx.x;
    size_t bb = (size_t)b * KK;

    for (int idx = t; idx < 32*DI; idx += 256) {
        int pl = idx / DI, d = idx % DI;
        int p  = p0 + pl;
        int l1 = (p & 63)*64 + (p >> 6);
        float v = g_sy[((bb + 0)*LL + p)*DI + d]
                + g_sy[((bb + 2)*LL + (LL-1-p))*DI + d]
                + g_sy[((bb + 1)*LL + l1)*DI + d]
                + g_sy[((bb + 3)*LL + (LL-1-l1))*DI + d]
                + g_dsum[d] * g_yin[((size_t)b*LL + p)*DI + d];
        ym_s[pl*DI + d] = v;
    }
    __syncthreads();

    {
        int warp = t >> 5, lane = t & 31;
        int pl  = warp*4 + (lane >> 3);
        int sub = lane & 7;
        float s = 0.f, s2 = 0.f;
        for (int j = sub; j < DI; j += 8) { float v = ym_s[pl*DI + j]; s += v; s2 += v*v; }
        s  += __shfl_xor_sync(0xffffffffu, s, 4);  s2 += __shfl_xor_sync(0xffffffffu, s2, 4);
        s  += __shfl_xor_sync(0xffffffffu, s, 2);  s2 += __shfl_xor_sync(0xffffffffu, s2, 2);
        s  += __shfl_xor_sync(0xffffffffu, s, 1);  s2 += __shfl_xor_sync(0xffffffffu, s2, 1);
        if (sub == 0) {
            float mu  = s * (1.f/DI);
            float var = s2 * (1.f/DI) - mu*mu;
            mu_s[pl] = mu;
            rs_s[pl] = rsqrtf(var + 1e-5f);
        }
    }
    __syncthreads();

    for (int idx = t; idx < 32*DI; idx += 256) {
        int pl = idx / DI, d = idx % DI;
        ym_s[idx] = (ym_s[idx] - mu_s[pl]) * rs_s[pl] * gamma[d] + beta[d];
    }

    int c0 = (t & 15) * 12;
    int px = (t >> 4) * 2;
    float acc[2][12];
#pragma unroll
    for (int i = 0; i < 2; i++)
#pragma unroll
        for (int j = 0; j < 12; j++) acc[i][j] = 0.f;

    for (int dc = 0; dc < DI; dc += 16) {
        __syncthreads();
        for (int idx = t; idx < 16*DI; idx += 256)
            W_s[idx] = opw[(dc + idx/DI)*DM + (idx % DI)];
        __syncthreads();
#pragma unroll
        for (int dd = 0; dd < 16; dd++) {
            float y0 = ym_s[(px + 0)*DI + dc + dd];
            float y1 = ym_s[(px + 1)*DI + dc + dd];
#pragma unroll
            for (int j = 0; j < 12; j += 4) {
                float4 wq = *(const float4*)&W_s[dd*DI + c0 + j];
                acc[0][j]   = fmaf(y0, wq.x, acc[0][j]);
                acc[0][j+1] = fmaf(y0, wq.y, acc[0][j+1]);
                acc[0][j+2] = fmaf(y0, wq.z, acc[0][j+2]);
                acc[0][j+3] = fmaf(y0, wq.w, acc[0][j+3]);
                acc[1][j]   = fmaf(y1, wq.x, acc[1][j]);
                acc[1][j+1] = fmaf(y1, wq.y, acc[1][j+1]);
                acc[1][j+2] = fmaf(y1, wq.z, acc[1][j+2]);
                acc[1][j+3] = fmaf(y1, wq.w, acc[1][j+3]);
            }
        }
    }
#pragma unroll
    for (int i = 0; i < 2; i++) {
        int p = p0 + px + i;
#pragma unroll
        for (int j = 0; j < 12; j++) {
            int c = c0 + j;
            out[((size_t)(b*DM + c))*LL + p] = acc[i][j];
        }
    }
}

// ---------------- launch ----------------------------------------------------
extern "C" void kernel_launch(void* const* d_in, const int* in_sizes, int n_in,
                              void* d_out, int out_size) {
    const float* x    = (const float*)d_in[0];
    const float* y    = (const float*)d_in[1];
    const float* wx   = (const float*)d_in[2];
    const float* wy   = (const float*)d_in[3];
    const float* xpw  = (const float*)d_in[4];
    const float* dtw  = (const float*)d_in[5];
    const float* dtb  = (const float*)d_in[6];
    const float* Alog = (const float*)d_in[7];
    const float* Ds   = (const float*)d_in[8];
    const float* gam  = (const float*)d_in[9];
    const float* bet  = (const float*)d_in[10];
    const float* opw  = (const float*)d_in[11];
    float* out = (float*)d_out;

    k0_init<<<1, 256>>>(Alog, Ds);
    k1_inproj<<<dim3(256, 2), 256>>>(x, y, wx, wy);
    k2_xproj<<<dim3(LL/32, KK, BATCH), 256>>>(xpw, dtw, dtb);
    k3_pass1<<<dim3(NC, KK, BATCH), 192>>>();
    k3_comb<<<192, 256>>>();
    k3_pass3<<<dim3(NC, KK, BATCH), 192>>>();
    k5_merge<<<dim3(LL/32, BATCH), 256>>>(gam, bet, opw, out);
}

// round 4
// speedup vs baseline: 4.4864x; 1.5160x over previous
#include <cuda_runtime.h>

#define BATCH 4
#define DM 192
#define DI 192
#define LL 4096
#define KK 4
#define NS 16
#define RR 12
#define CPROJ 44   // RR + 2*NS
#define CT 32      // chunk length
#define NC 128     // number of chunks

typedef unsigned long long u64;

// ---------------- scratch (static device allocations) -----------------------
__device__ __align__(16) float g_xin[BATCH*LL*DI];
__device__ __align__(16) float g_yin[BATCH*LL*DI];
__device__ __align__(16) float g_delta[(size_t)BATCH*KK*LL*DI];
__device__ __align__(16) float g_Bs[BATCH*KK*LL*NS];
__device__ __align__(16) float g_Cs[BATCH*KK*LL*NS];
__device__ __align__(16) float g_sy[(size_t)BATCH*KK*LL*DI];
__device__ __align__(16) float g_anl2[KK*DI*NS];     // A * log2e (negative)
__device__ __align__(16) float g_dsum[DI];
__device__ __align__(16) float g_H  [(size_t)BATCH*KK*DI*NC*NS];
__device__ __align__(16) float g_P  [(size_t)BATCH*KK*DI*NC*NS];
__device__ __align__(16) float g_Hin[(size_t)BATCH*KK*DI*NC*NS];
__device__ int g_fast;

// ---------------- helpers ----------------------------------------------------
__device__ __forceinline__ float ex2f(float x){
    float r; asm("ex2.approx.ftz.f32 %0, %1;" : "=f"(r) : "f"(x)); return r;
}
__device__ __forceinline__ float lg2f(float x){
    float r; asm("lg2.approx.f32 %0, %1;" : "=f"(r) : "f"(x)); return r;
}
__device__ __forceinline__ u64 pk(float lo, float hi){
    u64 r; asm("mov.b64 %0, {%1,%2};" : "=l"(r) : "f"(lo), "f"(hi)); return r;
}
__device__ __forceinline__ void upk(u64 v, float& lo, float& hi){
    asm("mov.b64 {%0,%1}, %2;" : "=f"(lo), "=f"(hi) : "l"(v));
}
__device__ __forceinline__ u64 mul2(u64 a, u64 b){
    u64 r; asm("mul.rn.f32x2 %0, %1, %2;" : "=l"(r) : "l"(a), "l"(b)); return r;
}
__device__ __forceinline__ u64 fma2(u64 a, u64 b, u64 c){
    u64 r; asm("fma.rn.f32x2 %0, %1, %2, %3;" : "=l"(r) : "l"(a), "l"(b), "l"(c)); return r;
}
__device__ __forceinline__ float softplusf(float x){
    float t = ex2f(-fabsf(x) * 1.4426950408889634f);
    return fmaxf(x, 0.f) + 0.6931471805599453f * lg2f(1.0f + t);
}
__device__ __forceinline__ int perm_pixel(int k, int l) {
    if (k == 0) return l;
    if (k == 1) return (l & 63)*64 + (l >> 6);
    if (k == 2) return LL - 1 - l;
    int l2 = LL - 1 - l;
    return (l2 & 63)*64 + (l2 >> 6);
}

// ---------------- kernel 0: precompute --------------------------------------
__global__ void k0_init(const float* __restrict__ A_logs, const float* __restrict__ Ds) {
    int t = threadIdx.x;
    if (t == 0) g_fast = 1;
    for (int i = t; i < KK*DI*NS; i += blockDim.x)
        g_anl2[i] = -expf(A_logs[i]) * 1.4426950408889634f;
    if (t < DI) g_dsum[t] = Ds[t] + Ds[DI + t] + Ds[2*DI + t] + Ds[3*DI + t];
    __syncthreads();
    int ok = 1;
    for (int i = t; i < KK*DI*NS; i += blockDim.x) {
        int n = i % NS;
        float base = g_anl2[i - n];
        float want = (float)(n + 1) * base;
        if (fabsf(g_anl2[i] - want) > 1e-3f * fabsf(want) + 1e-12f) ok = 0;
    }
    if (!ok) atomicExch(&g_fast, 0);
}

// ---------------- kernel 1: in_proj (f32x2) ---------------------------------
__global__ void k1_inproj(const float* __restrict__ x, const float* __restrict__ y,
                          const float* __restrict__ wx, const float* __restrict__ wy) {
    __shared__ __align__(16) float xs_s[16][64];
    __shared__ __align__(16) float ws_s[16][192];
    const float* src = blockIdx.y ? y : x;
    const float* w   = blockIdx.y ? wy : wx;
    float* dst       = blockIdx.y ? g_yin : g_xin;
    int tile = blockIdx.x;
    int b  = tile >> 6;
    int p0 = (tile & 63) * 64;
    int t  = threadIdx.x;
    int dg = t & 15;
    int pg = t >> 4;
    int d0 = dg * 12;
    int px = pg * 4;
    u64 acc2[4][6];
#pragma unroll
    for (int i = 0; i < 4; i++)
#pragma unroll
        for (int j = 0; j < 6; j++) acc2[i][j] = 0ull;

    for (int c0 = 0; c0 < DM; c0 += 16) {
        __syncthreads();
        for (int idx = t; idx < 16*64; idx += 256) {
            int cc = idx >> 6, j = idx & 63;
            xs_s[cc][j] = src[((size_t)(b*DM + c0 + cc))*LL + p0 + j];
        }
        for (int idx = t; idx < 16*192; idx += 256) {
            int cc = idx / 192, d = idx % 192;
            ws_s[cc][d] = w[(c0 + cc)*DI + d];
        }
        __syncthreads();
#pragma unroll
        for (int cc = 0; cc < 16; cc++) {
            float4 xv = *(const float4*)&xs_s[cc][px];
            ulonglong2 wq0 = *(const ulonglong2*)&ws_s[cc][d0];
            ulonglong2 wq1 = *(const ulonglong2*)&ws_s[cc][d0+4];
            ulonglong2 wq2 = *(const ulonglong2*)&ws_s[cc][d0+8];
            u64 wp[6] = {wq0.x, wq0.y, wq1.x, wq1.y, wq2.x, wq2.y};
            u64 xp[4] = {pk(xv.x,xv.x), pk(xv.y,xv.y), pk(xv.z,xv.z), pk(xv.w,xv.w)};
#pragma unroll
            for (int i = 0; i < 4; i++)
#pragma unroll
                for (int j = 0; j < 6; j++)
                    acc2[i][j] = fma2(xp[i], wp[j], acc2[i][j]);
        }
    }
#pragma unroll
    for (int i = 0; i < 4; i++) {
        float o[12];
#pragma unroll
        for (int j = 0; j < 6; j++) upk(acc2[i][j], o[2*j], o[2*j+1]);
        float* op = dst + ((size_t)b*LL + p0 + px + i)*DI + d0;
        *(float4*)(op + 0) = make_float4(o[0], o[1], o[2], o[3]);
        *(float4*)(op + 4) = make_float4(o[4], o[5], o[6], o[7]);
        *(float4*)(op + 8) = make_float4(o[8], o[9], o[10], o[11]);
    }
}

// ---------------- kernel 2: x_proj + dt_proj + softplus + B/C ---------------
#define XSTR 36
#define PSTR 34
__global__ void k2_xproj(const float* __restrict__ xpw, const float* __restrict__ dtw,
                         const float* __restrict__ dtb) {
    __shared__ __align__(16) float xin_s[DI*XSTR];     // [d][l] transposed
    __shared__ __align__(16) float proj_s[CPROJ*PSTR]; // [c][l]
    __shared__ __align__(16) float dtw_s[DI*RR];
    int ltile = blockIdx.x * 32;
    int k = blockIdx.y, b = blockIdx.z;
    int t = threadIdx.x;

    for (int i = t; i < DI*RR; i += 256) dtw_s[i] = dtw[k*DI*RR + i];
    for (int idx = t; idx < 32*DI; idx += 256) {
        int l = idx / DI, d = idx % DI;
        int p = perm_pixel(k, ltile + l);
        xin_s[d*XSTR + l] = g_xin[((size_t)b*LL + p)*DI + d];
    }
    __syncthreads();

    // phase 2: proj[c][l] = dot over d, 8 l's per thread as 4 packed pairs
    if (t < 176) {
        int c  = t >> 2;
        int lg = t & 3;
        const float* wrow = xpw + ((size_t)k*CPROJ + c)*DI;
        u64 a2[4] = {0ull, 0ull, 0ull, 0ull};
        for (int d0 = 0; d0 < DI; d0 += 4) {
            float4 wv = *(const float4*)(wrow + d0);
            float wvv[4] = {wv.x, wv.y, wv.z, wv.w};
#pragma unroll
            for (int dd = 0; dd < 4; dd++) {
                u64 wp = pk(wvv[dd], wvv[dd]);
                ulonglong2 xq0 = *(const ulonglong2*)&xin_s[(d0+dd)*XSTR + lg*8];
                ulonglong2 xq1 = *(const ulonglong2*)&xin_s[(d0+dd)*XSTR + lg*8 + 4];
                a2[0] = fma2(wp, xq0.x, a2[0]);
                a2[1] = fma2(wp, xq0.y, a2[1]);
                a2[2] = fma2(wp, xq1.x, a2[2]);
                a2[3] = fma2(wp, xq1.y, a2[3]);
            }
        }
        float o[8];
#pragma unroll
        for (int j = 0; j < 4; j++) upk(a2[j], o[2*j], o[2*j+1]);
#pragma unroll
        for (int j = 0; j < 8; j++) proj_s[c*PSTR + lg*8 + j] = o[j];
    }
    __syncthreads();

    if (t < DI) {
        // delta[l][d] = softplus(dtw[d]·proj[0:12][l] + bias[d]) ; l-pairs packed
        int d = t;
        u64 wp[RR];
#pragma unroll
        for (int r = 0; r < RR; r++) { float wv = dtw_s[d*RR + r]; wp[r] = pk(wv, wv); }
        float bias = dtb[k*DI + d];
        u64 bp = pk(bias, bias);
        float* dptr = g_delta + ((size_t)(b*KK + k)*LL + ltile)*DI + d;
#pragma unroll 2
        for (int jp = 0; jp < 16; jp++) {
            u64 a2 = bp;
#pragma unroll
            for (int r = 0; r < RR; r++) {
                u64 pq = *(const u64*)&proj_s[r*PSTR + 2*jp];
                a2 = fma2(wp[r], pq, a2);
            }
            float v0, v1; upk(a2, v0, v1);
            dptr[(size_t)(2*jp  )*DI] = softplusf(v0);
            dptr[(size_t)(2*jp+1)*DI] = softplusf(v1);
        }
    } else {
        int tt = t - DI;
        size_t base = ((size_t)(b*KK + k)*LL + ltile)*NS;
        for (int idx = tt; idx < 32*NS*2; idx += 64) {
            int l = idx >> 5, m = idx & 31;
            if (m < NS) g_Bs[base + l*NS + m]        = proj_s[(RR + m)*PSTR + l];
            else        g_Cs[base + l*NS + (m - NS)] = proj_s[(RR + m)*PSTR + l];
        }
    }
}

// ---------------- scan: packed pow helper ------------------------------------
// P[0..7] = (w^1,w^2),(w^3,w^4),...,(w^15,w^16)
__device__ __forceinline__ void pows16p(float w, u64* P){
    float w2 = w*w, w4 = w2*w2;
    u64 W2 = pk(w2,w2), W4 = pk(w4,w4);
    P[0] = pk(w, w2);
    P[1] = mul2(P[0], W2);
    P[2] = mul2(P[0], W4);
    P[3] = mul2(P[1], W4);
    P[4] = mul2(P[2], W4);
    P[5] = mul2(P[3], W4);
    P[6] = mul2(P[4], W4);
    P[7] = mul2(P[5], W4);
}

__device__ __forceinline__ int dir_step(int k){
    return (k==0) ? 1 : (k==1) ? 64 : (k==2) ? -1 : -64;
}

// ---------------- pass1 (FAST) ----------------------------------------------
__global__ __launch_bounds__(192, 5) void k3f_pass1() {
    if (!g_fast) return;
    int c = blockIdx.x, k = blockIdx.y, b = blockIdx.z;
    int d = threadIdx.x;
    size_t bk = (size_t)(b*KK + k);
    int l0 = c * CT;
    const float* dp = g_delta + (bk*LL + (size_t)l0)*DI + d;
    const ulonglong2* Bq = (const ulonglong2*)(g_Bs + (bk*LL + (size_t)l0)*NS);
    int pst = dir_step(k);
    int p0  = perm_pixel(k, l0);
    const float* up = g_yin + ((size_t)b*LL + p0)*DI + d;
    int ustep = pst * DI;
    float an0 = g_anl2[((size_t)k*DI + d)*NS];

    u64 h2[8];
#pragma unroll
    for (int i = 0; i < 8; i++) h2[i] = 0ull;
    float S = 0.f;

#pragma unroll 4
    for (int t = 0; t < CT; t++) {
        float dlt = *dp;
        float uv  = *up;
        ulonglong2 bA = Bq[0], bB = Bq[1], bC = Bq[2], bD = Bq[3];
        u64 P[8]; pows16p(ex2f(dlt * an0), P);
        float du = dlt * uv;
        u64 DU = pk(du, du);
        h2[0] = fma2(P[0], h2[0], mul2(DU, bA.x));
        h2[1] = fma2(P[1], h2[1], mul2(DU, bA.y));
        h2[2] = fma2(P[2], h2[2], mul2(DU, bB.x));
        h2[3] = fma2(P[3], h2[3], mul2(DU, bB.y));
        h2[4] = fma2(P[4], h2[4], mul2(DU, bC.x));
        h2[5] = fma2(P[5], h2[5], mul2(DU, bC.y));
        h2[6] = fma2(P[6], h2[6], mul2(DU, bD.x));
        h2[7] = fma2(P[7], h2[7], mul2(DU, bD.y));
        S += dlt;
        dp += DI; up += ustep; Bq += 4;
    }
    size_t ch = bk*DI + d;
    u64* Hp = (u64*)(g_H + (ch*NC + c)*NS);
    u64* Pp = (u64*)(g_P + (ch*NC + c)*NS);
    u64 Q[8]; pows16p(ex2f(an0 * S), Q);
#pragma unroll
    for (int i = 0; i < 8; i++) { Hp[i] = h2[i]; Pp[i] = Q[i]; }
}

// ---------------- pass1 (generic fallback) ----------------------------------
__global__ __launch_bounds__(192) void k3s_pass1() {
    if (g_fast) return;
    int c = blockIdx.x, k = blockIdx.y, b = blockIdx.z;
    int d = threadIdx.x;
    size_t bk = (size_t)(b*KK + k);
    int l0 = c * CT;
    const float* dp = g_delta + (bk*LL + (size_t)l0)*DI + d;
    const float* Bp = g_Bs + (bk*LL + (size_t)l0)*NS;
    int pst = dir_step(k);
    const float* up = g_yin + ((size_t)b*LL + perm_pixel(k, l0))*DI + d;
    int ustep = pst * DI;
    float an[NS];
    const float* ap = g_anl2 + ((size_t)k*DI + d)*NS;
#pragma unroll
    for (int n = 0; n < NS; n++) an[n] = ap[n];
    float h[NS];
#pragma unroll
    for (int n = 0; n < NS; n++) h[n] = 0.f;
    float S = 0.f;
    for (int t = 0; t < CT; t++) {
        float dlt = *dp, uv = *up;
        float du = dlt * uv;
#pragma unroll
        for (int n = 0; n < NS; n++)
            h[n] = fmaf(ex2f(dlt*an[n]), h[n], du * Bp[n]);
        S += dlt;
        dp += DI; up += ustep; Bp += NS;
    }
    size_t ch = bk*DI + d;
    float* Hp = g_H + (ch*NC + c)*NS;
    float* Pp = g_P + (ch*NC + c)*NS;
#pragma unroll
    for (int n = 0; n < NS; n++) { Hp[n] = h[n]; Pp[n] = ex2f(an[n]*S); }
}

// ---------------- combine ----------------------------------------------------
__global__ void k3_comb() {
    int t = blockIdx.x * blockDim.x + threadIdx.x;
    int n = t & 15;
    size_t ch = (size_t)(t >> 4);
    const float* __restrict__ Hp = g_H   + ch*NC*NS + n;
    const float* __restrict__ Pp = g_P   + ch*NC*NS + n;
    float*       __restrict__ Ip = g_Hin + ch*NC*NS + n;
    float h = 0.f;
#pragma unroll 4
    for (int c = 0; c < NC; c++) {
        Ip[c*NS] = h;
        h = fmaf(Pp[c*NS], h, Hp[c*NS]);
    }
}

// ---------------- pass3 (FAST) ----------------------------------------------
__global__ __launch_bounds__(192, 5) void k3f_pass3() {
    if (!g_fast) return;
    int c = blockIdx.x, k = blockIdx.y, b = blockIdx.z;
    int d = threadIdx.x;
    size_t bk = (size_t)(b*KK + k);
    int l0 = c * CT;
    const float* dp = g_delta + (bk*LL + (size_t)l0)*DI + d;
    const ulonglong2* Bq = (const ulonglong2*)(g_Bs + (bk*LL + (size_t)l0)*NS);
    const ulonglong2* Cq = (const ulonglong2*)(g_Cs + (bk*LL + (size_t)l0)*NS);
    float* op = g_sy + (bk*LL + (size_t)l0)*DI + d;
    int pst = dir_step(k);
    const float* up = g_yin + ((size_t)b*LL + perm_pixel(k, l0))*DI + d;
    int ustep = pst * DI;
    float an0 = g_anl2[((size_t)k*DI + d)*NS];

    size_t ch = bk*DI + d;
    const u64* Ip = (const u64*)(g_Hin + (ch*NC + c)*NS);
    u64 h2[8];
#pragma unroll
    for (int i = 0; i < 8; i++) h2[i] = Ip[i];

#pragma unroll 4
    for (int t = 0; t < CT; t++) {
        float dlt = *dp;
        float uv  = *up;
        ulonglong2 bA = Bq[0], bB = Bq[1], bC = Bq[2], bD = Bq[3];
        ulonglong2 cA = Cq[0], cB = Cq[1], cC = Cq[2], cD = Cq[3];
        u64 P[8]; pows16p(ex2f(dlt * an0), P);
        float du = dlt * uv;
        u64 DU = pk(du, du);
        h2[0] = fma2(P[0], h2[0], mul2(DU, bA.x));
        h2[1] = fma2(P[1], h2[1], mul2(DU, bA.y));
        h2[2] = fma2(P[2], h2[2], mul2(DU, bB.x));
        h2[3] = fma2(P[3], h2[3], mul2(DU, bB.y));
        h2[4] = fma2(P[4], h2[4], mul2(DU, bC.x));
        h2[5] = fma2(P[5], h2[5], mul2(DU, bC.y));
        h2[6] = fma2(P[6], h2[6], mul2(DU, bD.x));
        h2[7] = fma2(P[7], h2[7], mul2(DU, bD.y));
        u64 Y;
        Y = mul2(h2[0], cA.x);
        Y = fma2(h2[1], cA.y, Y);
        Y = fma2(h2[2], cB.x, Y);
        Y = fma2(h2[3], cB.y, Y);
        Y = fma2(h2[4], cC.x, Y);
        Y = fma2(h2[5], cC.y, Y);
        Y = fma2(h2[6], cD.x, Y);
        Y = fma2(h2[7], cD.y, Y);
        float ylo, yhi; upk(Y, ylo, yhi);
        *op = ylo + yhi;
        dp += DI; up += ustep; Bq += 4; Cq += 4; op += DI;
    }
}

// ---------------- pass3 (generic fallback) ----------------------------------
__global__ __launch_bounds__(192) void k3s_pass3() {
    if (g_fast) return;
    int c = blockIdx.x, k = blockIdx.y, b = blockIdx.z;
    int d = threadIdx.x;
    size_t bk = (size_t)(b*KK + k);
    int l0 = c * CT;
    const float* dp = g_delta + (bk*LL + (size_t)l0)*DI + d;
    const float* Bp = g_Bs + (bk*LL + (size_t)l0)*NS;
    const float* Cp = g_Cs + (bk*LL + (size_t)l0)*NS;
    float* op = g_sy + (bk*LL + (size_t)l0)*DI + d;
    int pst = dir_step(k);
    const float* up = g_yin + ((size_t)b*LL + perm_pixel(k, l0))*DI + d;
    int ustep = pst * DI;
    float an[NS];
    const float* ap = g_anl2 + ((size_t)k*DI + d)*NS;
#pragma unroll
    for (int n = 0; n < NS; n++) an[n] = ap[n];
    size_t ch = bk*DI + d;
    const float* Ip = g_Hin + (ch*NC + c)*NS;
    float h[NS];
#pragma unroll
    for (int n = 0; n < NS; n++) h[n] = Ip[n];
    for (int t = 0; t < CT; t++) {
        float dlt = *dp, uv = *up;
        float du = dlt * uv;
        float y = 0.f;
#pragma unroll
        for (int n = 0; n < NS; n++) {
            h[n] = fmaf(ex2f(dlt*an[n]), h[n], du * Bp[n]);
            y = fmaf(h[n], Cp[n], y);
        }
        *op = y;
        dp += DI; up += ustep; Bp += NS; Cp += NS; op += DI;
    }
}

// ---------------- kernel 5: merge + LayerNorm + out_proj --------------------
__global__ void k5_merge(const float* __restrict__ gamma, const float* __restrict__ beta,
                         const float* __restrict__ opw, float* __restrict__ out) {
    __shared__ __align__(16) float ym_s[32*DI];
    __shared__ __align__(16) float W_s[16*DI];
    __shared__ float mu_s[32], rs_s[32];
    int b = blockIdx.y;
    int p0 = blockIdx.x * 32;
    int t = threadIdx.x;
    size_t bb = (size_t)b * KK;

    for (int idx = t; idx < 32*DI; idx += 256) {
        int pl = idx / DI, d = idx % DI;
        int p  = p0 + pl;
        int l1 = (p & 63)*64 + (p >> 6);
        float v = g_sy[((bb + 0)*LL + p)*DI + d]
                + g_sy[((bb + 2)*LL + (LL-1-p))*DI + d]
                + g_sy[((bb + 1)*LL + l1)*DI + d]
                + g_sy[((bb + 3)*LL + (LL-1-l1))*DI + d]
                + g_dsum[d] * g_yin[((size_t)b*LL + p)*DI + d];
        ym_s[pl*DI + d] = v;
    }
    __syncthreads();

    {
        int warp = t >> 5, lane = t & 31;
        int pl  = warp*4 + (lane >> 3);
        int sub = lane & 7;
        float s = 0.f, s2 = 0.f;
        for (int j = sub; j < DI; j += 8) { float v = ym_s[pl*DI + j]; s += v; s2 += v*v; }
        s  += __shfl_xor_sync(0xffffffffu, s, 4);  s2 += __shfl_xor_sync(0xffffffffu, s2, 4);
        s  += __shfl_xor_sync(0xffffffffu, s, 2);  s2 += __shfl_xor_sync(0xffffffffu, s2, 2);
        s  += __shfl_xor_sync(0xffffffffu, s, 1);  s2 += __shfl_xor_sync(0xffffffffu, s2, 1);
        if (sub == 0) {
            float mu  = s * (1.f/DI);
            float var = s2 * (1.f/DI) - mu*mu;
            mu_s[pl] = mu;
            rs_s[pl] = rsqrtf(var + 1e-5f);
        }
    }
    __syncthreads();

    for (int idx = t; idx < 32*DI; idx += 256) {
        int pl = idx / DI, d = idx % DI;
        ym_s[idx] = (ym_s[idx] - mu_s[pl]) * rs_s[pl] * gamma[d] + beta[d];
    }

    int c0 = (t & 15) * 12;
    int px = (t >> 4) * 2;
    u64 acc2[2][6];
#pragma unroll
    for (int i = 0; i < 2; i++)
#pragma unroll
        for (int j = 0; j < 6; j++) acc2[i][j] = 0ull;

    for (int dc = 0; dc < DI; dc += 16) {
        __syncthreads();
        for (int idx = t; idx < 16*DI; idx += 256)
            W_s[idx] = opw[(dc + idx/DI)*DM + (idx % DI)];
        __syncthreads();
#pragma unroll
        for (int dd = 0; dd < 16; dd++) {
            float y0 = ym_s[(px + 0)*DI + dc + dd];
            float y1 = ym_s[(px + 1)*DI + dc + dd];
            u64 yp0 = pk(y0, y0), yp1 = pk(y1, y1);
            ulonglong2 wq0 = *(const ulonglong2*)&W_s[dd*DI + c0];
            ulonglong2 wq1 = *(const ulonglong2*)&W_s[dd*DI + c0 + 4];
            ulonglong2 wq2 = *(const ulonglong2*)&W_s[dd*DI + c0 + 8];
            u64 wp[6] = {wq0.x, wq0.y, wq1.x, wq1.y, wq2.x, wq2.y};
#pragma unroll
            for (int j = 0; j < 6; j++) {
                acc2[0][j] = fma2(yp0, wp[j], acc2[0][j]);
                acc2[1][j] = fma2(yp1, wp[j], acc2[1][j]);
            }
        }
    }
#pragma unroll
    for (int i = 0; i < 2; i++) {
        int p = p0 + px + i;
        float o[12];
#pragma unroll
        for (int j = 0; j < 6; j++) upk(acc2[i][j], o[2*j], o[2*j+1]);
#pragma unroll
        for (int j = 0; j < 12; j++)
            out[((size_t)(b*DM + c0 + j))*LL + p] = o[j];
    }
}

// ---------------- launch ----------------------------------------------------
extern "C" void kernel_launch(void* const* d_in, const int* in_sizes, int n_in,
                              void* d_out, int out_size) {
    const float* x    = (const float*)d_in[0];
    const float* y    = (const float*)d_in[1];
    const float* wx   = (const float*)d_in[2];
    const float* wy   = (const float*)d_in[3];
    const float* xpw  = (const float*)d_in[4];
    const float* dtw  = (const float*)d_in[5];
    const float* dtb  = (const float*)d_in[6];
    const float* Alog = (const float*)d_in[7];
    const float* Ds   = (const float*)d_in[8];
    const float* gam  = (const float*)d_in[9];
    const float* bet  = (const float*)d_in[10];
    const float* opw  = (const float*)d_in[11];
    float* out = (float*)d_out;

    k0_init<<<1, 256>>>(Alog, Ds);
    k1_inproj<<<dim3(256, 2), 256>>>(x, y, wx, wy);
    k2_xproj<<<dim3(LL/32, KK, BATCH), 256>>>(xpw, dtw, dtb);
    k3f_pass1<<<dim3(NC, KK, BATCH), 192>>>();
    k3s_pass1<<<dim3(NC, KK, BATCH), 192>>>();
    k3_comb<<<192, 256>>>();
    k3f_pass3<<<dim3(NC, KK, BATCH), 192>>>();
    k3s_pass3<<<dim3(NC, KK, BATCH), 192>>>();
    k5_merge<<<dim3(LL/32, BATCH), 256>>>(gam, bet, opw, out);
}

// round 5
// speedup vs baseline: 4.6501x; 1.0365x over previous
#include <cuda_runtime.h>

#define BATCH 4
#define DM 192
#define DI 192
#define LL 4096
#define KK 4
#define NS 16
#define RR 12
#define CPROJ 44
#define CT 32
#define NC 128

typedef unsigned long long u64;

__device__ __align__(16) float g_xin[BATCH*LL*DI];
__device__ __align__(16) float g_yin[BATCH*LL*DI];
__device__ __align__(16) float g_delta[(size_t)BATCH*KK*LL*DI]; // pass1 overwrites with Scum
__device__ __align__(16) float g_Bs[BATCH*KK*LL*NS];
__device__ __align__(16) float g_Cs[BATCH*KK*LL*NS];
__device__ __align__(16) float g_sy[(size_t)BATCH*KK*LL*DI];
__device__ __align__(16) float g_anl2[KK*DI*NS];
__device__ __align__(16) float g_dsum[DI];
__device__ __align__(16) float g_H  [(size_t)BATCH*KK*DI*NC*NS];
__device__ __align__(16) float g_P  [(size_t)BATCH*KK*DI*NC*NS];
__device__ __align__(16) float g_Hin[(size_t)BATCH*KK*DI*NC*NS];
__device__ int g_fast;

__device__ __forceinline__ float ex2f(float x){
    float r; asm("ex2.approx.ftz.f32 %0, %1;" : "=f"(r) : "f"(x)); return r;
}
__device__ __forceinline__ float lg2f(float x){
    float r; asm("lg2.approx.f32 %0, %1;" : "=f"(r) : "f"(x)); return r;
}
__device__ __forceinline__ u64 pk(float lo, float hi){
    u64 r; asm("mov.b64 %0, {%1,%2};" : "=l"(r) : "f"(lo), "f"(hi)); return r;
}
__device__ __forceinline__ void upk(u64 v, float& lo, float& hi){
    asm("mov.b64 {%0,%1}, %2;" : "=f"(lo), "=f"(hi) : "l"(v));
}
__device__ __forceinline__ u64 mul2(u64 a, u64 b){
    u64 r; asm("mul.rn.f32x2 %0, %1, %2;" : "=l"(r) : "l"(a), "l"(b)); return r;
}
__device__ __forceinline__ u64 fma2(u64 a, u64 b, u64 c){
    u64 r; asm("fma.rn.f32x2 %0, %1, %2, %3;" : "=l"(r) : "l"(a), "l"(b), "l"(c)); return r;
}
__device__ __forceinline__ float softplusf(float x){
    float t = ex2f(-fabsf(x) * 1.4426950408889634f);
    return fmaxf(x, 0.f) + 0.6931471805599453f * lg2f(1.0f + t);
}
__device__ __forceinline__ int perm_pixel(int k, int l) {
    if (k == 0) return l;
    if (k == 1) return (l & 63)*64 + (l >> 6);
    if (k == 2) return LL - 1 - l;
    int l2 = LL - 1 - l;
    return (l2 & 63)*64 + (l2 >> 6);
}
__device__ __forceinline__ int dir_step(int k){
    return (k==0) ? 1 : (k==1) ? 64 : (k==2) ? -1 : -64;
}
__device__ __forceinline__ void pows16p(float w, u64* P){
    float w2 = w*w, w4 = w2*w2;
    u64 W2 = pk(w2,w2), W4 = pk(w4,w4);
    P[0] = pk(w, w2);
    P[1] = mul2(P[0], W2);
    P[2] = mul2(P[0], W4);
    P[3] = mul2(P[1], W4);
    P[4] = mul2(P[2], W4);
    P[5] = mul2(P[3], W4);
    P[6] = mul2(P[4], W4);
    P[7] = mul2(P[5], W4);
}

__global__ void k0_init(const float* __restrict__ A_logs, const float* __restrict__ Ds) {
    int t = threadIdx.x;
    if (t == 0) g_fast = 1;
    for (int i = t; i < KK*DI*NS; i += blockDim.x)
        g_anl2[i] = -expf(A_logs[i]) * 1.4426950408889634f;
    if (t < DI) g_dsum[t] = Ds[t] + Ds[DI + t] + Ds[2*DI + t] + Ds[3*DI + t];
    __syncthreads();
    int ok = 1;
    for (int i = t; i < KK*DI*NS; i += blockDim.x) {
        int n = i % NS;
        float base = g_anl2[i - n];
        float want = (float)(n + 1) * base;
        if (fabsf(g_anl2[i] - want) > 1e-3f * fabsf(want) + 1e-12f) ok = 0;
    }
    if (!ok) atomicExch(&g_fast, 0);
}

__global__ void k1_inproj(const float* __restrict__ x, const float* __restrict__ y,
                          const float* __restrict__ wx, const float* __restrict__ wy) {
    __shared__ __align__(16) float xs_s[16][64];
    __shared__ __align__(16) float ws_s[16][192];
    const float* src = blockIdx.y ? y : x;
    const float* w   = blockIdx.y ? wy : wx;
    float* dst       = blockIdx.y ? g_yin : g_xin;
    int tile = blockIdx.x;
    int b  = tile >> 6;
    int p0 = (tile & 63) * 64;
    int t  = threadIdx.x;
    int dg = t & 15;
    int pg = t >> 4;
    int d0 = dg * 12;
    int px = pg * 4;
    u64 acc2[4][6];
#pragma unroll
    for (int i = 0; i < 4; i++)
#pragma unroll
        for (int j = 0; j < 6; j++) acc2[i][j] = 0ull;

    for (int c0 = 0; c0 < DM; c0 += 16) {
        __syncthreads();
        for (int idx = t; idx < 16*64; idx += 256) {
            int cc = idx >> 6, j = idx & 63;
            xs_s[cc][j] = src[((size_t)(b*DM + c0 + cc))*LL + p0 + j];
        }
        for (int idx = t; idx < 16*192; idx += 256) {
            int cc = idx / 192, d = idx % 192;
            ws_s[cc][d] = w[(c0 + cc)*DI + d];
        }
        __syncthreads();
#pragma unroll
        for (int cc = 0; cc < 16; cc++) {
            float4 xv = *(const float4*)&xs_s[cc][px];
            ulonglong2 wq0 = *(const ulonglong2*)&ws_s[cc][d0];
            ulonglong2 wq1 = *(const ulonglong2*)&ws_s[cc][d0+4];
            ulonglong2 wq2 = *(const ulonglong2*)&ws_s[cc][d0+8];
            u64 wp[6] = {wq0.x, wq0.y, wq1.x, wq1.y, wq2.x, wq2.y};
            u64 xp[4] = {pk(xv.x,xv.x), pk(xv.y,xv.y), pk(xv.z,xv.z), pk(xv.w,xv.w)};
#pragma unroll
            for (int i = 0; i < 4; i++)
#pragma unroll
                for (int j = 0; j < 6; j++)
                    acc2[i][j] = fma2(xp[i], wp[j], acc2[i][j]);
        }
    }
#pragma unroll
    for (int i = 0; i < 4; i++) {
        float o[12];
#pragma unroll
        for (int j = 0; j < 6; j++) upk(acc2[i][j], o[2*j], o[2*j+1]);
        float* op = dst + ((size_t)b*LL + p0 + px + i)*DI + d0;
        *(float4*)(op + 0) = make_float4(o[0], o[1], o[2], o[3]);
        *(float4*)(op + 4) = make_float4(o[4], o[5], o[6], o[7]);
        *(float4*)(op + 8) = make_float4(o[8], o[9], o[10], o[11]);
    }
}

#define XSTR 36
#define PSTR 34
__global__ void k2_xproj(const float* __restrict__ xpw, const float* __restrict__ dtw,
                         const float* __restrict__ dtb) {
    __shared__ __align__(16) float xin_s[DI*XSTR];
    __shared__ __align__(16) float proj_s[CPROJ*PSTR];
    __shared__ __align__(16) float dtw_s[DI*RR];
    int ltile = blockIdx.x * 32;
    int k = blockIdx.y, b = blockIdx.z;
    int t = threadIdx.x;

    for (int i = t; i < DI*RR; i += 256) dtw_s[i] = dtw[k*DI*RR + i];
    for (int idx = t; idx < 32*DI; idx += 256) {
        int l = idx / DI, d = idx % DI;
        int p = perm_pixel(k, ltile + l);
        xin_s[d*XSTR + l] = g_xin[((size_t)b*LL + p)*DI + d];
    }
    __syncthreads();

    if (t < 176) {
        int c  = t >> 2;
        int lg = t & 3;
        const float* wrow = xpw + ((size_t)k*CPROJ + c)*DI;
        u64 a2[4] = {0ull, 0ull, 0ull, 0ull};
        for (int d0 = 0; d0 < DI; d0 += 4) {
            float4 wv = *(const float4*)(wrow + d0);
            float wvv[4] = {wv.x, wv.y, wv.z, wv.w};
#pragma unroll
            for (int dd = 0; dd < 4; dd++) {
                u64 wp = pk(wvv[dd], wvv[dd]);
                ulonglong2 xq0 = *(const ulonglong2*)&xin_s[(d0+dd)*XSTR + lg*8];
                ulonglong2 xq1 = *(const ulonglong2*)&xin_s[(d0+dd)*XSTR + lg*8 + 4];
                a2[0] = fma2(wp, xq0.x, a2[0]);
                a2[1] = fma2(wp, xq0.y, a2[1]);
                a2[2] = fma2(wp, xq1.x, a2[2]);
                a2[3] = fma2(wp, xq1.y, a2[3]);
            }
        }
        float o[8];
#pragma unroll
        for (int j = 0; j < 4; j++) upk(a2[j], o[2*j], o[2*j+1]);
#pragma unroll
        for (int j = 0; j < 8; j++) proj_s[c*PSTR + lg*8 + j] = o[j];
    }
    __syncthreads();

    if (t < DI) {
        int d = t;
        u64 wp[RR];
#pragma unroll
        for (int r = 0; r < RR; r++) { float wv = dtw_s[d*RR + r]; wp[r] = pk(wv, wv); }
        float bias = dtb[k*DI + d];
        u64 bp = pk(bias, bias);
        float* dptr = g_delta + ((size_t)(b*KK + k)*LL + ltile)*DI + d;
#pragma unroll 2
        for (int jp = 0; jp < 16; jp++) {
            u64 a2 = bp;
#pragma unroll
            for (int r = 0; r < RR; r++) {
                u64 pq = *(const u64*)&proj_s[r*PSTR + 2*jp];
                a2 = fma2(wp[r], pq, a2);
            }
            float v0, v1; upk(a2, v0, v1);
            dptr[(size_t)(2*jp  )*DI] = softplusf(v0);
            dptr[(size_t)(2*jp+1)*DI] = softplusf(v1);
        }
    } else {
        int tt = t - DI;
        size_t base = ((size_t)(b*KK + k)*LL + ltile)*NS;
        for (int idx = tt; idx < 32*NS*2; idx += 64) {
            int l = idx >> 5, m = idx & 31;
            if (m < NS) g_Bs[base + l*NS + m]        = proj_s[(RR + m)*PSTR + l];
            else        g_Cs[base + l*NS + (m - NS)] = proj_s[(RR + m)*PSTR + l];
        }
    }
}

// ---- pass1 (FAST): full recursion + C-dot + y_local + Scum + summaries ------
__global__ __launch_bounds__(192, 5) void k3f_pass1() {
    if (!g_fast) return;
    __shared__ __align__(16) float sB[CT*NS];
    __shared__ __align__(16) float sC[CT*NS];
    int c = blockIdx.x, k = blockIdx.y, b = blockIdx.z;
    int d = threadIdx.x;
    size_t bk = (size_t)(b*KK + k);
    int l0 = c * CT;
    {
        const float4* Bg = (const float4*)(g_Bs + (bk*LL + (size_t)l0)*NS);
        const float4* Cg = (const float4*)(g_Cs + (bk*LL + (size_t)l0)*NS);
        float4* sB4 = (float4*)sB;
        float4* sC4 = (float4*)sC;
        for (int i = d; i < CT*NS/4; i += 192) { sB4[i] = Bg[i]; sC4[i] = Cg[i]; }
    }
    __syncthreads();

    float* dp = g_delta + (bk*LL + (size_t)l0)*DI + d;
    float* op = g_sy    + (bk*LL + (size_t)l0)*DI + d;
    int pst = dir_step(k);
    const float* up = g_yin + ((size_t)b*LL + perm_pixel(k, l0))*DI + d;
    int ustep = pst * DI;
    float an0 = g_anl2[((size_t)k*DI + d)*NS];

    u64 h2[8];
#pragma unroll
    for (int i = 0; i < 8; i++) h2[i] = 0ull;
    float S = 0.f;

#pragma unroll 4
    for (int t = 0; t < CT; t++) {
        float dlt = dp[(size_t)t*DI];
        float uv  = up[(size_t)t*ustep];
        const u64* Bw = (const u64*)&sB[t*NS];
        const u64* Cw = (const u64*)&sC[t*NS];
        u64 P[8]; pows16p(ex2f(dlt * an0), P);
        float du = dlt * uv;
        u64 DU = pk(du, du);
        u64 Y = 0ull;
#pragma unroll
        for (int i = 0; i < 8; i++) {
            h2[i] = fma2(P[i], h2[i], mul2(DU, Bw[i]));
            Y = fma2(h2[i], Cw[i], Y);
        }
        float ylo, yhi; upk(Y, ylo, yhi);
        op[(size_t)t*DI] = ylo + yhi;
        S += dlt;
        dp[(size_t)t*DI] = S;     // overwrite delta with inclusive prefix sum
    }
    size_t ch = bk*DI + d;
    u64* Hp = (u64*)(g_H + (ch*NC + c)*NS);
    u64* Pp = (u64*)(g_P + (ch*NC + c)*NS);
    u64 Q[8]; pows16p(ex2f(an0 * S), Q);
#pragma unroll
    for (int i = 0; i < 8; i++) { Hp[i] = h2[i]; Pp[i] = Q[i]; }
}

__global__ __launch_bounds__(192) void k3s_pass1() {
    if (g_fast) return;
    int c = blockIdx.x, k = blockIdx.y, b = blockIdx.z;
    int d = threadIdx.x;
    size_t bk = (size_t)(b*KK + k);
    int l0 = c * CT;
    const float* dp = g_delta + (bk*LL + (size_t)l0)*DI + d;
    const float* Bp = g_Bs + (bk*LL + (size_t)l0)*NS;
    int pst = dir_step(k);
    const float* up = g_yin + ((size_t)b*LL + perm_pixel(k, l0))*DI + d;
    int ustep = pst * DI;
    float an[NS];
    const float* ap = g_anl2 + ((size_t)k*DI + d)*NS;
#pragma unroll
    for (int n = 0; n < NS; n++) an[n] = ap[n];
    float h[NS];
#pragma unroll
    for (int n = 0; n < NS; n++) h[n] = 0.f;
    float S = 0.f;
    for (int t = 0; t < CT; t++) {
        float dlt = *dp, uv = *up;
        float du = dlt * uv;
#pragma unroll
        for (int n = 0; n < NS; n++)
            h[n] = fmaf(ex2f(dlt*an[n]), h[n], du * Bp[n]);
        S += dlt;
        dp += DI; up += ustep; Bp += NS;
    }
    size_t ch = bk*DI + d;
    float* Hp = g_H + (ch*NC + c)*NS;
    float* Pp = g_P + (ch*NC + c)*NS;
#pragma unroll
    for (int n = 0; n < NS; n++) { Hp[n] = h[n]; Pp[n] = ex2f(an[n]*S); }
}

__global__ void k3_comb() {
    int t = blockIdx.x * blockDim.x + threadIdx.x;
    int n = t & 15;
    size_t ch = (size_t)(t >> 4);
    const float* __restrict__ Hp = g_H   + ch*NC*NS + n;
    const float* __restrict__ Pp = g_P   + ch*NC*NS + n;
    float*       __restrict__ Ip = g_Hin + ch*NC*NS + n;
    float h = 0.f;
#pragma unroll 4
    for (int c = 0; c < NC; c++) {
        Ip[c*NS] = h;
        h = fmaf(Pp[c*NS], h, Hp[c*NS]);
    }
}

// ---- pass2 (FAST): chain-free carry correction ------------------------------
__global__ __launch_bounds__(192) void k3f_pass2() {
    if (!g_fast) return;
    __shared__ __align__(16) float sC[CT*NS];
    int c = blockIdx.x, k = blockIdx.y, b = blockIdx.z;
    int d = threadIdx.x;
    size_t bk = (size_t)(b*KK + k);
    int l0 = c * CT;
    {
        const float4* Cg = (const float4*)(g_Cs + (bk*LL + (size_t)l0)*NS);
        float4* sC4 = (float4*)sC;
        for (int i = d; i < CT*NS/4; i += 192) sC4[i] = Cg[i];
    }
    __syncthreads();

    const float* sp = g_delta + (bk*LL + (size_t)l0)*DI + d;  // Scum
    float*       yp = g_sy    + (bk*LL + (size_t)l0)*DI + d;
    float an0 = g_anl2[((size_t)k*DI + d)*NS];
    size_t ch = bk*DI + d;
    const u64* Ip = (const u64*)(g_Hin + (ch*NC + c)*NS);
    u64 hin[8];
#pragma unroll
    for (int i = 0; i < 8; i++) hin[i] = Ip[i];

#pragma unroll 4
    for (int t = 0; t < CT; t++) {
        float S = sp[(size_t)t*DI];
        u64 P[8]; pows16p(ex2f(an0 * S), P);
        const u64* Cw = (const u64*)&sC[t*NS];
        u64 Y = 0ull;
#pragma unroll
        for (int i = 0; i < 8; i++)
            Y = fma2(mul2(P[i], hin[i]), Cw[i], Y);
        float ylo, yhi; upk(Y, ylo, yhi);
        yp[(size_t)t*DI] += ylo + yhi;
    }
}

__global__ __launch_bounds__(192) void k3s_pass3() {
    if (g_fast) return;
    int c = blockIdx.x, k = blockIdx.y, b = blockIdx.z;
    int d = threadIdx.x;
    size_t bk = (size_t)(b*KK + k);
    int l0 = c * CT;
    const float* dp = g_delta + (bk*LL + (size_t)l0)*DI + d;
    const float* Bp = g_Bs + (bk*LL + (size_t)l0)*NS;
    const float* Cp = g_Cs + (bk*LL + (size_t)l0)*NS;
    float* op = g_sy + (bk*LL + (size_t)l0)*DI + d;
    int pst = dir_step(k);
    const float* up = g_yin + ((size_t)b*LL + perm_pixel(k, l0))*DI + d;
    int ustep = pst * DI;
    float an[NS];
    const float* ap = g_anl2 + ((size_t)k*DI + d)*NS;
#pragma unroll
    for (int n = 0; n < NS; n++) an[n] = ap[n];
    size_t ch = bk*DI + d;
    const float* Ip = g_Hin + (ch*NC + c)*NS;
    float h[NS];
#pragma unroll
    for (int n = 0; n < NS; n++) h[n] = Ip[n];
    for (int t = 0; t < CT; t++) {
        float dlt = *dp, uv = *up;
        float du = dlt * uv;
        float y = 0.f;
#pragma unroll
        for (int n = 0; n < NS; n++) {
            h[n] = fmaf(ex2f(dlt*an[n]), h[n], du * Bp[n]);
            y = fmaf(h[n], Cp[n], y);
        }
        *op = y;
        dp += DI; up += ustep; Bp += NS; Cp += NS; op += DI;
    }
}

__global__ void k5_merge(const float* __restrict__ gamma, const float* __restrict__ beta,
                         const float* __restrict__ opw, float* __restrict__ out) {
    __shared__ __align__(16) float ym_s[32*DI];
    __shared__ __align__(16) float W_s[16*DI];
    __shared__ float mu_s[32], rs_s[32];
    int b = blockIdx.y;
    int p0 = blockIdx.x * 32;
    int t = threadIdx.x;
    size_t bb = (size_t)b * KK;

    for (int idx = t; idx < 32*DI; idx += 256) {
        int pl = idx / DI, d = idx % DI;
        int p  = p0 + pl;
        int l1 = (p & 63)*64 + (p >> 6);
        float v = g_sy[((bb + 0)*LL + p)*DI + d]
                + g_sy[((bb + 2)*LL + (LL-1-p))*DI + d]
                + g_sy[((bb + 1)*LL + l1)*DI + d]
                + g_sy[((bb + 3)*LL + (LL-1-l1))*DI + d]
                + g_dsum[d] * g_yin[((size_t)b*LL + p)*DI + d];
        ym_s[pl*DI + d] = v;
    }
    __syncthreads();

    {
        int warp = t >> 5, lane = t & 31;
        int pl  = warp*4 + (lane >> 3);
        int sub = lane & 7;
        float s = 0.f, s2 = 0.f;
        for (int j = sub; j < DI; j += 8) { float v = ym_s[pl*DI + j]; s += v; s2 += v*v; }
        s  += __shfl_xor_sync(0xffffffffu, s, 4);  s2 += __shfl_xor_sync(0xffffffffu, s2, 4);
        s  += __shfl_xor_sync(0xffffffffu, s, 2);  s2 += __shfl_xor_sync(0xffffffffu, s2, 2);
        s  += __shfl_xor_sync(0xffffffffu, s, 1);  s2 += __shfl_xor_sync(0xffffffffu, s2, 1);
        if (sub == 0) {
            float mu  = s * (1.f/DI);
            float var = s2 * (1.f/DI) - mu*mu;
            mu_s[pl] = mu;
            rs_s[pl] = rsqrtf(var + 1e-5f);
        }
    }
    __syncthreads();

    for (int idx = t; idx < 32*DI; idx += 256) {
        int pl = idx / DI, d = idx % DI;
        ym_s[idx] = (ym_s[idx] - mu_s[pl]) * rs_s[pl] * gamma[d] + beta[d];
    }

    int c0 = (t & 15) * 12;
    int px = (t >> 4) * 2;
    u64 acc2[2][6];
#pragma unroll
    for (int i = 0; i < 2; i++)
#pragma unroll
        for (int j = 0; j < 6; j++) acc2[i][j] = 0ull;

    for (int dc = 0; dc < DI; dc += 16) {
        __syncthreads();
        for (int idx = t; idx < 16*DI; idx += 256)
            W_s[idx] = opw[(dc + idx/DI)*DM + (idx % DI)];
        __syncthreads();
#pragma unroll
        for (int dd = 0; dd < 16; dd++) {
            float y0 = ym_s[(px + 0)*DI + dc + dd];
            float y1 = ym_s[(px + 1)*DI + dc + dd];
            u64 yp0 = pk(y0, y0), yp1 = pk(y1, y1);
            ulonglong2 wq0 = *(const ulonglong2*)&W_s[dd*DI + c0];
            ulonglong2 wq1 = *(const ulonglong2*)&W_s[dd*DI + c0 + 4];
            ulonglong2 wq2 = *(const ulonglong2*)&W_s[dd*DI + c0 + 8];
            u64 wp[6] = {wq0.x, wq0.y, wq1.x, wq1.y, wq2.x, wq2.y};
#pragma unroll
            for (int j = 0; j < 6; j++) {
                acc2[0][j] = fma2(yp0, wp[j], acc2[0][j]);
                acc2[1][j] = fma2(yp1, wp[j], acc2[1][j]);
            }
        }
    }
#pragma unroll
    for (int i = 0; i < 2; i++) {
        int p = p0 + px + i;
        float o[12];
#pragma unroll
        for (int j = 0; j < 6; j++) upk(acc2[i][j], o[2*j], o[2*j+1]);
#pragma unroll
        for (int j = 0; j < 12; j++)
            out[((size_t)(b*DM + c0 + j))*LL + p] = o[j];
    }
}

extern "C" void kernel_launch(void* const* d_in, const int* in_sizes, int n_in,
                              void* d_out, int out_size) {
    const float* x    = (const float*)d_in[0];
    const float* y    = (const float*)d_in[1];
    const float* wx   = (const float*)d_in[2];
    const float* wy   = (const float*)d_in[3];
    const float* xpw  = (const float*)d_in[4];
    const float* dtw  = (const float*)d_in[5];
    const float* dtb  = (const float*)d_in[6];
    const float* Alog = (const float*)d_in[7];
    const float* Ds   = (const float*)d_in[8];
    const float* gam  = (const float*)d_in[9];
    const float* bet  = (const float*)d_in[10];
    const float* opw  = (const float*)d_in[11];
    float* out = (float*)d_out;

    k0_init<<<1, 256>>>(Alog, Ds);
    k1_inproj<<<dim3(256, 2), 256>>>(x, y, wx, wy);
    k2_xproj<<<dim3(LL/32, KK, BATCH), 256>>>(xpw, dtw, dtb);
    k3f_pass1<<<dim3(NC, KK, BATCH), 192>>>();
    k3s_pass1<<<dim3(NC, KK, BATCH), 192>>>();
    k3_comb<<<192, 256>>>();
    k3f_pass2<<<dim3(NC, KK, BATCH), 192>>>();
    k3s_pass3<<<dim3(NC, KK, BATCH), 192>>>();
    k5_merge<<<dim3(LL/32, BATCH), 256>>>(gam, bet, opw, out);
}

// round 6
// speedup vs baseline: 4.6683x; 1.0039x over previous
#include <cuda_runtime.h>

#define BATCH 4
#define DM 192
#define DI 192
#define LL 4096
#define KK 4
#define NS 16
#define RR 12
#define CPROJ 44
#define CT 32
#define NC 128

typedef unsigned long long u64;

__device__ __align__(16) float g_xin[BATCH*LL*DI];
__device__ __align__(16) float g_yin[BATCH*LL*DI];
__device__ __align__(16) float g_yinT[BATCH*LL*DI];             // yinT[q] = yin[T(q)]
__device__ __align__(16) float g_delta[(size_t)BATCH*KK*LL*DI]; // pass1 overwrites with Scum
__device__ __align__(16) float g_Bs[BATCH*KK*LL*NS];
__device__ __align__(16) float g_Cs[BATCH*KK*LL*NS];
__device__ __align__(16) float g_sy[(size_t)BATCH*KK*LL*DI];
__device__ __align__(16) float g_anl2[KK*DI*NS];
__device__ __align__(16) float g_dsum[DI];
__device__ __align__(16) float g_H  [(size_t)BATCH*KK*DI*NC*NS];
__device__ __align__(16) float g_P  [(size_t)BATCH*KK*DI*NC*NS];
__device__ __align__(16) float g_Hin[(size_t)BATCH*KK*DI*NC*NS];
__device__ int g_fast;

__device__ __forceinline__ float ex2f(float x){
    float r; asm("ex2.approx.ftz.f32 %0, %1;" : "=f"(r) : "f"(x)); return r;
}
__device__ __forceinline__ float lg2f(float x){
    float r; asm("lg2.approx.f32 %0, %1;" : "=f"(r) : "f"(x)); return r;
}
__device__ __forceinline__ u64 pk(float lo, float hi){
    u64 r; asm("mov.b64 %0, {%1,%2};" : "=l"(r) : "f"(lo), "f"(hi)); return r;
}
__device__ __forceinline__ void upk(u64 v, float& lo, float& hi){
    asm("mov.b64 {%0,%1}, %2;" : "=f"(lo), "=f"(hi) : "l"(v));
}
__device__ __forceinline__ u64 mul2(u64 a, u64 b){
    u64 r; asm("mul.rn.f32x2 %0, %1, %2;" : "=l"(r) : "l"(a), "l"(b)); return r;
}
__device__ __forceinline__ u64 fma2(u64 a, u64 b, u64 c){
    u64 r; asm("fma.rn.f32x2 %0, %1, %2, %3;" : "=l"(r) : "l"(a), "l"(b), "l"(c)); return r;
}
__device__ __forceinline__ float softplusf(float x){
    float t = ex2f(-fabsf(x) * 1.4426950408889634f);
    return fmaxf(x, 0.f) + 0.6931471805599453f * lg2f(1.0f + t);
}
// inverse direction permutation: chain position l for pixel p (all involutive pieces)
__device__ __forceinline__ int inv_perm(int k, int p) {
    if (k == 0) return p;
    if (k == 1) return ((p & 63) << 6) | (p >> 6);
    if (k == 2) return LL - 1 - p;
    return LL - 1 - (((p & 63) << 6) | (p >> 6));
}
__device__ __forceinline__ void pows16p(float w, u64* P){
    float w2 = w*w, w4 = w2*w2;
    u64 W2 = pk(w2,w2), W4 = pk(w4,w4);
    P[0] = pk(w, w2);
    P[1] = mul2(P[0], W2);
    P[2] = mul2(P[0], W4);
    P[3] = mul2(P[1], W4);
    P[4] = mul2(P[2], W4);
    P[5] = mul2(P[3], W4);
    P[6] = mul2(P[4], W4);
    P[7] = mul2(P[5], W4);
}

__global__ void k0_init(const float* __restrict__ A_logs, const float* __restrict__ Ds) {
    int t = threadIdx.x;
    if (t == 0) g_fast = 1;
    for (int i = t; i < KK*DI*NS; i += blockDim.x)
        g_anl2[i] = -expf(A_logs[i]) * 1.4426950408889634f;
    if (t < DI) g_dsum[t] = Ds[t] + Ds[DI + t] + Ds[2*DI + t] + Ds[3*DI + t];
    __syncthreads();
    int ok = 1;
    for (int i = t; i < KK*DI*NS; i += blockDim.x) {
        int n = i % NS;
        float base = g_anl2[i - n];
        float want = (float)(n + 1) * base;
        if (fabsf(g_anl2[i] - want) > 1e-3f * fabsf(want) + 1e-12f) ok = 0;
    }
    if (!ok) atomicExch(&g_fast, 0);
}

// ---------------- kernel 1: in_proj (f32x2) + yinT scatter -------------------
__global__ void k1_inproj(const float* __restrict__ x, const float* __restrict__ y,
                          const float* __restrict__ wx, const float* __restrict__ wy) {
    __shared__ __align__(16) float xs_s[16][64];
    __shared__ __align__(16) float ws_s[16][192];
    const float* src = blockIdx.y ? y : x;
    const float* w   = blockIdx.y ? wy : wx;
    float* dst       = blockIdx.y ? g_yin : g_xin;
    int tile = blockIdx.x;
    int b  = tile >> 6;
    int p0 = (tile & 63) * 64;
    int t  = threadIdx.x;
    int dg = t & 15;
    int pg = t >> 4;
    int d0 = dg * 12;
    int px = pg * 4;
    u64 acc2[4][6];
#pragma unroll
    for (int i = 0; i < 4; i++)
#pragma unroll
        for (int j = 0; j < 6; j++) acc2[i][j] = 0ull;

    for (int c0 = 0; c0 < DM; c0 += 16) {
        __syncthreads();
        for (int idx = t; idx < 16*64; idx += 256) {
            int cc = idx >> 6, j = idx & 63;
            xs_s[cc][j] = src[((size_t)(b*DM + c0 + cc))*LL + p0 + j];
        }
        for (int idx = t; idx < 16*192; idx += 256) {
            int cc = idx / 192, d = idx % 192;
            ws_s[cc][d] = w[(c0 + cc)*DI + d];
        }
        __syncthreads();
#pragma unroll
        for (int cc = 0; cc < 16; cc++) {
            float4 xv = *(const float4*)&xs_s[cc][px];
            ulonglong2 wq0 = *(const ulonglong2*)&ws_s[cc][d0];
            ulonglong2 wq1 = *(const ulonglong2*)&ws_s[cc][d0+4];
            ulonglong2 wq2 = *(const ulonglong2*)&ws_s[cc][d0+8];
            u64 wp[6] = {wq0.x, wq0.y, wq1.x, wq1.y, wq2.x, wq2.y};
            u64 xp[4] = {pk(xv.x,xv.x), pk(xv.y,xv.y), pk(xv.z,xv.z), pk(xv.w,xv.w)};
#pragma unroll
            for (int i = 0; i < 4; i++)
#pragma unroll
                for (int j = 0; j < 6; j++)
                    acc2[i][j] = fma2(xp[i], wp[j], acc2[i][j]);
        }
    }
#pragma unroll
    for (int i = 0; i < 4; i++) {
        float o[12];
#pragma unroll
        for (int j = 0; j < 6; j++) upk(acc2[i][j], o[2*j], o[2*j+1]);
        int p = p0 + px + i;
        float* op = dst + ((size_t)b*LL + p)*DI + d0;
        float4 q0 = make_float4(o[0], o[1], o[2], o[3]);
        float4 q1 = make_float4(o[4], o[5], o[6], o[7]);
        float4 q2 = make_float4(o[8], o[9], o[10], o[11]);
        *(float4*)(op + 0) = q0;
        *(float4*)(op + 4) = q1;
        *(float4*)(op + 8) = q2;
        if (blockIdx.y) {   // also write transposed copy for the scan u-stream
            int tp = ((p & 63) << 6) | (p >> 6);
            float* ot = g_yinT + ((size_t)b*LL + tp)*DI + d0;
            *(float4*)(ot + 0) = q0;
            *(float4*)(ot + 4) = q1;
            *(float4*)(ot + 8) = q2;
        }
    }
}

// ---------------- kernel 2: one x_inner tile -> all 4 directions -------------
#define XSTR 36
#define PSTR 34
__global__ void k2_xproj(const float* __restrict__ xpw, const float* __restrict__ dtw,
                         const float* __restrict__ dtb) {
    __shared__ __align__(16) float xin_s[DI*XSTR];     // [d][l], l = pixel-local
    __shared__ __align__(16) float proj_s[CPROJ*PSTR];
    int p0 = blockIdx.x * 32;
    int b  = blockIdx.y;
    int t  = threadIdx.x;

    // contiguous stage of 32 pixels (no permutation!)
    for (int idx = t; idx < 32*DI; idx += 256) {
        int l = idx / DI, d = idx % DI;
        xin_s[d*XSTR + l] = g_xin[((size_t)b*LL + p0 + l)*DI + d];
    }
    __syncthreads();

    for (int k = 0; k < KK; k++) {
        // phase2: proj[c][l] = W_k[c,:] . xin[:,l]
        if (t < 176) {
            int c  = t >> 2;
            int lg = t & 3;
            const float* wrow = xpw + ((size_t)k*CPROJ + c)*DI;
            u64 a2[4] = {0ull, 0ull, 0ull, 0ull};
            for (int d0 = 0; d0 < DI; d0 += 4) {
                float4 wv = *(const float4*)(wrow + d0);
                float wvv[4] = {wv.x, wv.y, wv.z, wv.w};
#pragma unroll
                for (int dd = 0; dd < 4; dd++) {
                    u64 wp = pk(wvv[dd], wvv[dd]);
                    ulonglong2 xq0 = *(const ulonglong2*)&xin_s[(d0+dd)*XSTR + lg*8];
                    ulonglong2 xq1 = *(const ulonglong2*)&xin_s[(d0+dd)*XSTR + lg*8 + 4];
                    a2[0] = fma2(wp, xq0.x, a2[0]);
                    a2[1] = fma2(wp, xq0.y, a2[1]);
                    a2[2] = fma2(wp, xq1.x, a2[2]);
                    a2[3] = fma2(wp, xq1.y, a2[3]);
                }
            }
            float o[8];
#pragma unroll
            for (int j = 0; j < 4; j++) upk(a2[j], o[2*j], o[2*j+1]);
#pragma unroll
            for (int j = 0; j < 8; j++) proj_s[c*PSTR + lg*8 + j] = o[j];
        }
        __syncthreads();

        if (t < DI) {
            // dt-proj + softplus, scatter rows to inv_perm positions
            int d = t;
            const float4* dwr = (const float4*)(dtw + ((size_t)k*DI + d)*RR);
            float4 w0 = dwr[0], w1 = dwr[1], w2 = dwr[2];
            float wv[RR] = {w0.x,w0.y,w0.z,w0.w, w1.x,w1.y,w1.z,w1.w, w2.x,w2.y,w2.z,w2.w};
            u64 wp[RR];
#pragma unroll
            for (int r = 0; r < RR; r++) wp[r] = pk(wv[r], wv[r]);
            float bias = dtb[k*DI + d];
            u64 bp = pk(bias, bias);
            size_t rowbase = (size_t)(b*KK + k)*LL;
#pragma unroll 2
            for (int jp = 0; jp < 16; jp++) {
                u64 a2 = bp;
#pragma unroll
                for (int r = 0; r < RR; r++) {
                    u64 pq = *(const u64*)&proj_s[r*PSTR + 2*jp];
                    a2 = fma2(wp[r], pq, a2);
                }
                float v0, v1; upk(a2, v0, v1);
                int lA = inv_perm(k, p0 + 2*jp);
                int lB = inv_perm(k, p0 + 2*jp + 1);
                g_delta[(rowbase + lA)*DI + d] = softplusf(v0);
                g_delta[(rowbase + lB)*DI + d] = softplusf(v1);
            }
        } else {
            int tt = t - DI;
            size_t rowbase = (size_t)(b*KK + k)*LL;
            for (int idx = tt; idx < 32*NS*2; idx += 64) {
                int lp = idx >> 5, m = idx & 31;
                int l = inv_perm(k, p0 + lp);
                size_t base = (rowbase + l)*NS;
                if (m < NS) g_Bs[base + m]      = proj_s[(RR + m)*PSTR + lp];
                else        g_Cs[base + m - NS] = proj_s[(RR + m)*PSTR + lp];
            }
        }
        __syncthreads();
    }
}

// u-stream pointer: all 4 directions stream contiguously via yin / yinT
__device__ __forceinline__ const float* u_base(int k, int b, int l0, int d, int& ustep) {
    if (k == 0) { ustep =  DI; return g_yin  + ((size_t)b*LL + l0)*DI + d; }
    if (k == 1) { ustep =  DI; return g_yinT + ((size_t)b*LL + l0)*DI + d; }
    if (k == 2) { ustep = -DI; return g_yin  + ((size_t)b*LL + (LL-1-l0))*DI + d; }
    ustep = -DI; return g_yinT + ((size_t)b*LL + (LL-1-l0))*DI + d;
}

// ---- pass1 (FAST): full recursion + C-dot + y_local + Scum + summaries ------
__global__ __launch_bounds__(192, 6) void k3f_pass1() {
    if (!g_fast) return;
    __shared__ __align__(16) float sB[CT*NS];
    __shared__ __align__(16) float sC[CT*NS];
    int c = blockIdx.x, k = blockIdx.y, b = blockIdx.z;
    int d = threadIdx.x;
    size_t bk = (size_t)(b*KK + k);
    int l0 = c * CT;
    {
        const float4* Bg = (const float4*)(g_Bs + (bk*LL + (size_t)l0)*NS);
        const float4* Cg = (const float4*)(g_Cs + (bk*LL + (size_t)l0)*NS);
        float4* sB4 = (float4*)sB;
        float4* sC4 = (float4*)sC;
        for (int i = d; i < CT*NS/4; i += 192) { sB4[i] = Bg[i]; sC4[i] = Cg[i]; }
    }
    __syncthreads();

    float* dp = g_delta + (bk*LL + (size_t)l0)*DI + d;
    float* op = g_sy    + (bk*LL + (size_t)l0)*DI + d;
    int ustep;
    const float* up = u_base(k, b, l0, d, ustep);
    float an0 = g_anl2[((size_t)k*DI + d)*NS];

    u64 h2[8];
#pragma unroll
    for (int i = 0; i < 8; i++) h2[i] = 0ull;
    float S = 0.f;

#pragma unroll 4
    for (int t = 0; t < CT; t++) {
        float dlt = dp[(size_t)t*DI];
        float uv  = up[(size_t)t*ustep];
        const u64* Bw = (const u64*)&sB[t*NS];
        const u64* Cw = (const u64*)&sC[t*NS];
        u64 P[8]; pows16p(ex2f(dlt * an0), P);
        float du = dlt * uv;
        u64 DU = pk(du, du);
        u64 Y = 0ull;
#pragma unroll
        for (int i = 0; i < 8; i++) {
            h2[i] = fma2(P[i], h2[i], mul2(DU, Bw[i]));
            Y = fma2(h2[i], Cw[i], Y);
        }
        float ylo, yhi; upk(Y, ylo, yhi);
        op[(size_t)t*DI] = ylo + yhi;
        S += dlt;
        dp[(size_t)t*DI] = S;     // overwrite delta with inclusive prefix sum
    }
    size_t ch = bk*DI + d;
    u64* Hp = (u64*)(g_H + (ch*NC + c)*NS);
    u64* Pp = (u64*)(g_P + (ch*NC + c)*NS);
    u64 Q[8]; pows16p(ex2f(an0 * S), Q);
#pragma unroll
    for (int i = 0; i < 8; i++) { Hp[i] = h2[i]; Pp[i] = Q[i]; }
}

__global__ __launch_bounds__(192) void k3s_pass1() {
    if (g_fast) return;
    int c = blockIdx.x, k = blockIdx.y, b = blockIdx.z;
    int d = threadIdx.x;
    size_t bk = (size_t)(b*KK + k);
    int l0 = c * CT;
    const float* dp = g_delta + (bk*LL + (size_t)l0)*DI + d;
    const float* Bp = g_Bs + (bk*LL + (size_t)l0)*NS;
    int ustep;
    const float* up = u_base(k, b, l0, d, ustep);
    float an[NS];
    const float* ap = g_anl2 + ((size_t)k*DI + d)*NS;
#pragma unroll
    for (int n = 0; n < NS; n++) an[n] = ap[n];
    float h[NS];
#pragma unroll
    for (int n = 0; n < NS; n++) h[n] = 0.f;
    float S = 0.f;
    for (int t = 0; t < CT; t++) {
        float dlt = *dp, uv = *up;
        float du = dlt * uv;
#pragma unroll
        for (int n = 0; n < NS; n++)
            h[n] = fmaf(ex2f(dlt*an[n]), h[n], du * Bp[n]);
        S += dlt;
        dp += DI; up += ustep; Bp += NS;
    }
    size_t ch = bk*DI + d;
    float* Hp = g_H + (ch*NC + c)*NS;
    float* Pp = g_P + (ch*NC + c)*NS;
#pragma unroll
    for (int n = 0; n < NS; n++) { Hp[n] = h[n]; Pp[n] = ex2f(an[n]*S); }
}

__global__ void k3_comb() {
    int t = blockIdx.x * blockDim.x + threadIdx.x;
    int n = t & 15;
    size_t ch = (size_t)(t >> 4);
    const float* __restrict__ Hp = g_H   + ch*NC*NS + n;
    const float* __restrict__ Pp = g_P   + ch*NC*NS + n;
    float*       __restrict__ Ip = g_Hin + ch*NC*NS + n;
    float h = 0.f;
#pragma unroll 4
    for (int c = 0; c < NC; c++) {
        Ip[c*NS] = h;
        h = fmaf(Pp[c*NS], h, Hp[c*NS]);
    }
}

// ---- pass2 (FAST): chain-free carry correction ------------------------------
__global__ __launch_bounds__(192, 6) void k3f_pass2() {
    if (!g_fast) return;
    __shared__ __align__(16) float sC[CT*NS];
    int c = blockIdx.x, k = blockIdx.y, b = blockIdx.z;
    int d = threadIdx.x;
    size_t bk = (size_t)(b*KK + k);
    int l0 = c * CT;
    {
        const float4* Cg = (const float4*)(g_Cs + (bk*LL + (size_t)l0)*NS);
        float4* sC4 = (float4*)sC;
        for (int i = d; i < CT*NS/4; i += 192) sC4[i] = Cg[i];
    }
    __syncthreads();

    const float* sp = g_delta + (bk*LL + (size_t)l0)*DI + d;  // Scum
    float*       yp = g_sy    + (bk*LL + (size_t)l0)*DI + d;
    float an0 = g_anl2[((size_t)k*DI + d)*NS];
    size_t ch = bk*DI + d;
    const u64* Ip = (const u64*)(g_Hin + (ch*NC + c)*NS);
    u64 hin[8];
#pragma unroll
    for (int i = 0; i < 8; i++) hin[i] = Ip[i];

#pragma unroll 4
    for (int t = 0; t < CT; t++) {
        float S = sp[(size_t)t*DI];
        u64 P[8]; pows16p(ex2f(an0 * S), P);
        const u64* Cw = (const u64*)&sC[t*NS];
        u64 Y = 0ull;
#pragma unroll
        for (int i = 0; i < 8; i++)
            Y = fma2(mul2(P[i], hin[i]), Cw[i], Y);
        float ylo, yhi; upk(Y, ylo, yhi);
        yp[(size_t)t*DI] += ylo + yhi;
    }
}

__global__ __launch_bounds__(192) void k3s_pass3() {
    if (g_fast) return;
    int c = blockIdx.x, k = blockIdx.y, b = blockIdx.z;
    int d = threadIdx.x;
    size_t bk = (size_t)(b*KK + k);
    int l0 = c * CT;
    const float* dp = g_delta + (bk*LL + (size_t)l0)*DI + d;
    const float* Bp = g_Bs + (bk*LL + (size_t)l0)*NS;
    const float* Cp = g_Cs + (bk*LL + (size_t)l0)*NS;
    float* op = g_sy + (bk*LL + (size_t)l0)*DI + d;
    int ustep;
    const float* up = u_base(k, b, l0, d, ustep);
    float an[NS];
    const float* ap = g_anl2 + ((size_t)k*DI + d)*NS;
#pragma unroll
    for (int n = 0; n < NS; n++) an[n] = ap[n];
    size_t ch = bk*DI + d;
    const float* Ip = g_Hin + (ch*NC + c)*NS;
    float h[NS];
#pragma unroll
    for (int n = 0; n < NS; n++) h[n] = Ip[n];
    for (int t = 0; t < CT; t++) {
        float dlt = *dp, uv = *up;
        float du = dlt * uv;
        float y = 0.f;
#pragma unroll
        for (int n = 0; n < NS; n++) {
            h[n] = fmaf(ex2f(dlt*an[n]), h[n], du * Bp[n]);
            y = fmaf(h[n], Cp[n], y);
        }
        *op = y;
        dp += DI; up += ustep; Bp += NS; Cp += NS; op += DI;
    }
}

__global__ void k5_merge(const float* __restrict__ gamma, const float* __restrict__ beta,
                         const float* __restrict__ opw, float* __restrict__ out) {
    __shared__ __align__(16) float ym_s[32*DI];
    __shared__ __align__(16) float W_s[16*DI];
    __shared__ float mu_s[32], rs_s[32];
    int b = blockIdx.y;
    int p0 = blockIdx.x * 32;
    int t = threadIdx.x;
    size_t bb = (size_t)b * KK;

    for (int idx = t; idx < 32*DI; idx += 256) {
        int pl = idx / DI, d = idx % DI;
        int p  = p0 + pl;
        int l1 = (p & 63)*64 + (p >> 6);
        float v = g_sy[((bb + 0)*LL + p)*DI + d]
                + g_sy[((bb + 2)*LL + (LL-1-p))*DI + d]
                + g_sy[((bb + 1)*LL + l1)*DI + d]
                + g_sy[((bb + 3)*LL + (LL-1-l1))*DI + d]
                + g_dsum[d] * g_yin[((size_t)b*LL + p)*DI + d];
        ym_s[pl*DI + d] = v;
    }
    __syncthreads();

    {
        int warp = t >> 5, lane = t & 31;
        int pl  = warp*4 + (lane >> 3);
        int sub = lane & 7;
        float s = 0.f, s2 = 0.f;
        for (int j = sub; j < DI; j += 8) { float v = ym_s[pl*DI + j]; s += v; s2 += v*v; }
        s  += __shfl_xor_sync(0xffffffffu, s, 4);  s2 += __shfl_xor_sync(0xffffffffu, s2, 4);
        s  += __shfl_xor_sync(0xffffffffu, s, 2);  s2 += __shfl_xor_sync(0xffffffffu, s2, 2);
        s  += __shfl_xor_sync(0xffffffffu, s, 1);  s2 += __shfl_xor_sync(0xffffffffu, s2, 1);
        if (sub == 0) {
            float mu  = s * (1.f/DI);
            float var = s2 * (1.f/DI) - mu*mu;
            mu_s[pl] = mu;
            rs_s[pl] = rsqrtf(var + 1e-5f);
        }
    }
    __syncthreads();

    for (int idx = t; idx < 32*DI; idx += 256) {
        int pl = idx / DI, d = idx % DI;
        ym_s[idx] = (ym_s[idx] - mu_s[pl]) * rs_s[pl] * gamma[d] + beta[d];
    }

    int c0 = (t & 15) * 12;
    int px = (t >> 4) * 2;
    u64 acc2[2][6];
#pragma unroll
    for (int i = 0; i < 2; i++)
#pragma unroll
        for (int j = 0; j < 6; j++) acc2[i][j] = 0ull;

    for (int dc = 0; dc < DI; dc += 16) {
        __syncthreads();
        for (int idx = t; idx < 16*DI; idx += 256)
            W_s[idx] = opw[(dc + idx/DI)*DM + (idx % DI)];
        __syncthreads();
#pragma unroll
        for (int dd = 0; dd < 16; dd++) {
            float y0 = ym_s[(px + 0)*DI + dc + dd];
            float y1 = ym_s[(px + 1)*DI + dc + dd];
            u64 yp0 = pk(y0, y0), yp1 = pk(y1, y1);
            ulonglong2 wq0 = *(const ulonglong2*)&W_s[dd*DI + c0];
            ulonglong2 wq1 = *(const ulonglong2*)&W_s[dd*DI + c0 + 4];
            ulonglong2 wq2 = *(const ulonglong2*)&W_s[dd*DI + c0 + 8];
            u64 wp[6] = {wq0.x, wq0.y, wq1.x, wq1.y, wq2.x, wq2.y};
#pragma unroll
            for (int j = 0; j < 6; j++) {
                acc2[0][j] = fma2(yp0, wp[j], acc2[0][j]);
                acc2[1][j] = fma2(yp1, wp[j], acc2[1][j]);
            }
        }
    }
#pragma unroll
    for (int i = 0; i < 2; i++) {
        int p = p0 + px + i;
        float o[12];
#pragma unroll
        for (int j = 0; j < 6; j++) upk(acc2[i][j], o[2*j], o[2*j+1]);
#pragma unroll
        for (int j = 0; j < 12; j++)
            out[((size_t)(b*DM + c0 + j))*LL + p] = o[j];
    }
}

extern "C" void kernel_launch(void* const* d_in, const int* in_sizes, int n_in,
                              void* d_out, int out_size) {
    const float* x    = (const float*)d_in[0];
    const float* y    = (const float*)d_in[1];
    const float* wx   = (const float*)d_in[2];
    const float* wy   = (const float*)d_in[3];
    const float* xpw  = (const float*)d_in[4];
    const float* dtw  = (const float*)d_in[5];
    const float* dtb  = (const float*)d_in[6];
    const float* Alog = (const float*)d_in[7];
    const float* Ds   = (const float*)d_in[8];
    const float* gam  = (const float*)d_in[9];
    const float* bet  = (const float*)d_in[10];
    const float* opw  = (const float*)d_in[11];
    float* out = (float*)d_out;

    k0_init<<<1, 256>>>(Alog, Ds);
    k1_inproj<<<dim3(256, 2), 256>>>(x, y, wx, wy);
    k2_xproj<<<dim3(LL/32, BATCH), 256>>>(xpw, dtw, dtb);
    k3f_pass1<<<dim3(NC, KK, BATCH), 192>>>();
    k3s_pass1<<<dim3(NC, KK, BATCH), 192>>>();
    k3_comb<<<192, 256>>>();
    k3f_pass2<<<dim3(NC, KK, BATCH), 192>>>();
    k3s_pass3<<<dim3(NC, KK, BATCH), 192>>>();
    k5_merge<<<dim3(LL/32, BATCH), 256>>>(gam, bet, opw, out);
}

// round 7
// speedup vs baseline: 4.6886x; 1.0044x over previous
#include <cuda_runtime.h>

#define BATCH 4
#define DM 192
#define DI 192
#define LL 4096
#define KK 4
#define NS 16
#define RR 12
#define CPROJ 44
#define CT 32
#define NC 128

typedef unsigned long long u64;

__device__ __align__(16) float g_xin[BATCH*LL*DI];
__device__ __align__(16) float g_yin[BATCH*LL*DI];
__device__ __align__(16) float g_yinT[BATCH*LL*DI];
__device__ __align__(16) float g_delta[(size_t)BATCH*KK*LL*DI]; // pass1 overwrites with Scum
__device__ __align__(16) float g_Bs[BATCH*KK*LL*NS];
__device__ __align__(16) float g_Cs[BATCH*KK*LL*NS];
__device__ __align__(16) float g_sy[(size_t)BATCH*KK*LL*DI];
__device__ __align__(16) float g_anl2[KK*DI*NS];
__device__ __align__(16) float g_dsum[DI];
__device__ __align__(16) float g_H  [(size_t)BATCH*KK*DI*NC*NS];
__device__ __align__(16) float g_P  [(size_t)BATCH*KK*DI*NC*NS];
__device__ __align__(16) float g_Hin[(size_t)BATCH*KK*DI*NC*NS];
__device__ int g_fast;

__device__ __forceinline__ float ex2f(float x){
    float r; asm("ex2.approx.ftz.f32 %0, %1;" : "=f"(r) : "f"(x)); return r;
}
__device__ __forceinline__ float lg2f(float x){
    float r; asm("lg2.approx.f32 %0, %1;" : "=f"(r) : "f"(x)); return r;
}
__device__ __forceinline__ u64 pk(float lo, float hi){
    u64 r; asm("mov.b64 %0, {%1,%2};" : "=l"(r) : "f"(lo), "f"(hi)); return r;
}
__device__ __forceinline__ void upk(u64 v, float& lo, float& hi){
    asm("mov.b64 {%0,%1}, %2;" : "=f"(lo), "=f"(hi) : "l"(v));
}
__device__ __forceinline__ u64 mul2(u64 a, u64 b){
    u64 r; asm("mul.rn.f32x2 %0, %1, %2;" : "=l"(r) : "l"(a), "l"(b)); return r;
}
__device__ __forceinline__ u64 fma2(u64 a, u64 b, u64 c){
    u64 r; asm("fma.rn.f32x2 %0, %1, %2, %3;" : "=l"(r) : "l"(a), "l"(b), "l"(c)); return r;
}
__device__ __forceinline__ float softplusf(float x){
    float t = ex2f(-fabsf(x) * 1.4426950408889634f);
    return fmaxf(x, 0.f) + 0.6931471805599453f * lg2f(1.0f + t);
}
__device__ __forceinline__ int inv_perm(int k, int p) {
    if (k == 0) return p;
    if (k == 1) return ((p & 63) << 6) | (p >> 6);
    if (k == 2) return LL - 1 - p;
    return LL - 1 - (((p & 63) << 6) | (p >> 6));
}
__device__ __forceinline__ void pows16p(float w, u64* P){
    float w2 = w*w, w4 = w2*w2;
    u64 W2 = pk(w2,w2), W4 = pk(w4,w4);
    P[0] = pk(w, w2);
    P[1] = mul2(P[0], W2);
    P[2] = mul2(P[0], W4);
    P[3] = mul2(P[1], W4);
    P[4] = mul2(P[2], W4);
    P[5] = mul2(P[3], W4);
    P[6] = mul2(P[4], W4);
    P[7] = mul2(P[5], W4);
}

__global__ void k0_init(const float* __restrict__ A_logs, const float* __restrict__ Ds) {
    int t = threadIdx.x;
    if (t == 0) g_fast = 1;
    for (int i = t; i < KK*DI*NS; i += blockDim.x)
        g_anl2[i] = -expf(A_logs[i]) * 1.4426950408889634f;
    if (t < DI) g_dsum[t] = Ds[t] + Ds[DI + t] + Ds[2*DI + t] + Ds[3*DI + t];
    __syncthreads();
    int ok = 1;
    for (int i = t; i < KK*DI*NS; i += blockDim.x) {
        int n = i % NS;
        float base = g_anl2[i - n];
        float want = (float)(n + 1) * base;
        if (fabsf(g_anl2[i] - want) > 1e-3f * fabsf(want) + 1e-12f) ok = 0;
    }
    if (!ok) atomicExch(&g_fast, 0);
}

// ---------------- kernel 1: in_proj (f32x2) + yinT scatter -------------------
__global__ void k1_inproj(const float* __restrict__ x, const float* __restrict__ y,
                          const float* __restrict__ wx, const float* __restrict__ wy) {
    __shared__ __align__(16) float xs_s[16][64];
    __shared__ __align__(16) float ws_s[16][192];
    const float* src = blockIdx.y ? y : x;
    const float* w   = blockIdx.y ? wy : wx;
    float* dst       = blockIdx.y ? g_yin : g_xin;
    int tile = blockIdx.x;
    int b  = tile >> 6;
    int p0 = (tile & 63) * 64;
    int t  = threadIdx.x;
    int dg = t & 15;
    int pg = t >> 4;
    int d0 = dg * 12;
    int px = pg * 4;
    u64 acc2[4][6];
#pragma unroll
    for (int i = 0; i < 4; i++)
#pragma unroll
        for (int j = 0; j < 6; j++) acc2[i][j] = 0ull;

    for (int c0 = 0; c0 < DM; c0 += 16) {
        __syncthreads();
        for (int idx = t; idx < 16*64; idx += 256) {
            int cc = idx >> 6, j = idx & 63;
            xs_s[cc][j] = src[((size_t)(b*DM + c0 + cc))*LL + p0 + j];
        }
        for (int idx = t; idx < 16*192; idx += 256) {
            int cc = idx / 192, d = idx % 192;
            ws_s[cc][d] = w[(c0 + cc)*DI + d];
        }
        __syncthreads();
#pragma unroll
        for (int cc = 0; cc < 16; cc++) {
            float4 xv = *(const float4*)&xs_s[cc][px];
            ulonglong2 wq0 = *(const ulonglong2*)&ws_s[cc][d0];
            ulonglong2 wq1 = *(const ulonglong2*)&ws_s[cc][d0+4];
            ulonglong2 wq2 = *(const ulonglong2*)&ws_s[cc][d0+8];
            u64 wp[6] = {wq0.x, wq0.y, wq1.x, wq1.y, wq2.x, wq2.y};
            u64 xp[4] = {pk(xv.x,xv.x), pk(xv.y,xv.y), pk(xv.z,xv.z), pk(xv.w,xv.w)};
#pragma unroll
            for (int i = 0; i < 4; i++)
#pragma unroll
                for (int j = 0; j < 6; j++)
                    acc2[i][j] = fma2(xp[i], wp[j], acc2[i][j]);
        }
    }
#pragma unroll
    for (int i = 0; i < 4; i++) {
        float o[12];
#pragma unroll
        for (int j = 0; j < 6; j++) upk(acc2[i][j], o[2*j], o[2*j+1]);
        int p = p0 + px + i;
        float* op = dst + ((size_t)b*LL + p)*DI + d0;
        float4 q0 = make_float4(o[0], o[1], o[2], o[3]);
        float4 q1 = make_float4(o[4], o[5], o[6], o[7]);
        float4 q2 = make_float4(o[8], o[9], o[10], o[11]);
        *(float4*)(op + 0) = q0;
        *(float4*)(op + 4) = q1;
        *(float4*)(op + 8) = q2;
        if (blockIdx.y) {
            int tp = ((p & 63) << 6) | (p >> 6);
            float* ot = g_yinT + ((size_t)b*LL + tp)*DI + d0;
            *(float4*)(ot + 0) = q0;
            *(float4*)(ot + 4) = q1;
            *(float4*)(ot + 8) = q2;
        }
    }
}

// ---------------- kernel 2: all 4 directions, 2 syncs ------------------------
#define XSTR 36
#define PSTR 34
__global__ void k2_xproj(const float* __restrict__ xpw, const float* __restrict__ dtw,
                         const float* __restrict__ dtb) {
    __shared__ __align__(16) float xin_s[DI*XSTR];           // [d][l]
    __shared__ __align__(16) float proj_s[KK][CPROJ*PSTR];   // per-direction
    int p0 = blockIdx.x * 32;
    int b  = blockIdx.y;
    int t  = threadIdx.x;

    for (int idx = t; idx < 32*DI; idx += 256) {
        int l = idx / DI, d = idx % DI;
        xin_s[d*XSTR + l] = g_xin[((size_t)b*LL + p0 + l)*DI + d];
    }
    __syncthreads();

    // phase2 for all directions, no intermediate syncs
    if (t < 176) {
        int c  = t >> 2;
        int lg = t & 3;
#pragma unroll
        for (int k = 0; k < KK; k++) {
            const float* wrow = xpw + ((size_t)k*CPROJ + c)*DI;
            u64 a2[4] = {0ull, 0ull, 0ull, 0ull};
            for (int d0 = 0; d0 < DI; d0 += 4) {
                float4 wv = *(const float4*)(wrow + d0);
                float wvv[4] = {wv.x, wv.y, wv.z, wv.w};
#pragma unroll
                for (int dd = 0; dd < 4; dd++) {
                    u64 wp = pk(wvv[dd], wvv[dd]);
                    ulonglong2 xq0 = *(const ulonglong2*)&xin_s[(d0+dd)*XSTR + lg*8];
                    ulonglong2 xq1 = *(const ulonglong2*)&xin_s[(d0+dd)*XSTR + lg*8 + 4];
                    a2[0] = fma2(wp, xq0.x, a2[0]);
                    a2[1] = fma2(wp, xq0.y, a2[1]);
                    a2[2] = fma2(wp, xq1.x, a2[2]);
                    a2[3] = fma2(wp, xq1.y, a2[3]);
                }
            }
            float o[8];
#pragma unroll
            for (int j = 0; j < 4; j++) upk(a2[j], o[2*j], o[2*j+1]);
#pragma unroll
            for (int j = 0; j < 8; j++) proj_s[k][c*PSTR + lg*8 + j] = o[j];
        }
    }
    __syncthreads();

    if (t < DI) {
        int d = t;
#pragma unroll
        for (int k = 0; k < KK; k++) {
            const float4* dwr = (const float4*)(dtw + ((size_t)k*DI + d)*RR);
            float4 w0 = dwr[0], w1 = dwr[1], w2 = dwr[2];
            float wv[RR] = {w0.x,w0.y,w0.z,w0.w, w1.x,w1.y,w1.z,w1.w, w2.x,w2.y,w2.z,w2.w};
            u64 wp[RR];
#pragma unroll
            for (int r = 0; r < RR; r++) wp[r] = pk(wv[r], wv[r]);
            float bias = dtb[k*DI + d];
            u64 bp = pk(bias, bias);
            size_t rowbase = (size_t)(b*KK + k)*LL;
#pragma unroll 2
            for (int jp = 0; jp < 16; jp++) {
                u64 a2 = bp;
#pragma unroll
                for (int r = 0; r < RR; r++) {
                    u64 pq = *(const u64*)&proj_s[k][r*PSTR + 2*jp];
                    a2 = fma2(wp[r], pq, a2);
                }
                float v0, v1; upk(a2, v0, v1);
                int lA = inv_perm(k, p0 + 2*jp);
                int lB = inv_perm(k, p0 + 2*jp + 1);
                g_delta[(rowbase + lA)*DI + d] = softplusf(v0);
                g_delta[(rowbase + lB)*DI + d] = softplusf(v1);
            }
        }
    } else {
        int tt = t - DI;
#pragma unroll
        for (int k = 0; k < KK; k++) {
            size_t rowbase = (size_t)(b*KK + k)*LL;
            for (int idx = tt; idx < 32*NS*2; idx += 64) {
                int lp = idx >> 5, m = idx & 31;
                int l = inv_perm(k, p0 + lp);
                size_t base = (rowbase + l)*NS;
                if (m < NS) g_Bs[base + m]      = proj_s[k][(RR + m)*PSTR + lp];
                else        g_Cs[base + m - NS] = proj_s[k][(RR + m)*PSTR + lp];
            }
        }
    }
}

// u-stream: all 4 directions contiguous via yin / yinT
__device__ __forceinline__ const float* u_base(int k, int b, int l0, int d, int& ustep) {
    if (k == 0) { ustep =  DI; return g_yin  + ((size_t)b*LL + l0)*DI + d; }
    if (k == 1) { ustep =  DI; return g_yinT + ((size_t)b*LL + l0)*DI + d; }
    if (k == 2) { ustep = -DI; return g_yin  + ((size_t)b*LL + (LL-1-l0))*DI + d; }
    ustep = -DI; return g_yinT + ((size_t)b*LL + (LL-1-l0))*DI + d;
}

// ---- pass1: recursion + C-dot + y_local + Scum + chunk summaries ------------
__global__ __launch_bounds__(192, 6) void k3_pass1() {
    __shared__ __align__(16) float sB[CT*NS];
    __shared__ __align__(16) float sC[CT*NS];
    int c = blockIdx.x, k = blockIdx.y, b = blockIdx.z;
    int d = threadIdx.x;
    size_t bk = (size_t)(b*KK + k);
    int l0 = c * CT;
    {
        const float4* Bg = (const float4*)(g_Bs + (bk*LL + (size_t)l0)*NS);
        const float4* Cg = (const float4*)(g_Cs + (bk*LL + (size_t)l0)*NS);
        float4* sB4 = (float4*)sB;
        float4* sC4 = (float4*)sC;
        for (int i = d; i < CT*NS/4; i += 192) { sB4[i] = Bg[i]; sC4[i] = Cg[i]; }
    }
    __syncthreads();

    float* dp = g_delta + (bk*LL + (size_t)l0)*DI + d;
    float* op = g_sy    + (bk*LL + (size_t)l0)*DI + d;
    int ustep;
    const float* up = u_base(k, b, l0, d, ustep);
    size_t ch = bk*DI + d;

    if (g_fast) {
        float an0 = g_anl2[((size_t)k*DI + d)*NS];
        u64 h2[8];
#pragma unroll
        for (int i = 0; i < 8; i++) h2[i] = 0ull;
        float S = 0.f;
#pragma unroll 4
        for (int t = 0; t < CT; t++) {
            float dlt = dp[(size_t)t*DI];
            float uv  = up[(size_t)t*ustep];
            const u64* Bw = (const u64*)&sB[t*NS];
            const u64* Cw = (const u64*)&sC[t*NS];
            u64 P[8]; pows16p(ex2f(dlt * an0), P);
            float du = dlt * uv;
            u64 DU = pk(du, du);
            u64 Y = 0ull;
#pragma unroll
            for (int i = 0; i < 8; i++) {
                h2[i] = fma2(P[i], h2[i], mul2(DU, Bw[i]));
                Y = fma2(h2[i], Cw[i], Y);
            }
            float ylo, yhi; upk(Y, ylo, yhi);
            op[(size_t)t*DI] = ylo + yhi;
            S += dlt;
            dp[(size_t)t*DI] = S;
        }
        u64* Hp = (u64*)(g_H + (ch*NC + c)*NS);
        u64* Pp = (u64*)(g_P + (ch*NC + c)*NS);
        u64 Q[8]; pows16p(ex2f(an0 * S), Q);
#pragma unroll
        for (int i = 0; i < 8; i++) { Hp[i] = h2[i]; Pp[i] = Q[i]; }
    } else {
        // generic path (A structure not n+1-multiples): local recursion, no C-dot
        float an[NS];
        const float* ap = g_anl2 + ((size_t)k*DI + d)*NS;
#pragma unroll
        for (int n = 0; n < NS; n++) an[n] = ap[n];
        float h[NS];
#pragma unroll
        for (int n = 0; n < NS; n++) h[n] = 0.f;
        float S = 0.f;
        for (int t = 0; t < CT; t++) {
            float dlt = dp[(size_t)t*DI];
            float uv  = up[(size_t)t*ustep];
            float du = dlt * uv;
            const float* Bp = &sB[t*NS];
            const float* Cp = &sC[t*NS];
            float y = 0.f;
#pragma unroll
            for (int n = 0; n < NS; n++) {
                h[n] = fmaf(ex2f(dlt*an[n]), h[n], du * Bp[n]);
                y = fmaf(h[n], Cp[n], y);
            }
            op[(size_t)t*DI] = y;
            S += dlt;
            dp[(size_t)t*DI] = S;
        }
        float* Hp = g_H + (ch*NC + c)*NS;
        float* Pp = g_P + (ch*NC + c)*NS;
#pragma unroll
        for (int n = 0; n < NS; n++) { Hp[n] = h[n]; Pp[n] = ex2f(an[n]*S); }
    }
}

__global__ void k3_comb() {
    int t = blockIdx.x * blockDim.x + threadIdx.x;
    int n = t & 15;
    size_t ch = (size_t)(t >> 4);
    const float* __restrict__ Hp = g_H   + ch*NC*NS + n;
    const float* __restrict__ Pp = g_P   + ch*NC*NS + n;
    float*       __restrict__ Ip = g_Hin + ch*NC*NS + n;
    float h = 0.f;
#pragma unroll 4
    for (int c = 0; c < NC; c++) {
        Ip[c*NS] = h;
        h = fmaf(Pp[c*NS], h, Hp[c*NS]);
    }
}

// ---- pass2: chain-free carry correction -------------------------------------
__global__ __launch_bounds__(192, 6) void k3_pass2() {
    __shared__ __align__(16) float sC[CT*NS];
    int c = blockIdx.x, k = blockIdx.y, b = blockIdx.z;
    int d = threadIdx.x;
    size_t bk = (size_t)(b*KK + k);
    int l0 = c * CT;
    {
        const float4* Cg = (const float4*)(g_Cs + (bk*LL + (size_t)l0)*NS);
        float4* sC4 = (float4*)sC;
        for (int i = d; i < CT*NS/4; i += 192) sC4[i] = Cg[i];
    }
    __syncthreads();

    const float* sp = g_delta + (bk*LL + (size_t)l0)*DI + d;  // Scum
    float*       yp = g_sy    + (bk*LL + (size_t)l0)*DI + d;
    size_t ch = bk*DI + d;

    if (g_fast) {
        float an0 = g_anl2[((size_t)k*DI + d)*NS];
        const u64* Ip = (const u64*)(g_Hin + (ch*NC + c)*NS);
        u64 hin[8];
#pragma unroll
        for (int i = 0; i < 8; i++) hin[i] = Ip[i];
#pragma unroll 4
        for (int t = 0; t < CT; t++) {
            float S = sp[(size_t)t*DI];
            u64 P[8]; pows16p(ex2f(an0 * S), P);
            const u64* Cw = (const u64*)&sC[t*NS];
            u64 Y = 0ull;
#pragma unroll
            for (int i = 0; i < 8; i++)
                Y = fma2(mul2(P[i], hin[i]), Cw[i], Y);
            float ylo, yhi; upk(Y, ylo, yhi);
            yp[(size_t)t*DI] += ylo + yhi;
        }
    } else {
        float an[NS];
        const float* ap = g_anl2 + ((size_t)k*DI + d)*NS;
#pragma unroll
        for (int n = 0; n < NS; n++) an[n] = ap[n];
        const float* Ip = g_Hin + (ch*NC + c)*NS;
        float hin[NS];
#pragma unroll
        for (int n = 0; n < NS; n++) hin[n] = Ip[n];
        for (int t = 0; t < CT; t++) {
            float S = sp[(size_t)t*DI];
            const float* Cp = &sC[t*NS];
            float y = 0.f;
#pragma unroll
            for (int n = 0; n < NS; n++)
                y = fmaf(ex2f(an[n]*S) * hin[n], Cp[n], y);
            yp[(size_t)t*DI] += y;
        }
    }
}

// ---------------- kernel 5: merge + LN + out_proj (64-px tiles) --------------
__global__ __launch_bounds__(256) void k5_merge(
        const float* __restrict__ gamma, const float* __restrict__ beta,
        const float* __restrict__ opw, float* __restrict__ out) {
    __shared__ __align__(16) float ym_s[64*DI];
    __shared__ __align__(16) float W_s[16*DI];
    __shared__ float mu_s[64], rs_s[64];
    int b = blockIdx.y;
    int p0 = blockIdx.x * 64;
    int t = threadIdx.x;
    size_t bb = (size_t)b * KK;

    for (int idx = t; idx < 64*DI; idx += 256) {
        int pl = idx / DI, d = idx % DI;
        int p  = p0 + pl;
        int l1 = (p & 63)*64 + (p >> 6);
        float v = g_sy[((bb + 0)*LL + p)*DI + d]
                + g_sy[((bb + 2)*LL + (LL-1-p))*DI + d]
                + g_sy[((bb + 1)*LL + l1)*DI + d]
                + g_sy[((bb + 3)*LL + (LL-1-l1))*DI + d]
                + g_dsum[d] * g_yin[((size_t)b*LL + p)*DI + d];
        ym_s[pl*DI + d] = v;
    }
    __syncthreads();

    {   // LN stats: 8 warps x 8 px, 4 lanes per px
        int warp = t >> 5, lane = t & 31;
        int pl  = warp*8 + (lane >> 2);
        int sub = lane & 3;
        float s = 0.f, s2 = 0.f;
        for (int j = sub; j < DI; j += 4) { float v = ym_s[pl*DI + j]; s += v; s2 += v*v; }
        s  += __shfl_xor_sync(0xffffffffu, s, 2);  s2 += __shfl_xor_sync(0xffffffffu, s2, 2);
        s  += __shfl_xor_sync(0xffffffffu, s, 1);  s2 += __shfl_xor_sync(0xffffffffu, s2, 1);
        if (sub == 0) {
            float mu  = s * (1.f/DI);
            float var = s2 * (1.f/DI) - mu*mu;
            mu_s[pl] = mu;
            rs_s[pl] = rsqrtf(var + 1e-5f);
        }
    }
    __syncthreads();

    for (int idx = t; idx < 64*DI; idx += 256) {
        int pl = idx / DI, d = idx % DI;
        ym_s[idx] = (ym_s[idx] - mu_s[pl]) * rs_s[pl] * gamma[d] + beta[d];
    }

    int c0 = (t & 15) * 12;
    int px = (t >> 4) * 4;
    u64 acc2[4][6];
#pragma unroll
    for (int i = 0; i < 4; i++)
#pragma unroll
        for (int j = 0; j < 6; j++) acc2[i][j] = 0ull;

    for (int dc = 0; dc < DI; dc += 16) {
        __syncthreads();
        for (int idx = t; idx < 16*DI; idx += 256)
            W_s[idx] = opw[(dc + idx/DI)*DM + (idx % DI)];
        __syncthreads();
#pragma unroll
        for (int dd = 0; dd < 16; dd++) {
            ulonglong2 wq0 = *(const ulonglong2*)&W_s[dd*DI + c0];
            ulonglong2 wq1 = *(const ulonglong2*)&W_s[dd*DI + c0 + 4];
            ulonglong2 wq2 = *(const ulonglong2*)&W_s[dd*DI + c0 + 8];
            u64 wp[6] = {wq0.x, wq0.y, wq1.x, wq1.y, wq2.x, wq2.y};
#pragma unroll
            for (int i = 0; i < 4; i++) {
                float yv = ym_s[(px + i)*DI + dc + dd];
                u64 yp2 = pk(yv, yv);
#pragma unroll
                for (int j = 0; j < 6; j++)
                    acc2[i][j] = fma2(yp2, wp[j], acc2[i][j]);
            }
        }
    }
#pragma unroll
    for (int i = 0; i < 4; i++) {
        int p = p0 + px + i;
        float o[12];
#pragma unroll
        for (int j = 0; j < 6; j++) upk(acc2[i][j], o[2*j], o[2*j+1]);
#pragma unroll
        for (int j = 0; j < 12; j++)
            out[((size_t)(b*DM + c0 + j))*LL + p] = o[j];
    }
}

extern "C" void kernel_launch(void* const* d_in, const int* in_sizes, int n_in,
                              void* d_out, int out_size) {
    const float* x    = (const float*)d_in[0];
    const float* y    = (const float*)d_in[1];
    const float* wx   = (const float*)d_in[2];
    const float* wy   = (const float*)d_in[3];
    const float* xpw  = (const float*)d_in[4];
    const float* dtw  = (const float*)d_in[5];
    const float* dtb  = (const float*)d_in[6];
    const float* Alog = (const float*)d_in[7];
    const float* Ds   = (const float*)d_in[8];
    const float* gam  = (const float*)d_in[9];
    const float* bet  = (const float*)d_in[10];
    const float* opw  = (const float*)d_in[11];
    float* out = (float*)d_out;

    k0_init<<<1, 256>>>(Alog, Ds);
    k1_inproj<<<dim3(256, 2), 256>>>(x, y, wx, wy);
    k2_xproj<<<dim3(LL/32, BATCH), 256>>>(xpw, dtw, dtb);
    k3_pass1<<<dim3(NC, KK, BATCH), 192>>>();
    k3_comb<<<192, 256>>>();
    k3_pass2<<<dim3(NC, KK, BATCH), 192>>>();
    k5_merge<<<dim3(LL/64, BATCH), 256>>>(gam, bet, opw, out);
}

// round 8
// speedup vs baseline: 5.1483x; 1.0980x over previous
#include <cuda_runtime.h>

#define BATCH 4
#define DM 192
#define DI 192
#define LL 4096
#define KK 4
#define NS 16
#define RR 12
#define CPROJ 44
#define CT 32
#define NC 128

typedef unsigned long long u64;

__device__ __align__(16) float g_xin[BATCH*LL*DI];
__device__ __align__(16) float g_yin[BATCH*LL*DI];
__device__ __align__(16) float g_yinT[BATCH*LL*DI];
__device__ __align__(16) float g_pj[BATCH*KK*LL*RR];     // 3.1MB raw proj rows (chain order)
__device__ __align__(16) float g_Bs[BATCH*KK*LL*NS];
__device__ __align__(16) float g_Cs[BATCH*KK*LL*NS];
__device__ __align__(16) float g_sy[(size_t)BATCH*KK*LL*DI];  // PIXEL order [bk][p][d]
__device__ __align__(16) float g_anl2[KK*DI*NS];
__device__ __align__(16) float g_dsum[DI];
__device__ __align__(16) float g_H  [(size_t)BATCH*KK*DI*NC*NS];
__device__ __align__(16) float g_P  [(size_t)BATCH*KK*DI*NC*NS];
__device__ __align__(16) float g_Hin[(size_t)BATCH*KK*DI*NC*NS];
__device__ int g_fast;

__device__ __forceinline__ float ex2f(float x){
    float r; asm("ex2.approx.ftz.f32 %0, %1;" : "=f"(r) : "f"(x)); return r;
}
__device__ __forceinline__ float lg2f(float x){
    float r; asm("lg2.approx.f32 %0, %1;" : "=f"(r) : "f"(x)); return r;
}
__device__ __forceinline__ u64 pk(float lo, float hi){
    u64 r; asm("mov.b64 %0, {%1,%2};" : "=l"(r) : "f"(lo), "f"(hi)); return r;
}
__device__ __forceinline__ void upk(u64 v, float& lo, float& hi){
    asm("mov.b64 {%0,%1}, %2;" : "=f"(lo), "=f"(hi) : "l"(v));
}
__device__ __forceinline__ u64 mul2(u64 a, u64 b){
    u64 r; asm("mul.rn.f32x2 %0, %1, %2;" : "=l"(r) : "l"(a), "l"(b)); return r;
}
__device__ __forceinline__ u64 fma2(u64 a, u64 b, u64 c){
    u64 r; asm("fma.rn.f32x2 %0, %1, %2, %3;" : "=l"(r) : "l"(a), "l"(b), "l"(c)); return r;
}
__device__ __forceinline__ float softplusf(float x){
    float t = ex2f(-fabsf(x) * 1.4426950408889634f);
    return fmaxf(x, 0.f) + 0.6931471805599453f * lg2f(1.0f + t);
}
__device__ __forceinline__ int inv_perm(int k, int p) {
    if (k == 0) return p;
    if (k == 1) return ((p & 63) << 6) | (p >> 6);
    if (k == 2) return LL - 1 - p;
    return LL - 1 - (((p & 63) << 6) | (p >> 6));
}
__device__ __forceinline__ void pows16p(float w, u64* P){
    float w2 = w*w, w4 = w2*w2;
    u64 W2 = pk(w2,w2), W4 = pk(w4,w4);
    P[0] = pk(w, w2);
    P[1] = mul2(P[0], W2);
    P[2] = mul2(P[0], W4);
    P[3] = mul2(P[1], W4);
    P[4] = mul2(P[2], W4);
    P[5] = mul2(P[3], W4);
    P[6] = mul2(P[4], W4);
    P[7] = mul2(P[5], W4);
}

__global__ void k0_init(const float* __restrict__ A_logs, const float* __restrict__ Ds) {
    int t = threadIdx.x;
    if (t == 0) g_fast = 1;
    for (int i = t; i < KK*DI*NS; i += blockDim.x)
        g_anl2[i] = -expf(A_logs[i]) * 1.4426950408889634f;
    if (t < DI) g_dsum[t] = Ds[t] + Ds[DI + t] + Ds[2*DI + t] + Ds[3*DI + t];
    __syncthreads();
    int ok = 1;
    for (int i = t; i < KK*DI*NS; i += blockDim.x) {
        int n = i % NS;
        float base = g_anl2[i - n];
        float want = (float)(n + 1) * base;
        if (fabsf(g_anl2[i] - want) > 1e-3f * fabsf(want) + 1e-12f) ok = 0;
    }
    if (!ok) atomicExch(&g_fast, 0);
}

// ---------------- kernel 1: in_proj (f32x2) + yinT scatter -------------------
__global__ void k1_inproj(const float* __restrict__ x, const float* __restrict__ y,
                          const float* __restrict__ wx, const float* __restrict__ wy) {
    __shared__ __align__(16) float xs_s[16][64];
    __shared__ __align__(16) float ws_s[16][192];
    const float* src = blockIdx.y ? y : x;
    const float* w   = blockIdx.y ? wy : wx;
    float* dst       = blockIdx.y ? g_yin : g_xin;
    int tile = blockIdx.x;
    int b  = tile >> 6;
    int p0 = (tile & 63) * 64;
    int t  = threadIdx.x;
    int dg = t & 15;
    int pg = t >> 4;
    int d0 = dg * 12;
    int px = pg * 4;
    u64 acc2[4][6];
#pragma unroll
    for (int i = 0; i < 4; i++)
#pragma unroll
        for (int j = 0; j < 6; j++) acc2[i][j] = 0ull;

    for (int c0 = 0; c0 < DM; c0 += 16) {
        __syncthreads();
        for (int idx = t; idx < 16*64; idx += 256) {
            int cc = idx >> 6, j = idx & 63;
            xs_s[cc][j] = src[((size_t)(b*DM + c0 + cc))*LL + p0 + j];
        }
        for (int idx = t; idx < 16*192; idx += 256) {
            int cc = idx / 192, d = idx % 192;
            ws_s[cc][d] = w[(c0 + cc)*DI + d];
        }
        __syncthreads();
#pragma unroll
        for (int cc = 0; cc < 16; cc++) {
            float4 xv = *(const float4*)&xs_s[cc][px];
            ulonglong2 wq0 = *(const ulonglong2*)&ws_s[cc][d0];
            ulonglong2 wq1 = *(const ulonglong2*)&ws_s[cc][d0+4];
            ulonglong2 wq2 = *(const ulonglong2*)&ws_s[cc][d0+8];
            u64 wp[6] = {wq0.x, wq0.y, wq1.x, wq1.y, wq2.x, wq2.y};
            u64 xp[4] = {pk(xv.x,xv.x), pk(xv.y,xv.y), pk(xv.z,xv.z), pk(xv.w,xv.w)};
#pragma unroll
            for (int i = 0; i < 4; i++)
#pragma unroll
                for (int j = 0; j < 6; j++)
                    acc2[i][j] = fma2(xp[i], wp[j], acc2[i][j]);
        }
    }
#pragma unroll
    for (int i = 0; i < 4; i++) {
        float o[12];
#pragma unroll
        for (int j = 0; j < 6; j++) upk(acc2[i][j], o[2*j], o[2*j+1]);
        int p = p0 + px + i;
        float* op = dst + ((size_t)b*LL + p)*DI + d0;
        float4 q0 = make_float4(o[0], o[1], o[2], o[3]);
        float4 q1 = make_float4(o[4], o[5], o[6], o[7]);
        float4 q2 = make_float4(o[8], o[9], o[10], o[11]);
        *(float4*)(op + 0) = q0;
        *(float4*)(op + 4) = q1;
        *(float4*)(op + 8) = q2;
        if (blockIdx.y) {
            int tp = ((p & 63) << 6) | (p >> 6);
            float* ot = g_yinT + ((size_t)b*LL + tp)*DI + d0;
            *(float4*)(ot + 0) = q0;
            *(float4*)(ot + 4) = q1;
            *(float4*)(ot + 8) = q2;
        }
    }
}

// ---------------- kernel 2: x_proj GEMM only, scatter proj/B/C ---------------
#define XSTR 36
#define PSTR 34
__global__ void k2_xproj(const float* __restrict__ xpw) {
    __shared__ __align__(16) float xin_s[DI*XSTR];           // [d][l]
    __shared__ __align__(16) float proj_s[KK][CPROJ*PSTR];   // per-direction
    int p0 = blockIdx.x * 32;
    int b  = blockIdx.y;
    int t  = threadIdx.x;

    for (int idx = t; idx < 32*DI; idx += 256) {
        int l = idx / DI, d = idx % DI;
        xin_s[d*XSTR + l] = g_xin[((size_t)b*LL + p0 + l)*DI + d];
    }
    __syncthreads();

    if (t < 176) {
        int c  = t >> 2;
        int lg = t & 3;
#pragma unroll
        for (int k = 0; k < KK; k++) {
            const float* wrow = xpw + ((size_t)k*CPROJ + c)*DI;
            u64 a2[4] = {0ull, 0ull, 0ull, 0ull};
            for (int d0 = 0; d0 < DI; d0 += 4) {
                float4 wv = *(const float4*)(wrow + d0);
                float wvv[4] = {wv.x, wv.y, wv.z, wv.w};
#pragma unroll
                for (int dd = 0; dd < 4; dd++) {
                    u64 wp = pk(wvv[dd], wvv[dd]);
                    ulonglong2 xq0 = *(const ulonglong2*)&xin_s[(d0+dd)*XSTR + lg*8];
                    ulonglong2 xq1 = *(const ulonglong2*)&xin_s[(d0+dd)*XSTR + lg*8 + 4];
                    a2[0] = fma2(wp, xq0.x, a2[0]);
                    a2[1] = fma2(wp, xq0.y, a2[1]);
                    a2[2] = fma2(wp, xq1.x, a2[2]);
                    a2[3] = fma2(wp, xq1.y, a2[3]);
                }
            }
            float o[8];
#pragma unroll
            for (int j = 0; j < 4; j++) upk(a2[j], o[2*j], o[2*j+1]);
#pragma unroll
            for (int j = 0; j < 8; j++) proj_s[k][c*PSTR + lg*8 + j] = o[j];
        }
    }
    __syncthreads();

    // scatter: proj rows (12), B (16), C (16) per (k, lp) at chain positions
#pragma unroll
    for (int k = 0; k < KK; k++) {
        size_t rowbase = (size_t)(b*KK + k)*LL;
        for (int idx = t; idx < 32*CPROJ; idx += 256) {
            int lp = idx / CPROJ, c = idx % CPROJ;
            int l = inv_perm(k, p0 + lp);
            float v = proj_s[k][c*PSTR + lp];
            if (c < RR)           g_pj[(rowbase + l)*RR + c]           = v;
            else if (c < RR + NS) g_Bs[(rowbase + l)*NS + (c - RR)]    = v;
            else                  g_Cs[(rowbase + l)*NS + (c - RR - NS)] = v;
        }
    }
}

// u-stream: all 4 directions contiguous via yin / yinT
__device__ __forceinline__ const float* u_base(int k, int b, int l0, int d, int& ustep) {
    if (k == 0) { ustep =  DI; return g_yin  + ((size_t)b*LL + l0)*DI + d; }
    if (k == 1) { ustep =  DI; return g_yinT + ((size_t)b*LL + l0)*DI + d; }
    if (k == 2) { ustep = -DI; return g_yin  + ((size_t)b*LL + (LL-1-l0))*DI + d; }
    ustep = -DI; return g_yinT + ((size_t)b*LL + (LL-1-l0))*DI + d;
}

// y-output in PIXEL order: start pixel + uniform stride per direction
__device__ __forceinline__ float* y_base(int k, size_t bk, int l0, int d, int& ostep) {
    int pstart;
    if (k == 0)      { pstart = l0;                                  ostep =  DI;    }
    else if (k == 1) { pstart = ((l0 & 63) << 6) | (l0 >> 6);        ostep =  64*DI; }
    else if (k == 2) { pstart = LL - 1 - l0;                          ostep = -DI;    }
    else { int q = LL - 1 - l0; pstart = ((q & 63) << 6) | (q >> 6);  ostep = -64*DI; }
    return g_sy + (bk*LL + (size_t)pstart)*DI + d;
}

// delta recompute: 6 r-pair fma2 against smem proj row + softplus
__device__ __forceinline__ float delta_step(const u64* wp2, float bias, const float* pjrow){
    const u64* pj = (const u64*)pjrow;
    u64 a2 = fma2(wp2[0], pj[0], 0ull);
    a2 = fma2(wp2[1], pj[1], a2);
    a2 = fma2(wp2[2], pj[2], a2);
    a2 = fma2(wp2[3], pj[3], a2);
    a2 = fma2(wp2[4], pj[4], a2);
    a2 = fma2(wp2[5], pj[5], a2);
    float alo, ahi; upk(a2, alo, ahi);
    return softplusf(bias + alo + ahi);
}

// ---- pass1: recursion + C-dot + y_local (pixel order) + chunk summaries -----
__global__ __launch_bounds__(192, 5) void k3_pass1() {
    __shared__ __align__(16) float sB[CT*NS];
    __shared__ __align__(16) float sC[CT*NS];
    __shared__ __align__(16) float sPJ[CT*RR];
    int c = blockIdx.x, k = blockIdx.y, b = blockIdx.z;
    int d = threadIdx.x;
    size_t bk = (size_t)(b*KK + k);
    int l0 = c * CT;
    {
        const float4* Bg = (const float4*)(g_Bs + (bk*LL + (size_t)l0)*NS);
        const float4* Cg = (const float4*)(g_Cs + (bk*LL + (size_t)l0)*NS);
        const float4* Pg = (const float4*)(g_pj + (bk*LL + (size_t)l0)*RR);
        float4* sB4 = (float4*)sB;
        float4* sC4 = (float4*)sC;
        float4* sP4 = (float4*)sPJ;
        for (int i = d; i < CT*NS/4; i += 192) { sB4[i] = Bg[i]; sC4[i] = Cg[i]; }
        for (int i = d; i < CT*RR/4; i += 192) sP4[i] = Pg[i];
    }
    __syncthreads();

    // dt weights for this d
    const float4* dwr = (const float4*)( (const float*)0 );  // placeholder; set below
    float* op; int ostep;
    op = y_base(k, bk, l0, d, ostep);
    int ustep;
    const float* up = u_base(k, b, l0, d, ustep);
    size_t ch = bk*DI + d;

    // load dtw row + bias from global (cached; passed via g_dtw copy below)
    extern __device__ float g_dtw[KK*DI*RR];
    extern __device__ float g_dtb[KK*DI];
    const float4* wr4 = (const float4*)(g_dtw + ((size_t)k*DI + d)*RR);
    float4 w0 = wr4[0], w1 = wr4[1], w2 = wr4[2];
    u64 wp2[6] = { pk(w0.x,w0.y), pk(w0.z,w0.w), pk(w1.x,w1.y),
                   pk(w1.z,w1.w), pk(w2.x,w2.y), pk(w2.z,w2.w) };
    float bias = g_dtb[k*DI + d];

    if (g_fast) {
        float an0 = g_anl2[((size_t)k*DI + d)*NS];
        u64 h2[8];
#pragma unroll
        for (int i = 0; i < 8; i++) h2[i] = 0ull;
        float S = 0.f;
#pragma unroll 4
        for (int t = 0; t < CT; t++) {
            float dlt = delta_step(wp2, bias, &sPJ[t*RR]);
            float uv  = up[(size_t)t*ustep];
            const u64* Bw = (const u64*)&sB[t*NS];
            const u64* Cw = (const u64*)&sC[t*NS];
            u64 P[8]; pows16p(ex2f(dlt * an0), P);
            float du = dlt * uv;
            u64 DU = pk(du, du);
            u64 Y = 0ull;
#pragma unroll
            for (int i = 0; i < 8; i++) {
                h2[i] = fma2(P[i], h2[i], mul2(DU, Bw[i]));
                Y = fma2(h2[i], Cw[i], Y);
            }
            float ylo, yhi; upk(Y, ylo, yhi);
            op[(size_t)t*ostep] = ylo + yhi;
            S += dlt;
        }
        u64* Hp = (u64*)(g_H + (ch*NC + c)*NS);
        u64* Pp = (u64*)(g_P + (ch*NC + c)*NS);
        u64 Q[8]; pows16p(ex2f(an0 * S), Q);
#pragma unroll
        for (int i = 0; i < 8; i++) { Hp[i] = h2[i]; Pp[i] = Q[i]; }
    } else {
        float an[NS];
        const float* ap = g_anl2 + ((size_t)k*DI + d)*NS;
#pragma unroll
        for (int n = 0; n < NS; n++) an[n] = ap[n];
        float h[NS];
#pragma unroll
        for (int n = 0; n < NS; n++) h[n] = 0.f;
        float S = 0.f;
        for (int t = 0; t < CT; t++) {
            float dlt = delta_step(wp2, bias, &sPJ[t*RR]);
            float uv  = up[(size_t)t*ustep];
            float du = dlt * uv;
            const float* Bp = &sB[t*NS];
            const float* Cp = &sC[t*NS];
            float y = 0.f;
#pragma unroll
            for (int n = 0; n < NS; n++) {
                h[n] = fmaf(ex2f(dlt*an[n]), h[n], du * Bp[n]);
                y = fmaf(h[n], Cp[n], y);
            }
            op[(size_t)t*ostep] = y;
            S += dlt;
        }
        float* Hp = g_H + (ch*NC + c)*NS;
        float* Pp = g_P + (ch*NC + c)*NS;
#pragma unroll
        for (int n = 0; n < NS; n++) { Hp[n] = h[n]; Pp[n] = ex2f(an[n]*S); }
    }
}

__global__ void k3_comb() {
    int t = blockIdx.x * blockDim.x + threadIdx.x;
    int n = t & 15;
    size_t ch = (size_t)(t >> 4);
    const float* __restrict__ Hp = g_H   + ch*NC*NS + n;
    const float* __restrict__ Pp = g_P   + ch*NC*NS + n;
    float*       __restrict__ Ip = g_Hin + ch*NC*NS + n;
    float h = 0.f;
#pragma unroll 4
    for (int c = 0; c < NC; c++) {
        Ip[c*NS] = h;
        h = fmaf(Pp[c*NS], h, Hp[c*NS]);
    }
}

// ---- pass2: chain-free carry correction (recomputes delta prefix) -----------
__global__ __launch_bounds__(192, 5) void k3_pass2() {
    __shared__ __align__(16) float sC[CT*NS];
    __shared__ __align__(16) float sPJ[CT*RR];
    int c = blockIdx.x, k = blockIdx.y, b = blockIdx.z;
    int d = threadIdx.x;
    size_t bk = (size_t)(b*KK + k);
    int l0 = c * CT;
    {
        const float4* Cg = (const float4*)(g_Cs + (bk*LL + (size_t)l0)*NS);
        const float4* Pg = (const float4*)(g_pj + (bk*LL + (size_t)l0)*RR);
        float4* sC4 = (float4*)sC;
        float4* sP4 = (float4*)sPJ;
        for (int i = d; i < CT*NS/4; i += 192) sC4[i] = Cg[i];
        for (int i = d; i < CT*RR/4; i += 192) sP4[i] = Pg[i];
    }
    __syncthreads();

    extern __device__ float g_dtw[KK*DI*RR];
    extern __device__ float g_dtb[KK*DI];
    const float4* wr4 = (const float4*)(g_dtw + ((size_t)k*DI + d)*RR);
    float4 w0 = wr4[0], w1 = wr4[1], w2 = wr4[2];
    u64 wp2[6] = { pk(w0.x,w0.y), pk(w0.z,w0.w), pk(w1.x,w1.y),
                   pk(w1.z,w1.w), pk(w2.x,w2.y), pk(w2.z,w2.w) };
    float bias = g_dtb[k*DI + d];

    float* yp; int ostep;
    yp = y_base(k, bk, l0, d, ostep);
    size_t ch = bk*DI + d;

    if (g_fast) {
        float an0 = g_anl2[((size_t)k*DI + d)*NS];
        const u64* Ip = (const u64*)(g_Hin + (ch*NC + c)*NS);
        u64 hin[8];
#pragma unroll
        for (int i = 0; i < 8; i++) hin[i] = Ip[i];
        float S = 0.f;
#pragma unroll 4
        for (int t = 0; t < CT; t++) {
            S += delta_step(wp2, bias, &sPJ[t*RR]);
            u64 P[8]; pows16p(ex2f(an0 * S), P);
            const u64* Cw = (const u64*)&sC[t*NS];
            u64 Y = 0ull;
#pragma unroll
            for (int i = 0; i < 8; i++)
                Y = fma2(mul2(P[i], hin[i]), Cw[i], Y);
            float ylo, yhi; upk(Y, ylo, yhi);
            yp[(size_t)t*ostep] += ylo + yhi;
        }
    } else {
        float an[NS];
        const float* ap = g_anl2 + ((size_t)k*DI + d)*NS;
#pragma unroll
        for (int n = 0; n < NS; n++) an[n] = ap[n];
        const float* Ip = g_Hin + (ch*NC + c)*NS;
        float hin[NS];
#pragma unroll
        for (int n = 0; n < NS; n++) hin[n] = Ip[n];
        float S = 0.f;
        for (int t = 0; t < CT; t++) {
            S += delta_step(wp2, bias, &sPJ[t*RR]);
            const float* Cp = &sC[t*NS];
            float y = 0.f;
#pragma unroll
            for (int n = 0; n < NS; n++)
                y = fmaf(ex2f(an[n]*S) * hin[n], Cp[n], y);
            yp[(size_t)t*ostep] += y;
        }
    }
}

// actual definitions for the dt weights (copied once in k0b)
__device__ __align__(16) float g_dtw[KK*DI*RR];
__device__ __align__(16) float g_dtb[KK*DI];

__global__ void k0b_copy(const float* __restrict__ dtw, const float* __restrict__ dtb) {
    int t = blockIdx.x * blockDim.x + threadIdx.x;
    if (t < KK*DI*RR) g_dtw[t] = dtw[t];
    if (t < KK*DI)    g_dtb[t] = dtb[t];
}

// ---------------- kernel 5: merge + LN + out_proj (64-px tiles) --------------
__global__ __launch_bounds__(256) void k5_merge(
        const float* __restrict__ gamma, const float* __restrict__ beta,
        const float* __restrict__ opw, float* __restrict__ out) {
    __shared__ __align__(16) float ym_s[64*DI];
    __shared__ __align__(16) float W_s[16*DI];
    __shared__ float mu_s[64], rs_s[64];
    int b = blockIdx.y;
    int p0 = blockIdx.x * 64;
    int t = threadIdx.x;
    size_t bb = (size_t)b * KK;

    // merge: 4 contiguous direction streams (pixel order) + Ds*u term
    for (int idx = t; idx < 64*DI/4; idx += 256) {
        size_t off = (size_t)p0*DI + idx*4;
        float4 v0 = *(const float4*)&g_sy[((bb + 0)*LL)*DI + off];
        float4 v1 = *(const float4*)&g_sy[((bb + 1)*LL)*DI + off];
        float4 v2 = *(const float4*)&g_sy[((bb + 2)*LL)*DI + off];
        float4 v3 = *(const float4*)&g_sy[((bb + 3)*LL)*DI + off];
        float4 u  = *(const float4*)&g_yin[((size_t)b*LL)*DI + off];
        int dd = (idx*4) % DI;
        float4 ds = *(const float4*)&g_dsum[dd];
        float4 r;
        r.x = v0.x + v1.x + v2.x + v3.x + ds.x * u.x;
        r.y = v0.y + v1.y + v2.y + v3.y + ds.y * u.y;
        r.z = v0.z + v1.z + v2.z + v3.z + ds.z * u.z;
        r.w = v0.w + v1.w + v2.w + v3.w + ds.w * u.w;
        *(float4*)&ym_s[idx*4] = r;
    }
    __syncthreads();

    {   // LN stats: 8 warps x 8 px, 4 lanes per px
        int warp = t >> 5, lane = t & 31;
        int pl  = warp*8 + (lane >> 2);
        int sub = lane & 3;
        float s = 0.f, s2 = 0.f;
        for (int j = sub; j < DI; j += 4) { float v = ym_s[pl*DI + j]; s += v; s2 += v*v; }
        s  += __shfl_xor_sync(0xffffffffu, s, 2);  s2 += __shfl_xor_sync(0xffffffffu, s2, 2);
        s  += __shfl_xor_sync(0xffffffffu, s, 1);  s2 += __shfl_xor_sync(0xffffffffu, s2, 1);
        if (sub == 0) {
            float mu  = s * (1.f/DI);
            float var = s2 * (1.f/DI) - mu*mu;
            mu_s[pl] = mu;
            rs_s[pl] = rsqrtf(var + 1e-5f);
        }
    }
    __syncthreads();

    for (int idx = t; idx < 64*DI; idx += 256) {
        int pl = idx / DI, d = idx % DI;
        ym_s[idx] = (ym_s[idx] - mu_s[pl]) * rs_s[pl] * gamma[d] + beta[d];
    }

    int c0 = (t & 15) * 12;
    int px = (t >> 4) * 4;
    u64 acc2[4][6];
#pragma unroll
    for (int i = 0; i < 4; i++)
#pragma unroll
        for (int j = 0; j < 6; j++) acc2[i][j] = 0ull;

    for (int dc = 0; dc < DI; dc += 16) {
        __syncthreads();
        for (int idx = t; idx < 16*DI; idx += 256)
            W_s[idx] = opw[(dc + idx/DI)*DM + (idx % DI)];
        __syncthreads();
#pragma unroll
        for (int dd = 0; dd < 16; dd++) {
            ulonglong2 wq0 = *(const ulonglong2*)&W_s[dd*DI + c0];
            ulonglong2 wq1 = *(const ulonglong2*)&W_s[dd*DI + c0 + 4];
            ulonglong2 wq2 = *(const ulonglong2*)&W_s[dd*DI + c0 + 8];
            u64 wp[6] = {wq0.x, wq0.y, wq1.x, wq1.y, wq2.x, wq2.y};
#pragma unroll
            for (int i = 0; i < 4; i++) {
                float yv = ym_s[(px + i)*DI + dc + dd];
                u64 yp2 = pk(yv, yv);
#pragma unroll
                for (int j = 0; j < 6; j++)
                    acc2[i][j] = fma2(yp2, wp[j], acc2[i][j]);
            }
        }
    }
#pragma unroll
    for (int i = 0; i < 4; i++) {
        int p = p0 + px + i;
        float o[12];
#pragma unroll
        for (int j = 0; j < 6; j++) upk(acc2[i][j], o[2*j], o[2*j+1]);
#pragma unroll
        for (int j = 0; j < 12; j++)
            out[((size_t)(b*DM + c0 + j))*LL + p] = o[j];
    }
}

extern "C" void kernel_launch(void* const* d_in, const int* in_sizes, int n_in,
                              void* d_out, int out_size) {
    const float* x    = (const float*)d_in[0];
    const float* y    = (const float*)d_in[1];
    const float* wx   = (const float*)d_in[2];
    const float* wy   = (const float*)d_in[3];
    const float* xpw  = (const float*)d_in[4];
    const float* dtw  = (const float*)d_in[5];
    const float* dtb  = (const float*)d_in[6];
    const float* Alog = (const float*)d_in[7];
    const float* Ds   = (const float*)d_in[8];
    const float* gam  = (const float*)d_in[9];
    const float* bet  = (const float*)d_in[10];
    const float* opw  = (const float*)d_in[11];
    float* out = (float*)d_out;

    k0_init<<<1, 256>>>(Alog, Ds);
    k0b_copy<<<(KK*DI*RR + 255)/256, 256>>>(dtw, dtb);
    k1_inproj<<<dim3(256, 2), 256>>>(x, y, wx, wy);
    k2_xproj<<<dim3(LL/32, BATCH), 256>>>(xpw);
    k3_pass1<<<dim3(NC, KK, BATCH), 192>>>();
    k3_comb<<<192, 256>>>();
    k3_pass2<<<dim3(NC, KK, BATCH), 192>>>();
    k5_merge<<<dim3(LL/64, BATCH), 256>>>(gam, bet, opw, out);
}

// round 10
// speedup vs baseline: 5.2708x; 1.0238x over previous
#include <cuda_runtime.h>

#define BATCH 4
#define DM 192
#define DI 192
#define LL 4096
#define KK 4
#define NS 16
#define RR 12
#define CPROJ 44
#define CT 32
#define NC 128

typedef unsigned long long u64;

__device__ __align__(16) float g_xin[BATCH*LL*DI];
__device__ __align__(16) float g_yin[BATCH*LL*DI];
__device__ __align__(16) float g_yinT[BATCH*LL*DI];
__device__ __align__(16) float g_pj[BATCH*KK*LL*RR];     // 3.1MB raw proj rows (chain order)
__device__ __align__(16) float g_Bs[BATCH*KK*LL*NS];
__device__ __align__(16) float g_Cs[BATCH*KK*LL*NS];
__device__ __align__(16) float g_sy[(size_t)BATCH*KK*LL*DI];  // PIXEL order [bk][p][d]
__device__ __align__(16) float g_anl2[KK*DI*NS];
__device__ __align__(16) float g_dsum[DI];
__device__ __align__(16) float g_H  [(size_t)BATCH*KK*DI*NC*NS];
__device__ __align__(16) float g_P  [(size_t)BATCH*KK*DI*NC*NS];
__device__ __align__(16) float g_Hin[(size_t)BATCH*KK*DI*NC*NS];
__device__ __align__(16) float g_dtw[KK*DI*RR];
__device__ __align__(16) float g_dtb[KK*DI];
__device__ int g_fast;

__device__ __forceinline__ float ex2f(float x){
    float r; asm("ex2.approx.ftz.f32 %0, %1;" : "=f"(r) : "f"(x)); return r;
}
__device__ __forceinline__ float lg2f(float x){
    float r; asm("lg2.approx.f32 %0, %1;" : "=f"(r) : "f"(x)); return r;
}
__device__ __forceinline__ u64 pk(float lo, float hi){
    u64 r; asm("mov.b64 %0, {%1,%2};" : "=l"(r) : "f"(lo), "f"(hi)); return r;
}
__device__ __forceinline__ void upk(u64 v, float& lo, float& hi){
    asm("mov.b64 {%0,%1}, %2;" : "=f"(lo), "=f"(hi) : "l"(v));
}
__device__ __forceinline__ u64 mul2(u64 a, u64 b){
    u64 r; asm("mul.rn.f32x2 %0, %1, %2;" : "=l"(r) : "l"(a), "l"(b)); return r;
}
__device__ __forceinline__ u64 fma2(u64 a, u64 b, u64 c){
    u64 r; asm("fma.rn.f32x2 %0, %1, %2, %3;" : "=l"(r) : "l"(a), "l"(b), "l"(c)); return r;
}
__device__ __forceinline__ float softplusf(float x){
    float t = ex2f(-fabsf(x) * 1.4426950408889634f);
    return fmaxf(x, 0.f) + 0.6931471805599453f * lg2f(1.0f + t);
}
__device__ __forceinline__ int inv_perm(int k, int p) {
    if (k == 0) return p;
    if (k == 1) return ((p & 63) << 6) | (p >> 6);
    if (k == 2) return LL - 1 - p;
    return LL - 1 - (((p & 63) << 6) | (p >> 6));
}
__device__ __forceinline__ void pows16p(float w, u64* P){
    float w2 = w*w, w4 = w2*w2;
    u64 W2 = pk(w2,w2), W4 = pk(w4,w4);
    P[0] = pk(w, w2);
    P[1] = mul2(P[0], W2);
    P[2] = mul2(P[0], W4);
    P[3] = mul2(P[1], W4);
    P[4] = mul2(P[2], W4);
    P[5] = mul2(P[3], W4);
    P[6] = mul2(P[4], W4);
    P[7] = mul2(P[5], W4);
}

__global__ void k0_init(const float* __restrict__ A_logs, const float* __restrict__ Ds) {
    int t = threadIdx.x;
    if (t == 0) g_fast = 1;
    for (int i = t; i < KK*DI*NS; i += blockDim.x)
        g_anl2[i] = -expf(A_logs[i]) * 1.4426950408889634f;
    if (t < DI) g_dsum[t] = Ds[t] + Ds[DI + t] + Ds[2*DI + t] + Ds[3*DI + t];
    __syncthreads();
    int ok = 1;
    for (int i = t; i < KK*DI*NS; i += blockDim.x) {
        int n = i % NS;
        float base = g_anl2[i - n];
        float want = (float)(n + 1) * base;
        if (fabsf(g_anl2[i] - want) > 1e-3f * fabsf(want) + 1e-12f) ok = 0;
    }
    if (!ok) atomicExch(&g_fast, 0);
}

__global__ void k0b_copy(const float* __restrict__ dtw, const float* __restrict__ dtb) {
    int t = blockIdx.x * blockDim.x + threadIdx.x;
    if (t < KK*DI*RR) g_dtw[t] = dtw[t];
    if (t < KK*DI)    g_dtb[t] = dtb[t];
}

// ---------------- kernel 1: in_proj (f32x2) + yinT scatter -------------------
__global__ void k1_inproj(const float* __restrict__ x, const float* __restrict__ y,
                          const float* __restrict__ wx, const float* __restrict__ wy) {
    __shared__ __align__(16) float xs_s[16][64];
    __shared__ __align__(16) float ws_s[16][192];
    const float* src = blockIdx.y ? y : x;
    const float* w   = blockIdx.y ? wy : wx;
    float* dst       = blockIdx.y ? g_yin : g_xin;
    int tile = blockIdx.x;
    int b  = tile >> 6;
    int p0 = (tile & 63) * 64;
    int t  = threadIdx.x;
    int dg = t & 15;
    int pg = t >> 4;
    int d0 = dg * 12;
    int px = pg * 4;
    u64 acc2[4][6];
#pragma unroll
    for (int i = 0; i < 4; i++)
#pragma unroll
        for (int j = 0; j < 6; j++) acc2[i][j] = 0ull;

    for (int c0 = 0; c0 < DM; c0 += 16) {
        __syncthreads();
        for (int idx = t; idx < 16*64; idx += 256) {
            int cc = idx >> 6, j = idx & 63;
            xs_s[cc][j] = src[((size_t)(b*DM + c0 + cc))*LL + p0 + j];
        }
        for (int idx = t; idx < 16*192; idx += 256) {
            int cc = idx / 192, d = idx % 192;
            ws_s[cc][d] = w[(c0 + cc)*DI + d];
        }
        __syncthreads();
#pragma unroll
        for (int cc = 0; cc < 16; cc++) {
            float4 xv = *(const float4*)&xs_s[cc][px];
            ulonglong2 wq0 = *(const ulonglong2*)&ws_s[cc][d0];
            ulonglong2 wq1 = *(const ulonglong2*)&ws_s[cc][d0+4];
            ulonglong2 wq2 = *(const ulonglong2*)&ws_s[cc][d0+8];
            u64 wp[6] = {wq0.x, wq0.y, wq1.x, wq1.y, wq2.x, wq2.y};
            u64 xp[4] = {pk(xv.x,xv.x), pk(xv.y,xv.y), pk(xv.z,xv.z), pk(xv.w,xv.w)};
#pragma unroll
            for (int i = 0; i < 4; i++)
#pragma unroll
                for (int j = 0; j < 6; j++)
                    acc2[i][j] = fma2(xp[i], wp[j], acc2[i][j]);
        }
    }
#pragma unroll
    for (int i = 0; i < 4; i++) {
        float o[12];
#pragma unroll
        for (int j = 0; j < 6; j++) upk(acc2[i][j], o[2*j], o[2*j+1]);
        int p = p0 + px + i;
        float* op = dst + ((size_t)b*LL + p)*DI + d0;
        float4 q0 = make_float4(o[0], o[1], o[2], o[3]);
        float4 q1 = make_float4(o[4], o[5], o[6], o[7]);
        float4 q2 = make_float4(o[8], o[9], o[10], o[11]);
        *(float4*)(op + 0) = q0;
        *(float4*)(op + 4) = q1;
        *(float4*)(op + 8) = q2;
        if (blockIdx.y) {
            int tp = ((p & 63) << 6) | (p >> 6);
            float* ot = g_yinT + ((size_t)b*LL + tp)*DI + d0;
            *(float4*)(ot + 0) = q0;
            *(float4*)(ot + 4) = q1;
            *(float4*)(ot + 8) = q2;
        }
    }
}

// ---------------- kernel 2: x_proj GEMM, broadcast-LDS tiling ----------------
// thread = (k, c): accumulates proj[k][c][l] for ALL 32 l's. Every lane of a
// warp reads the same x-row per d -> LDS.128 broadcasts (one wavefront each).
#define XSTR 36
#define PSTR 34
__global__ __launch_bounds__(256) void k2_xproj(const float* __restrict__ xpw) {
    __shared__ __align__(16) float xin_s[DI*XSTR];           // [d][l]
    __shared__ __align__(16) float proj_s[KK][CPROJ*PSTR];   // per-direction
    int p0 = blockIdx.x * 32;
    int b  = blockIdx.y;
    int t  = threadIdx.x;

    for (int idx = t; idx < 32*DI; idx += 256) {
        int l = idx / DI, d = idx % DI;
        xin_s[d*XSTR + l] = g_xin[((size_t)b*LL + p0 + l)*DI + d];
    }
    __syncthreads();

    if (t < KK*CPROJ) {
        int k = t / CPROJ;
        int c = t % CPROJ;
        const float4* wrow = (const float4*)(xpw + ((size_t)k*CPROJ + c)*DI);
        u64 acc[16];
#pragma unroll
        for (int i = 0; i < 16; i++) acc[i] = 0ull;

        for (int d0 = 0; d0 < DI; d0 += 4) {
            float4 wv = __ldg(wrow + (d0 >> 2));
            float wa[4] = {wv.x, wv.y, wv.z, wv.w};
#pragma unroll
            for (int dd = 0; dd < 4; dd++) {
                u64 wp = pk(wa[dd], wa[dd]);
                const float* xr = &xin_s[(d0 + dd)*XSTR];
                ulonglong2 x0 = *(const ulonglong2*)(xr);
                ulonglong2 x1 = *(const ulonglong2*)(xr + 4);
                ulonglong2 x2 = *(const ulonglong2*)(xr + 8);
                ulonglong2 x3 = *(const ulonglong2*)(xr + 12);
                ulonglong2 x4 = *(const ulonglong2*)(xr + 16);
                ulonglong2 x5 = *(const ulonglong2*)(xr + 20);
                ulonglong2 x6 = *(const ulonglong2*)(xr + 24);
                ulonglong2 x7 = *(const ulonglong2*)(xr + 28);
                acc[0]  = fma2(wp, x0.x, acc[0]);
                acc[1]  = fma2(wp, x0.y, acc[1]);
                acc[2]  = fma2(wp, x1.x, acc[2]);
                acc[3]  = fma2(wp, x1.y, acc[3]);
                acc[4]  = fma2(wp, x2.x, acc[4]);
                acc[5]  = fma2(wp, x2.y, acc[5]);
                acc[6]  = fma2(wp, x3.x, acc[6]);
                acc[7]  = fma2(wp, x3.y, acc[7]);
                acc[8]  = fma2(wp, x4.x, acc[8]);
                acc[9]  = fma2(wp, x4.y, acc[9]);
                acc[10] = fma2(wp, x5.x, acc[10]);
                acc[11] = fma2(wp, x5.y, acc[11]);
                acc[12] = fma2(wp, x6.x, acc[12]);
                acc[13] = fma2(wp, x6.y, acc[13]);
                acc[14] = fma2(wp, x7.x, acc[14]);
                acc[15] = fma2(wp, x7.y, acc[15]);
            }
        }
        float* pr = &proj_s[k][c*PSTR];
#pragma unroll
        for (int i = 0; i < 16; i++) {
            float lo, hi; upk(acc[i], lo, hi);
            pr[2*i] = lo; pr[2*i + 1] = hi;
        }
    }
    __syncthreads();

    // scatter: proj rows (12), B (16), C (16) per (k, lp) at chain positions
#pragma unroll
    for (int k = 0; k < KK; k++) {
        size_t rowbase = (size_t)(b*KK + k)*LL;
        for (int idx = t; idx < 32*CPROJ; idx += 256) {
            int lp = idx / CPROJ, c = idx % CPROJ;
            int l = inv_perm(k, p0 + lp);
            float v = proj_s[k][c*PSTR + lp];
            if (c < RR)           g_pj[(rowbase + l)*RR + c]           = v;
            else if (c < RR + NS) g_Bs[(rowbase + l)*NS + (c - RR)]    = v;
            else                  g_Cs[(rowbase + l)*NS + (c - RR - NS)] = v;
        }
    }
}

// u-stream: all 4 directions contiguous via yin / yinT
__device__ __forceinline__ const float* u_base(int k, int b, int l0, int d, int& ustep) {
    if (k == 0) { ustep =  DI; return g_yin  + ((size_t)b*LL + l0)*DI + d; }
    if (k == 1) { ustep =  DI; return g_yinT + ((size_t)b*LL + l0)*DI + d; }
    if (k == 2) { ustep = -DI; return g_yin  + ((size_t)b*LL + (LL-1-l0))*DI + d; }
    ustep = -DI; return g_yinT + ((size_t)b*LL + (LL-1-l0))*DI + d;
}

// y-output in PIXEL order: start pixel + uniform stride per direction
__device__ __forceinline__ float* y_base(int k, size_t bk, int l0, int d, int& ostep) {
    int pstart;
    if (k == 0)      { pstart = l0;                                  ostep =  DI;    }
    else if (k == 1) { pstart = ((l0 & 63) << 6) | (l0 >> 6);        ostep =  64*DI; }
    else if (k == 2) { pstart = LL - 1 - l0;                          ostep = -DI;    }
    else { int q = LL - 1 - l0; pstart = ((q & 63) << 6) | (q >> 6);  ostep = -64*DI; }
    return g_sy + (bk*LL + (size_t)pstart)*DI + d;
}

// delta recompute: 6 r-pair fma2 against smem proj row + softplus
__device__ __forceinline__ float delta_step(const u64* wp2, float bias, const float* pjrow){
    const u64* pj = (const u64*)pjrow;
    u64 a2 = fma2(wp2[0], pj[0], 0ull);
    a2 = fma2(wp2[1], pj[1], a2);
    a2 = fma2(wp2[2], pj[2], a2);
    a2 = fma2(wp2[3], pj[3], a2);
    a2 = fma2(wp2[4], pj[4], a2);
    a2 = fma2(wp2[5], pj[5], a2);
    float alo, ahi; upk(a2, alo, ahi);
    return softplusf(bias + alo + ahi);
}

// ---- pass1: recursion + C-dot + y_local (pixel order) + chunk summaries -----
__global__ __launch_bounds__(192, 5) void k3_pass1() {
    __shared__ __align__(16) float sB[CT*NS];
    __shared__ __align__(16) float sC[CT*NS];
    __shared__ __align__(16) float sPJ[CT*RR];
    int c = blockIdx.x, k = blockIdx.y, b = blockIdx.z;
    int d = threadIdx.x;
    size_t bk = (size_t)(b*KK + k);
    int l0 = c * CT;
    {
        const float4* Bg = (const float4*)(g_Bs + (bk*LL + (size_t)l0)*NS);
        const float4* Cg = (const float4*)(g_Cs + (bk*LL + (size_t)l0)*NS);
        const float4* Pg = (const float4*)(g_pj + (bk*LL + (size_t)l0)*RR);
        float4* sB4 = (float4*)sB;
        float4* sC4 = (float4*)sC;
        float4* sP4 = (float4*)sPJ;
        for (int i = d; i < CT*NS/4; i += 192) { sB4[i] = Bg[i]; sC4[i] = Cg[i]; }
        for (int i = d; i < CT*RR/4; i += 192) sP4[i] = Pg[i];
    }
    __syncthreads();

    float* op; int ostep;
    op = y_base(k, bk, l0, d, ostep);
    int ustep;
    const float* up = u_base(k, b, l0, d, ustep);
    size_t ch = bk*DI + d;

    const float4* wr4 = (const float4*)(g_dtw + ((size_t)k*DI + d)*RR);
    float4 w0 = wr4[0], w1 = wr4[1], w2 = wr4[2];
    u64 wp2[6] = { pk(w0.x,w0.y), pk(w0.z,w0.w), pk(w1.x,w1.y),
                   pk(w1.z,w1.w), pk(w2.x,w2.y), pk(w2.z,w2.w) };
    float bias = g_dtb[k*DI + d];

    if (g_fast) {
        float an0 = g_anl2[((size_t)k*DI + d)*NS];
        u64 h2[8];
#pragma unroll
        for (int i = 0; i < 8; i++) h2[i] = 0ull;
        float S = 0.f;
#pragma unroll 4
        for (int t = 0; t < CT; t++) {
            float dlt = delta_step(wp2, bias, &sPJ[t*RR]);
            float uv  = up[(size_t)t*ustep];
            const u64* Bw = (const u64*)&sB[t*NS];
            const u64* Cw = (const u64*)&sC[t*NS];
            u64 P[8]; pows16p(ex2f(dlt * an0), P);
            float du = dlt * uv;
            u64 DU = pk(du, du);
            u64 Y = 0ull;
#pragma unroll
            for (int i = 0; i < 8; i++) {
                h2[i] = fma2(P[i], h2[i], mul2(DU, Bw[i]));
                Y = fma2(h2[i], Cw[i], Y);
            }
            float ylo, yhi; upk(Y, ylo, yhi);
            op[(size_t)t*ostep] = ylo + yhi;
            S += dlt;
        }
        u64* Hp = (u64*)(g_H + (ch*NC + c)*NS);
        u64* Pp = (u64*)(g_P + (ch*NC + c)*NS);
        u64 Q[8]; pows16p(ex2f(an0 * S), Q);
#pragma unroll
        for (int i = 0; i < 8; i++) { Hp[i] = h2[i]; Pp[i] = Q[i]; }
    } else {
        float an[NS];
        const float* ap = g_anl2 + ((size_t)k*DI + d)*NS;
#pragma unroll
        for (int n = 0; n < NS; n++) an[n] = ap[n];
        float h[NS];
#pragma unroll
        for (int n = 0; n < NS; n++) h[n] = 0.f;
        float S = 0.f;
        for (int t = 0; t < CT; t++) {
            float dlt = delta_step(wp2, bias, &sPJ[t*RR]);
            float uv  = up[(size_t)t*ustep];
            float du = dlt * uv;
            const float* Bp = &sB[t*NS];
            const float* Cp = &sC[t*NS];
            float y = 0.f;
#pragma unroll
            for (int n = 0; n < NS; n++) {
                h[n] = fmaf(ex2f(dlt*an[n]), h[n], du * Bp[n]);
                y = fmaf(h[n], Cp[n], y);
            }
            op[(size_t)t*ostep] = y;
            S += dlt;
        }
        float* Hp = g_H + (ch*NC + c)*NS;
        float* Pp = g_P + (ch*NC + c)*NS;
#pragma unroll
        for (int n = 0; n < NS; n++) { Hp[n] = h[n]; Pp[n] = ex2f(an[n]*S); }
    }
}

__global__ void k3_comb() {
    int t = blockIdx.x * blockDim.x + threadIdx.x;
    int n = t & 15;
    size_t ch = (size_t)(t >> 4);
    const float* __restrict__ Hp = g_H   + ch*NC*NS + n;
    const float* __restrict__ Pp = g_P   + ch*NC*NS + n;
    float*       __restrict__ Ip = g_Hin + ch*NC*NS + n;
    float h = 0.f;
#pragma unroll 4
    for (int c = 0; c < NC; c++) {
        Ip[c*NS] = h;
        h = fmaf(Pp[c*NS], h, Hp[c*NS]);
    }
}

// ---- pass2: chain-free carry correction (recomputes delta prefix) -----------
__global__ __launch_bounds__(192, 5) void k3_pass2() {
    __shared__ __align__(16) float sC[CT*NS];
    __shared__ __align__(16) float sPJ[CT*RR];
    int c = blockIdx.x, k = blockIdx.y, b = blockIdx.z;
    int d = threadIdx.x;
    size_t bk = (size_t)(b*KK + k);
    int l0 = c * CT;
    {
        const float4* Cg = (const float4*)(g_Cs + (bk*LL + (size_t)l0)*NS);
        const float4* Pg = (const float4*)(g_pj + (bk*LL + (size_t)l0)*RR);
        float4* sC4 = (float4*)sC;
        float4* sP4 = (float4*)sPJ;
        for (int i = d; i < CT*NS/4; i += 192) sC4[i] = Cg[i];
        for (int i = d; i < CT*RR/4; i += 192) sP4[i] = Pg[i];
    }
    __syncthreads();

    const float4* wr4 = (const float4*)(g_dtw + ((size_t)k*DI + d)*RR);
    float4 w0 = wr4[0], w1 = wr4[1], w2 = wr4[2];
    u64 wp2[6] = { pk(w0.x,w0.y), pk(w0.z,w0.w), pk(w1.x,w1.y),
                   pk(w1.z,w1.w), pk(w2.x,w2.y), pk(w2.z,w2.w) };
    float bias = g_dtb[k*DI + d];

    float* yp; int ostep;
    yp = y_base(k, bk, l0, d, ostep);
    size_t ch = bk*DI + d;

    if (g_fast) {
        float an0 = g_anl2[((size_t)k*DI + d)*NS];
        const u64* Ip = (const u64*)(g_Hin + (ch*NC + c)*NS);
        u64 hin[8];
#pragma unroll
        for (int i = 0; i < 8; i++) hin[i] = Ip[i];
        float S = 0.f;
#pragma unroll 4
        for (int t = 0; t < CT; t++) {
            S += delta_step(wp2, bias, &sPJ[t*RR]);
            u64 P[8]; pows16p(ex2f(an0 * S), P);
            const u64* Cw = (const u64*)&sC[t*NS];
            u64 Y = 0ull;
#pragma unroll
            for (int i = 0; i < 8; i++)
                Y = fma2(mul2(P[i], hin[i]), Cw[i], Y);
            float ylo, yhi; upk(Y, ylo, yhi);
            yp[(size_t)t*ostep] += ylo + yhi;
        }
    } else {
        float an[NS];
        const float* ap = g_anl2 + ((size_t)k*DI + d)*NS;
#pragma unroll
        for (int n = 0; n < NS; n++) an[n] = ap[n];
        const float* Ip = g_Hin + (ch*NC + c)*NS;
        float hin[NS];
#pragma unroll
        for (int n = 0; n < NS; n++) hin[n] = Ip[n];
        float S = 0.f;
        for (int t = 0; t < CT; t++) {
            S += delta_step(wp2, bias, &sPJ[t*RR]);
            const float* Cp = &sC[t*NS];
            float y = 0.f;
#pragma unroll
            for (int n = 0; n < NS; n++)
                y = fmaf(ex2f(an[n]*S) * hin[n], Cp[n], y);
            yp[(size_t)t*ostep] += y;
        }
    }
}

// ---------------- kernel 5: merge + LN + out_proj (64-px tiles) --------------
__global__ __launch_bounds__(256) void k5_merge(
        const float* __restrict__ gamma, const float* __restrict__ beta,
        const float* __restrict__ opw, float* __restrict__ out) {
    __shared__ __align__(16) float ym_s[64*DI];
    __shared__ __align__(16) float W_s[16*DI];
    __shared__ float mu_s[64], rs_s[64];
    int b = blockIdx.y;
    int p0 = blockIdx.x * 64;
    int t = threadIdx.x;
    size_t bb = (size_t)b * KK;

    for (int idx = t; idx < 64*DI/4; idx += 256) {
        size_t off = (size_t)p0*DI + idx*4;
        float4 v0 = *(const float4*)&g_sy[((bb + 0)*LL)*DI + off];
        float4 v1 = *(const float4*)&g_sy[((bb + 1)*LL)*DI + off];
        float4 v2 = *(const float4*)&g_sy[((bb + 2)*LL)*DI + off];
        float4 v3 = *(const float4*)&g_sy[((bb + 3)*LL)*DI + off];
        float4 u  = *(const float4*)&g_yin[((size_t)b*LL)*DI + off];
        int dd = (idx*4) % DI;
        float4 ds = *(const float4*)&g_dsum[dd];
        float4 r;
        r.x = v0.x + v1.x + v2.x + v3.x + ds.x * u.x;
        r.y = v0.y + v1.y + v2.y + v3.y + ds.y * u.y;
        r.z = v0.z + v1.z + v2.z + v3.z + ds.z * u.z;
        r.w = v0.w + v1.w + v2.w + v3.w + ds.w * u.w;
        *(float4*)&ym_s[idx*4] = r;
    }
    __syncthreads();

    {
        int warp = t >> 5, lane = t & 31;
        int pl  = warp*8 + (lane >> 2);
        int sub = lane & 3;
        float s = 0.f, s2 = 0.f;
        for (int j = sub; j < DI; j += 4) { float v = ym_s[pl*DI + j]; s += v; s2 += v*v; }
        s  += __shfl_xor_sync(0xffffffffu, s, 2);  s2 += __shfl_xor_sync(0xffffffffu, s2, 2);
        s  += __shfl_xor_sync(0xffffffffu, s, 1);  s2 += __shfl_xor_sync(0xffffffffu, s2, 1);
        if (sub == 0) {
            float mu  = s * (1.f/DI);
            float var = s2 * (1.f/DI) - mu*mu;
            mu_s[pl] = mu;
            rs_s[pl] = rsqrtf(var + 1e-5f);
        }
    }
    __syncthreads();

    for (int idx = t; idx < 64*DI; idx += 256) {
        int pl = idx / DI, d = idx % DI;
        ym_s[idx] = (ym_s[idx] - mu_s[pl]) * rs_s[pl] * gamma[d] + beta[d];
    }

    int c0 = (t & 15) * 12;
    int px = (t >> 4) * 4;
    u64 acc2[4][6];
#pragma unroll
    for (int i = 0; i < 4; i++)
#pragma unroll
        for (int j = 0; j < 6; j++) acc2[i][j] = 0ull;

    for (int dc = 0; dc < DI; dc += 16) {
        __syncthreads();
        for (int idx = t; idx < 16*DI; idx += 256)
            W_s[idx] = opw[(dc + idx/DI)*DM + (idx % DI)];
        __syncthreads();
#pragma unroll
        for (int dd = 0; dd < 16; dd++) {
            ulonglong2 wq0 = *(const ulonglong2*)&W_s[dd*DI + c0];
            ulonglong2 wq1 = *(const ulonglong2*)&W_s[dd*DI + c0 + 4];
            ulonglong2 wq2 = *(const ulonglong2*)&W_s[dd*DI + c0 + 8];
            u64 wp[6] = {wq0.x, wq0.y, wq1.x, wq1.y, wq2.x, wq2.y};
#pragma unroll
            for (int i = 0; i < 4; i++) {
                float yv = ym_s[(px + i)*DI + dc + dd];
                u64 yp2 = pk(yv, yv);
#pragma unroll
                for (int j = 0; j < 6; j++)
                    acc2[i][j] = fma2(yp2, wp[j], acc2[i][j]);
            }
        }
    }
#pragma unroll
    for (int i = 0; i < 4; i++) {
        int p = p0 + px + i;
        float o[12];
#pragma unroll
        for (int j = 0; j < 6; j++) upk(acc2[i][j], o[2*j], o[2*j+1]);
#pragma unroll
        for (int j = 0; j < 12; j++)
            out[((size_t)(b*DM + c0 + j))*LL + p] = o[j];
    }
}

extern "C" void kernel_launch(void* const* d_in, const int* in_sizes, int n_in,
                              void* d_out, int out_size) {
    const float* x    = (const float*)d_in[0];
    const float* y    = (const float*)d_in[1];
    const float* wx   = (const float*)d_in[2];
    const float* wy   = (const float*)d_in[3];
    const float* xpw  = (const float*)d_in[4];
    const float* dtw  = (const float*)d_in[5];
    const float* dtb  = (const float*)d_in[6];
    const float* Alog = (const float*)d_in[7];
    const float* Ds   = (const float*)d_in[8];
    const float* gam  = (const float*)d_in[9];
    const float* bet  = (const float*)d_in[10];
    const float* opw  = (const float*)d_in[11];
    float* out = (float*)d_out;

    k0_init<<<1, 256>>>(Alog, Ds);
    k0b_copy<<<(KK*DI*RR + 255)/256, 256>>>(dtw, dtb);
    k1_inproj<<<dim3(256, 2), 256>>>(x, y, wx, wy);
    k2_xproj<<<dim3(LL/32, BATCH), 256>>>(xpw);
    k3_pass1<<<dim3(NC, KK, BATCH), 192>>>();
    k3_comb<<<192, 256>>>();
    k3_pass2<<<dim3(NC, KK, BATCH), 192>>>();
    k5_merge<<<dim3(LL/64, BATCH), 256>>>(gam, bet, opw, out);
}

// round 11
// speedup vs baseline: 5.6231x; 1.0668x over previous
#include <cuda_runtime.h>

#define BATCH 4
#define DM 192
#define DI 192
#define LL 4096
#define KK 4
#define NS 16
#define RR 12
#define CPROJ 44
#define CT 32
#define NC 128

typedef unsigned long long u64;

__device__ __align__(16) float g_xin[BATCH*LL*DI];
__device__ __align__(16) float g_yin[BATCH*LL*DI];
__device__ __align__(16) float g_yinT[BATCH*LL*DI];
__device__ __align__(16) float g_pj[BATCH*KK*LL*RR];     // raw proj rows (chain order)
__device__ __align__(16) float g_Bs[BATCH*KK*LL*NS];
__device__ __align__(16) float g_Cs[BATCH*KK*LL*NS];
__device__ __align__(16) float g_sy[(size_t)BATCH*KK*LL*DI];  // PIXEL order [bk][p][d]
__device__ __align__(16) float g_anl2[KK*DI*NS];
__device__ __align__(16) float g_dsum[DI];
__device__ __align__(16) float g_H  [(size_t)BATCH*KK*DI*NC*NS];
__device__ __align__(16) float g_P  [(size_t)BATCH*KK*DI*NC*NS];
__device__ __align__(16) float g_Hin[(size_t)BATCH*KK*DI*NC*NS];
__device__ __align__(16) float g_dtw[KK*DI*RR];
__device__ __align__(16) float g_dtb[KK*DI];
__device__ int g_fast;

__device__ __forceinline__ float ex2f(float x){
    float r; asm("ex2.approx.ftz.f32 %0, %1;" : "=f"(r) : "f"(x)); return r;
}
__device__ __forceinline__ float lg2f(float x){
    float r; asm("lg2.approx.f32 %0, %1;" : "=f"(r) : "f"(x)); return r;
}
__device__ __forceinline__ u64 pk(float lo, float hi){
    u64 r; asm("mov.b64 %0, {%1,%2};" : "=l"(r) : "f"(lo), "f"(hi)); return r;
}
__device__ __forceinline__ void upk(u64 v, float& lo, float& hi){
    asm("mov.b64 {%0,%1}, %2;" : "=f"(lo), "=f"(hi) : "l"(v));
}
__device__ __forceinline__ u64 mul2(u64 a, u64 b){
    u64 r; asm("mul.rn.f32x2 %0, %1, %2;" : "=l"(r) : "l"(a), "l"(b)); return r;
}
__device__ __forceinline__ u64 fma2(u64 a, u64 b, u64 c){
    u64 r; asm("fma.rn.f32x2 %0, %1, %2, %3;" : "=l"(r) : "l"(a), "l"(b), "l"(c)); return r;
}
__device__ __forceinline__ float softplusf(float x){
    float t = ex2f(-fabsf(x) * 1.4426950408889634f);
    return fmaxf(x, 0.f) + 0.6931471805599453f * lg2f(1.0f + t);
}
__device__ __forceinline__ int inv_perm(int k, int p) {
    if (k == 0) return p;
    if (k == 1) return ((p & 63) << 6) | (p >> 6);
    if (k == 2) return LL - 1 - p;
    return LL - 1 - (((p & 63) << 6) | (p >> 6));
}
__device__ __forceinline__ void pows16p(float w, u64* P){
    float w2 = w*w, w4 = w2*w2;
    u64 W2 = pk(w2,w2), W4 = pk(w4,w4);
    P[0] = pk(w, w2);
    P[1] = mul2(P[0], W2);
    P[2] = mul2(P[0], W4);
    P[3] = mul2(P[1], W4);
    P[4] = mul2(P[2], W4);
    P[5] = mul2(P[3], W4);
    P[6] = mul2(P[4], W4);
    P[7] = mul2(P[5], W4);
}

__global__ void k0_init(const float* __restrict__ A_logs, const float* __restrict__ Ds) {
    int t = threadIdx.x;
    if (t == 0) g_fast = 1;
    for (int i = t; i < KK*DI*NS; i += blockDim.x)
        g_anl2[i] = -expf(A_logs[i]) * 1.4426950408889634f;
    if (t < DI) g_dsum[t] = Ds[t] + Ds[DI + t] + Ds[2*DI + t] + Ds[3*DI + t];
    __syncthreads();
    int ok = 1;
    for (int i = t; i < KK*DI*NS; i += blockDim.x) {
        int n = i % NS;
        float base = g_anl2[i - n];
        float want = (float)(n + 1) * base;
        if (fabsf(g_anl2[i] - want) > 1e-3f * fabsf(want) + 1e-12f) ok = 0;
    }
    if (!ok) atomicExch(&g_fast, 0);
}

__global__ void k0b_copy(const float* __restrict__ dtw, const float* __restrict__ dtb) {
    int t = blockIdx.x * blockDim.x + threadIdx.x;
    if (t < KK*DI*RR) g_dtw[t] = dtw[t];
    if (t < KK*DI)    g_dtb[t] = dtb[t];
}

// ---------------- kernel 1: in_proj (f32x2) + yinT scatter -------------------
__global__ void k1_inproj(const float* __restrict__ x, const float* __restrict__ y,
                          const float* __restrict__ wx, const float* __restrict__ wy) {
    __shared__ __align__(16) float xs_s[16][64];
    __shared__ __align__(16) float ws_s[16][192];
    const float* src = blockIdx.y ? y : x;
    const float* w   = blockIdx.y ? wy : wx;
    float* dst       = blockIdx.y ? g_yin : g_xin;
    int tile = blockIdx.x;
    int b  = tile >> 6;
    int p0 = (tile & 63) * 64;
    int t  = threadIdx.x;
    int dg = t & 15;
    int pg = t >> 4;
    int d0 = dg * 12;
    int px = pg * 4;
    u64 acc2[4][6];
#pragma unroll
    for (int i = 0; i < 4; i++)
#pragma unroll
        for (int j = 0; j < 6; j++) acc2[i][j] = 0ull;

    for (int c0 = 0; c0 < DM; c0 += 16) {
        __syncthreads();
        for (int idx = t; idx < 16*64; idx += 256) {
            int cc = idx >> 6, j = idx & 63;
            xs_s[cc][j] = src[((size_t)(b*DM + c0 + cc))*LL + p0 + j];
        }
        for (int idx = t; idx < 16*192; idx += 256) {
            int cc = idx / 192, d = idx % 192;
            ws_s[cc][d] = w[(c0 + cc)*DI + d];
        }
        __syncthreads();
#pragma unroll
        for (int cc = 0; cc < 16; cc++) {
            float4 xv = *(const float4*)&xs_s[cc][px];
            ulonglong2 wq0 = *(const ulonglong2*)&ws_s[cc][d0];
            ulonglong2 wq1 = *(const ulonglong2*)&ws_s[cc][d0+4];
            ulonglong2 wq2 = *(const ulonglong2*)&ws_s[cc][d0+8];
            u64 wp[6] = {wq0.x, wq0.y, wq1.x, wq1.y, wq2.x, wq2.y};
            u64 xp[4] = {pk(xv.x,xv.x), pk(xv.y,xv.y), pk(xv.z,xv.z), pk(xv.w,xv.w)};
#pragma unroll
            for (int i = 0; i < 4; i++)
#pragma unroll
                for (int j = 0; j < 6; j++)
                    acc2[i][j] = fma2(xp[i], wp[j], acc2[i][j]);
        }
    }
#pragma unroll
    for (int i = 0; i < 4; i++) {
        float o[12];
#pragma unroll
        for (int j = 0; j < 6; j++) upk(acc2[i][j], o[2*j], o[2*j+1]);
        int p = p0 + px + i;
        float* op = dst + ((size_t)b*LL + p)*DI + d0;
        float4 q0 = make_float4(o[0], o[1], o[2], o[3]);
        float4 q1 = make_float4(o[4], o[5], o[6], o[7]);
        float4 q2 = make_float4(o[8], o[9], o[10], o[11]);
        *(float4*)(op + 0) = q0;
        *(float4*)(op + 4) = q1;
        *(float4*)(op + 8) = q2;
        if (blockIdx.y) {
            int tp = ((p & 63) << 6) | (p >> 6);
            float* ot = g_yinT + ((size_t)b*LL + tp)*DI + d0;
            *(float4*)(ot + 0) = q0;
            *(float4*)(ot + 4) = q1;
            *(float4*)(ot + 8) = q2;
        }
    }
}

// ---------------- kernel 2: x_proj as k1-style output-tile GEMM --------------
// 64-px tile; thread = (c-group of 12 padded channels, 4 px). 192 padded c-slots
// (4 dirs x 48, valid 44). Direct register->global scatter, no proj_s.
#define XS_PAD 68
#define WS_PAD 196
__global__ __launch_bounds__(256) void k2_xproj(const float* __restrict__ xpw) {
    __shared__ __align__(16) float xs_s[16][XS_PAD];
    __shared__ __align__(16) float ws_s[16][WS_PAD];
    int p0 = blockIdx.x * 64;
    int b  = blockIdx.y;
    int t  = threadIdx.x;
    int cg = t & 15;          // 16 c-groups of 12 slots
    int pg = t >> 4;          // 16 px-groups of 4
    int c0 = cg * 12;
    int px = pg * 4;
    u64 acc2[4][6];
#pragma unroll
    for (int i = 0; i < 4; i++)
#pragma unroll
        for (int j = 0; j < 6; j++) acc2[i][j] = 0ull;

    for (int d0 = 0; d0 < DI; d0 += 16) {
        __syncthreads();
        // stage x: [dd][l] (coalesced gmem reads along d)
        for (int idx = t; idx < 16*64; idx += 256) {
            int dd = idx & 15, l = idx >> 4;
            xs_s[dd][l] = g_xin[((size_t)b*LL + p0 + l)*DI + d0 + dd];
        }
        // stage w: [dd][kc-slot], zero-pad slots c>=44
        for (int idx = t; idx < 16*192; idx += 256) {
            int dd = idx & 15, kcs = idx >> 4;
            int k = kcs / 48, cc = kcs % 48;
            ws_s[dd][kcs] = (cc < CPROJ) ? xpw[((size_t)(k*CPROJ + cc))*DI + d0 + dd] : 0.f;
        }
        __syncthreads();
#pragma unroll
        for (int dd = 0; dd < 16; dd++) {
            float4 xv = *(const float4*)&xs_s[dd][px];
            ulonglong2 wq0 = *(const ulonglong2*)&ws_s[dd][c0];
            ulonglong2 wq1 = *(const ulonglong2*)&ws_s[dd][c0+4];
            ulonglong2 wq2 = *(const ulonglong2*)&ws_s[dd][c0+8];
            u64 wp[6] = {wq0.x, wq0.y, wq1.x, wq1.y, wq2.x, wq2.y};
            u64 xp[4] = {pk(xv.x,xv.x), pk(xv.y,xv.y), pk(xv.z,xv.z), pk(xv.w,xv.w)};
#pragma unroll
            for (int i = 0; i < 4; i++)
#pragma unroll
                for (int j = 0; j < 6; j++)
                    acc2[i][j] = fma2(xp[i], wp[j], acc2[i][j]);
        }
    }

    // register scatter: slot ranges -> pj[0:12) / B[0:16) / C[0:16) per (k,l)
    int k  = cg >> 2;               // direction
    int cl = (cg & 3) * 12;         // offset within the 48 slots of this k
    size_t rowbase = (size_t)(b*KK + k)*LL;
#pragma unroll
    for (int i = 0; i < 4; i++) {
        int p = p0 + px + i;
        int l = inv_perm(k, p);
        float o[12];
#pragma unroll
        for (int j = 0; j < 6; j++) upk(acc2[i][j], o[2*j], o[2*j+1]);
        if (cl == 0) {
            float* dst = g_pj + (rowbase + l)*RR;
            *(float4*)(dst + 0) = make_float4(o[0], o[1], o[2], o[3]);
            *(float4*)(dst + 4) = make_float4(o[4], o[5], o[6], o[7]);
            *(float4*)(dst + 8) = make_float4(o[8], o[9], o[10], o[11]);
        } else if (cl == 12) {
            float* dst = g_Bs + (rowbase + l)*NS;
            *(float4*)(dst + 0) = make_float4(o[0], o[1], o[2], o[3]);
            *(float4*)(dst + 4) = make_float4(o[4], o[5], o[6], o[7]);
            *(float4*)(dst + 8) = make_float4(o[8], o[9], o[10], o[11]);
        } else if (cl == 24) {
            *(float4*)(g_Bs + (rowbase + l)*NS + 12) = make_float4(o[0], o[1], o[2], o[3]);
            *(float4*)(g_Cs + (rowbase + l)*NS + 0)  = make_float4(o[4], o[5], o[6], o[7]);
            *(float4*)(g_Cs + (rowbase + l)*NS + 4)  = make_float4(o[8], o[9], o[10], o[11]);
        } else {
            *(float4*)(g_Cs + (rowbase + l)*NS + 8)  = make_float4(o[0], o[1], o[2], o[3]);
            *(float4*)(g_Cs + (rowbase + l)*NS + 12) = make_float4(o[4], o[5], o[6], o[7]);
            // o[8..11] are zero-pad slots, discarded
        }
    }
}

// u-stream: all 4 directions contiguous via yin / yinT
__device__ __forceinline__ const float* u_base(int k, int b, int l0, int d, int& ustep) {
    if (k == 0) { ustep =  DI; return g_yin  + ((size_t)b*LL + l0)*DI + d; }
    if (k == 1) { ustep =  DI; return g_yinT + ((size_t)b*LL + l0)*DI + d; }
    if (k == 2) { ustep = -DI; return g_yin  + ((size_t)b*LL + (LL-1-l0))*DI + d; }
    ustep = -DI; return g_yinT + ((size_t)b*LL + (LL-1-l0))*DI + d;
}

// y-output in PIXEL order: start pixel + uniform stride per direction
__device__ __forceinline__ float* y_base(int k, size_t bk, int l0, int d, int& ostep) {
    int pstart;
    if (k == 0)      { pstart = l0;                                  ostep =  DI;    }
    else if (k == 1) { pstart = ((l0 & 63) << 6) | (l0 >> 6);        ostep =  64*DI; }
    else if (k == 2) { pstart = LL - 1 - l0;                          ostep = -DI;    }
    else { int q = LL - 1 - l0; pstart = ((q & 63) << 6) | (q >> 6);  ostep = -64*DI; }
    return g_sy + (bk*LL + (size_t)pstart)*DI + d;
}

// delta recompute: 6 r-pair fma2 against smem proj row + softplus
__device__ __forceinline__ float delta_step(const u64* wp2, float bias, const float* pjrow){
    const u64* pj = (const u64*)pjrow;
    u64 a2 = fma2(wp2[0], pj[0], 0ull);
    a2 = fma2(wp2[1], pj[1], a2);
    a2 = fma2(wp2[2], pj[2], a2);
    a2 = fma2(wp2[3], pj[3], a2);
    a2 = fma2(wp2[4], pj[4], a2);
    a2 = fma2(wp2[5], pj[5], a2);
    float alo, ahi; upk(a2, alo, ahi);
    return softplusf(bias + alo + ahi);
}

// ---- pass1: recursion + C-dot + y_local (pixel order) + chunk summaries -----
__global__ __launch_bounds__(192, 5) void k3_pass1() {
    __shared__ __align__(16) float sB[CT*NS];
    __shared__ __align__(16) float sC[CT*NS];
    __shared__ __align__(16) float sPJ[CT*RR];
    int c = blockIdx.x, k = blockIdx.y, b = blockIdx.z;
    int d = threadIdx.x;
    size_t bk = (size_t)(b*KK + k);
    int l0 = c * CT;
    {
        const float4* Bg = (const float4*)(g_Bs + (bk*LL + (size_t)l0)*NS);
        const float4* Cg = (const float4*)(g_Cs + (bk*LL + (size_t)l0)*NS);
        const float4* Pg = (const float4*)(g_pj + (bk*LL + (size_t)l0)*RR);
        float4* sB4 = (float4*)sB;
        float4* sC4 = (float4*)sC;
        float4* sP4 = (float4*)sPJ;
        for (int i = d; i < CT*NS/4; i += 192) { sB4[i] = Bg[i]; sC4[i] = Cg[i]; }
        for (int i = d; i < CT*RR/4; i += 192) sP4[i] = Pg[i];
    }
    __syncthreads();

    float* op; int ostep;
    op = y_base(k, bk, l0, d, ostep);
    int ustep;
    const float* up = u_base(k, b, l0, d, ustep);
    size_t ch = bk*DI + d;

    const float4* wr4 = (const float4*)(g_dtw + ((size_t)k*DI + d)*RR);
    float4 w0 = wr4[0], w1 = wr4[1], w2 = wr4[2];
    u64 wp2[6] = { pk(w0.x,w0.y), pk(w0.z,w0.w), pk(w1.x,w1.y),
                   pk(w1.z,w1.w), pk(w2.x,w2.y), pk(w2.z,w2.w) };
    float bias = g_dtb[k*DI + d];

    if (g_fast) {
        float an0 = g_anl2[((size_t)k*DI + d)*NS];
        u64 h2[8];
#pragma unroll
        for (int i = 0; i < 8; i++) h2[i] = 0ull;
        float S = 0.f;
#pragma unroll 4
        for (int t = 0; t < CT; t++) {
            float dlt = delta_step(wp2, bias, &sPJ[t*RR]);
            float uv  = up[(size_t)t*ustep];
            const u64* Bw = (const u64*)&sB[t*NS];
            const u64* Cw = (const u64*)&sC[t*NS];
            u64 P[8]; pows16p(ex2f(dlt * an0), P);
            float du = dlt * uv;
            u64 DU = pk(du, du);
            u64 Y = 0ull;
#pragma unroll
            for (int i = 0; i < 8; i++) {
                h2[i] = fma2(P[i], h2[i], mul2(DU, Bw[i]));
                Y = fma2(h2[i], Cw[i], Y);
            }
            float ylo, yhi; upk(Y, ylo, yhi);
            op[(size_t)t*ostep] = ylo + yhi;
            S += dlt;
        }
        u64* Hp = (u64*)(g_H + (ch*NC + c)*NS);
        u64* Pp = (u64*)(g_P + (ch*NC + c)*NS);
        u64 Q[8]; pows16p(ex2f(an0 * S), Q);
#pragma unroll
        for (int i = 0; i < 8; i++) { Hp[i] = h2[i]; Pp[i] = Q[i]; }
    } else {
        float an[NS];
        const float* ap = g_anl2 + ((size_t)k*DI + d)*NS;
#pragma unroll
        for (int n = 0; n < NS; n++) an[n] = ap[n];
        float h[NS];
#pragma unroll
        for (int n = 0; n < NS; n++) h[n] = 0.f;
        float S = 0.f;
        for (int t = 0; t < CT; t++) {
            float dlt = delta_step(wp2, bias, &sPJ[t*RR]);
            float uv  = up[(size_t)t*ustep];
            float du = dlt * uv;
            const float* Bp = &sB[t*NS];
            const float* Cp = &sC[t*NS];
            float y = 0.f;
#pragma unroll
            for (int n = 0; n < NS; n++) {
                h[n] = fmaf(ex2f(dlt*an[n]), h[n], du * Bp[n]);
                y = fmaf(h[n], Cp[n], y);
            }
            op[(size_t)t*ostep] = y;
            S += dlt;
        }
        float* Hp = g_H + (ch*NC + c)*NS;
        float* Pp = g_P + (ch*NC + c)*NS;
#pragma unroll
        for (int n = 0; n < NS; n++) { Hp[n] = h[n]; Pp[n] = ex2f(an[n]*S); }
    }
}

__global__ void k3_comb() {
    int t = blockIdx.x * blockDim.x + threadIdx.x;
    int n = t & 15;
    size_t ch = (size_t)(t >> 4);
    const float* __restrict__ Hp = g_H   + ch*NC*NS + n;
    const float* __restrict__ Pp = g_P   + ch*NC*NS + n;
    float*       __restrict__ Ip = g_Hin + ch*NC*NS + n;
    float h = 0.f;
#pragma unroll 4
    for (int c = 0; c < NC; c++) {
        Ip[c*NS] = h;
        h = fmaf(Pp[c*NS], h, Hp[c*NS]);
    }
}

// ---- pass2: chain-free carry correction (recomputes delta prefix) -----------
__global__ __launch_bounds__(192, 5) void k3_pass2() {
    __shared__ __align__(16) float sC[CT*NS];
    __shared__ __align__(16) float sPJ[CT*RR];
    int c = blockIdx.x, k = blockIdx.y, b = blockIdx.z;
    int d = threadIdx.x;
    size_t bk = (size_t)(b*KK + k);
    int l0 = c * CT;
    {
        const float4* Cg = (const float4*)(g_Cs + (bk*LL + (size_t)l0)*NS);
        const float4* Pg = (const float4*)(g_pj + (bk*LL + (size_t)l0)*RR);
        float4* sC4 = (float4*)sC;
        float4* sP4 = (float4*)sPJ;
        for (int i = d; i < CT*NS/4; i += 192) sC4[i] = Cg[i];
        for (int i = d; i < CT*RR/4; i += 192) sP4[i] = Pg[i];
    }
    __syncthreads();

    const float4* wr4 = (const float4*)(g_dtw + ((size_t)k*DI + d)*RR);
    float4 w0 = wr4[0], w1 = wr4[1], w2 = wr4[2];
    u64 wp2[6] = { pk(w0.x,w0.y), pk(w0.z,w0.w), pk(w1.x,w1.y),
                   pk(w1.z,w1.w), pk(w2.x,w2.y), pk(w2.z,w2.w) };
    float bias = g_dtb[k*DI + d];

    float* yp; int ostep;
    yp = y_base(k, bk, l0, d, ostep);
    size_t ch = bk*DI + d;

    if (g_fast) {
        float an0 = g_anl2[((size_t)k*DI + d)*NS];
        const u64* Ip = (const u64*)(g_Hin + (ch*NC + c)*NS);
        u64 hin[8];
#pragma unroll
        for (int i = 0; i < 8; i++) hin[i] = Ip[i];
        float S = 0.f;
#pragma unroll 4
        for (int t = 0; t < CT; t++) {
            S += delta_step(wp2, bias, &sPJ[t*RR]);
            u64 P[8]; pows16p(ex2f(an0 * S), P);
            const u64* Cw = (const u64*)&sC[t*NS];
            u64 Y = 0ull;
#pragma unroll
            for (int i = 0; i < 8; i++)
                Y = fma2(mul2(P[i], hin[i]), Cw[i], Y);
            float ylo, yhi; upk(Y, ylo, yhi);
            yp[(size_t)t*ostep] += ylo + yhi;
        }
    } else {
        float an[NS];
        const float* ap = g_anl2 + ((size_t)k*DI + d)*NS;
#pragma unroll
        for (int n = 0; n < NS; n++) an[n] = ap[n];
        const float* Ip = g_Hin + (ch*NC + c)*NS;
        float hin[NS];
#pragma unroll
        for (int n = 0; n < NS; n++) hin[n] = Ip[n];
        float S = 0.f;
        for (int t = 0; t < CT; t++) {
            S += delta_step(wp2, bias, &sPJ[t*RR]);
            const float* Cp = &sC[t*NS];
            float y = 0.f;
#pragma unroll
            for (int n = 0; n < NS; n++)
                y = fmaf(ex2f(an[n]*S) * hin[n], Cp[n], y);
            yp[(size_t)t*ostep] += y;
        }
    }
}

// ---------------- kernel 5: merge + LN + out_proj (64-px tiles) --------------
__global__ __launch_bounds__(256) void k5_merge(
        const float* __restrict__ gamma, const float* __restrict__ beta,
        const float* __restrict__ opw, float* __restrict__ out) {
    __shared__ __align__(16) float ym_s[64*DI];
    __shared__ __align__(16) float W_s[16*DI];
    __shared__ float mu_s[64], rs_s[64];
    int b = blockIdx.y;
    int p0 = blockIdx.x * 64;
    int t = threadIdx.x;
    size_t bb = (size_t)b * KK;

    for (int idx = t; idx < 64*DI/4; idx += 256) {
        size_t off = (size_t)p0*DI + idx*4;
        float4 v0 = *(const float4*)&g_sy[((bb + 0)*LL)*DI + off];
        float4 v1 = *(const float4*)&g_sy[((bb + 1)*LL)*DI + off];
        float4 v2 = *(const float4*)&g_sy[((bb + 2)*LL)*DI + off];
        float4 v3 = *(const float4*)&g_sy[((bb + 3)*LL)*DI + off];
        float4 u  = *(const float4*)&g_yin[((size_t)b*LL)*DI + off];
        int dd = (idx*4) % DI;
        float4 ds = *(const float4*)&g_dsum[dd];
        float4 r;
        r.x = v0.x + v1.x + v2.x + v3.x + ds.x * u.x;
        r.y = v0.y + v1.y + v2.y + v3.y + ds.y * u.y;
        r.z = v0.z + v1.z + v2.z + v3.z + ds.z * u.z;
        r.w = v0.w + v1.w + v2.w + v3.w + ds.w * u.w;
        *(float4*)&ym_s[idx*4] = r;
    }
    __syncthreads();

    {
        int warp = t >> 5, lane = t & 31;
        int pl  = warp*8 + (lane >> 2);
        int sub = lane & 3;
        float s = 0.f, s2 = 0.f;
        for (int j = sub; j < DI; j += 4) { float v = ym_s[pl*DI + j]; s += v; s2 += v*v; }
        s  += __shfl_xor_sync(0xffffffffu, s, 2);  s2 += __shfl_xor_sync(0xffffffffu, s2, 2);
        s  += __shfl_xor_sync(0xffffffffu, s, 1);  s2 += __shfl_xor_sync(0xffffffffu, s2, 1);
        if (sub == 0) {
            float mu  = s * (1.f/DI);
            float var = s2 * (1.f/DI) - mu*mu;
            mu_s[pl] = mu;
            rs_s[pl] = rsqrtf(var + 1e-5f);
        }
    }
    __syncthreads();

    for (int idx = t; idx < 64*DI; idx += 256) {
        int pl = idx / DI, d = idx % DI;
        ym_s[idx] = (ym_s[idx] - mu_s[pl]) * rs_s[pl] * gamma[d] + beta[d];
    }

    int c0 = (t & 15) * 12;
    int px = (t >> 4) * 4;
    u64 acc2[4][6];
#pragma unroll
    for (int i = 0; i < 4; i++)
#pragma unroll
        for (int j = 0; j < 6; j++) acc2[i][j] = 0ull;

    for (int dc = 0; dc < DI; dc += 16) {
        __syncthreads();
        for (int idx = t; idx < 16*DI; idx += 256)
            W_s[idx] = opw[(dc + idx/DI)*DM + (idx % DI)];
        __syncthreads();
#pragma unroll
        for (int dd = 0; dd < 16; dd++) {
            ulonglong2 wq0 = *(const ulonglong2*)&W_s[dd*DI + c0];
            ulonglong2 wq1 = *(const ulonglong2*)&W_s[dd*DI + c0 + 4];
            ulonglong2 wq2 = *(const ulonglong2*)&W_s[dd*DI + c0 + 8];
            u64 wp[6] = {wq0.x, wq0.y, wq1.x, wq1.y, wq2.x, wq2.y};
#pragma unroll
            for (int i = 0; i < 4; i++) {
                float yv = ym_s[(px + i)*DI + dc + dd];
                u64 yp2 = pk(yv, yv);
#pragma unroll
                for (int j = 0; j < 6; j++)
                    acc2[i][j] = fma2(yp2, wp[j], acc2[i][j]);
            }
        }
    }
#pragma unroll
    for (int i = 0; i < 4; i++) {
        int p = p0 + px + i;
        float o[12];
#pragma unroll
        for (int j = 0; j < 6; j++) upk(acc2[i][j], o[2*j], o[2*j+1]);
#pragma unroll
        for (int j = 0; j < 12; j++)
            out[((size_t)(b*DM + c0 + j))*LL + p] = o[j];
    }
}

extern "C" void kernel_launch(void* const* d_in, const int* in_sizes, int n_in,
                              void* d_out, int out_size) {
    const float* x    = (const float*)d_in[0];
    const float* y    = (const float*)d_in[1];
    const float* wx   = (const float*)d_in[2];
    const float* wy   = (const float*)d_in[3];
    const float* xpw  = (const float*)d_in[4];
    const float* dtw  = (const float*)d_in[5];
    const float* dtb  = (const float*)d_in[6];
    const float* Alog = (const float*)d_in[7];
    const float* Ds   = (const float*)d_in[8];
    const float* gam  = (const float*)d_in[9];
    const float* bet  = (const float*)d_in[10];
    const float* opw  = (const float*)d_in[11];
    float* out = (float*)d_out;

    k0_init<<<1, 256>>>(Alog, Ds);
    k0b_copy<<<(KK*DI*RR + 255)/256, 256>>>(dtw, dtb);
    k1_inproj<<<dim3(256, 2), 256>>>(x, y, wx, wy);
    k2_xproj<<<dim3(LL/64, BATCH), 256>>>(xpw);
    k3_pass1<<<dim3(NC, KK, BATCH), 192>>>();
    k3_comb<<<192, 256>>>();
    k3_pass2<<<dim3(NC, KK, BATCH), 192>>>();
    k5_merge<<<dim3(LL/64, BATCH), 256>>>(gam, bet, opw, out);
}